// round 1
// baseline (speedup 1.0000x reference)
#include <cuda_runtime.h>
#include <cuda_bf16.h>
#include <cstdint>
#include <math.h>

// Problem dims
#define BB 32
#define TT 128
#define SSRC 128
#define HH 512
#define EE 256
#define VV 32000
#define K2H 1024   // 2H
#define G4 2048    // 4H
#define UD 1536    // 2H + H
#define KSA 8      // k-split for gates GEMM (k=1024 -> 128 each)
#define KSD 12     // k-split for dec GEMM (k=1536 -> 128 each)

// ---------------- device scratch (static, no allocation) ----------------
static __device__ float g_keys[BB*SSRC*HH];          // [b][s][h]
static __device__ float g_gatesy[TT*BB*G4];          // [t][b][g]
static __device__ float g_embseq[TT*BB*EE];          // [t][b][e]
static __device__ float g_h[BB*HH];
static __device__ float g_c[BB*HH];
static __device__ float g_u[BB*UD];                  // [a(1024), h(512)]
static __device__ float g_oseq[BB*TT*HH];            // row n = b*T+t
static __device__ float g_WihoT[HH*G4];              // [k][g]
static __device__ float g_WhhT[HH*G4];               // [k][g]
static __device__ float g_WdecT[UD*HH];              // [k][j]
static __device__ float g_gatepart[KSA][BB*G4];
static __device__ float g_decpart[KSD][BB*HH];
static __device__ __nv_bfloat16 g_obf[BB*TT*HH];
static __device__ __nv_bfloat16 g_wvb[VV*HH];

// ---------------- small prep kernels ----------------
__global__ void kt_transpose(const float* __restrict__ src, int mode) {
    int i = blockIdx.x * 256 + threadIdx.x;
    if (mode == 0) {            // W_ih (2048 x 768), cols 256..767 -> WihoT[k][g]
        if (i >= HH * G4) return;
        int k = i / G4, g = i % G4;
        g_WihoT[i] = src[g * 768 + 256 + k];
    } else if (mode == 1) {     // W_hh (2048 x 512) -> WhhT[k][g]
        if (i >= HH * G4) return;
        int k = i / G4, g = i % G4;
        g_WhhT[i] = src[g * 512 + k];
    } else {                    // W_dec (512 x 1536) -> WdecT[k][j]
        if (i >= UD * HH) return;
        int k = i / HH, j = i % HH;
        g_WdecT[i] = src[j * UD + k];
    }
}

__global__ void kt_init(const float* __restrict__ h0, const float* __restrict__ c0) {
    int i = blockIdx.x * 256 + threadIdx.x;
    if (i < BB * HH) { g_h[i] = h0[i]; g_c[i] = c0[i]; }
}

__global__ void kt_gather(const float* __restrict__ emb, const int* __restrict__ ids) {
    int i = blockIdx.x * 256 + threadIdx.x;
    if (i >= TT * BB * EE) return;
    int e = i % EE; int tb = i / EE; int b = tb % BB; int t = tb / BB;
    int tok = ids[b * (TT + 1) + t];
    g_embseq[(t * BB + b) * EE + e] = emb[tok * EE + e];
}

// ---------------- generic fp32 GEMM: C[m][n] = sum_k A[m][k]*B[n][k] (+bias) ----------------
// 64x64 block, 16 k-tile, 256 threads, 4x4 per thread. M,N %64==0, K %16==0.
__global__ void __launch_bounds__(256) kt_gemm_nt(
    const float* __restrict__ A, int lda,
    const float* __restrict__ Bm, int ldb,
    float* __restrict__ C, int ldc,
    int K,
    const float* __restrict__ bias0,
    const float* __restrict__ bias1)
{
    __shared__ float As[16][65];
    __shared__ float Bs[16][65];
    int tid = threadIdx.x;
    int tx = tid & 15, ty = tid >> 4;
    int m0 = blockIdx.y * 64, n0 = blockIdx.x * 64;
    float acc[4][4];
#pragma unroll
    for (int i = 0; i < 4; i++)
#pragma unroll
        for (int j = 0; j < 4; j++) acc[i][j] = 0.f;

    for (int k0 = 0; k0 < K; k0 += 16) {
#pragma unroll
        for (int i = tid; i < 1024; i += 256) {
            int r = i >> 4, kk = i & 15;
            As[kk][r] = A[(size_t)(m0 + r) * lda + k0 + kk];
            Bs[kk][r] = Bm[(size_t)(n0 + r) * ldb + k0 + kk];
        }
        __syncthreads();
#pragma unroll
        for (int kk = 0; kk < 16; kk++) {
            float av[4], bv[4];
#pragma unroll
            for (int i = 0; i < 4; i++) av[i] = As[kk][ty * 4 + i];
#pragma unroll
            for (int j = 0; j < 4; j++) bv[j] = Bs[kk][tx * 4 + j];
#pragma unroll
            for (int i = 0; i < 4; i++)
#pragma unroll
                for (int j = 0; j < 4; j++) acc[i][j] += av[i] * bv[j];
        }
        __syncthreads();
    }
#pragma unroll
    for (int j = 0; j < 4; j++) {
        int n = n0 + tx * 4 + j;
        float bb = 0.f;
        if (bias0) bb += bias0[n];
        if (bias1) bb += bias1[n];
#pragma unroll
        for (int i = 0; i < 4; i++)
            C[(size_t)(m0 + ty * 4 + i) * ldc + n] = acc[i][j] + bb;
    }
}

// ---------------- step kernel A: gates split-K GEMM ----------------
// grid (16 jchunks of 128 gate cols, 8 k-splits of 128), 256 threads.
// x = concat(o_{t-1}, h_{t-1}); o recomputed inline from dec partials.
__global__ void __launch_bounds__(256) kt_step_gates(int t, const float* __restrict__ bdec) {
    __shared__ float xs[32][128];
    int jc = blockIdx.x, ks = blockIdx.y;
    int g0 = jc * 128, k0 = ks * 128;
    int tid = threadIdx.x;

    for (int i = tid; i < 32 * 128; i += 256) {
        int b = i >> 7, kk = i & 127;
        int k = k0 + kk;
        float v;
        if (k < HH) {                 // o-part
            if (t == 0) v = 0.f;
            else {
                float s = bdec[k];
#pragma unroll
                for (int q = 0; q < KSD; q++) s += g_decpart[q][b * HH + k];
                v = tanhf(s);
                if (jc == 0) g_oseq[(size_t)(b * TT + (t - 1)) * HH + k] = v;
            }
        } else {
            v = g_h[b * HH + (k - HH)];
        }
        xs[b][kk] = v;
    }
    __syncthreads();

    const float* W = (k0 < HH) ? (g_WihoT + (size_t)k0 * G4)
                               : (g_WhhT + (size_t)(k0 - HH) * G4);
    int tb = tid >> 5;      // 0..7 -> batch quad
    int tg = tid & 31;
    int g = g0 + tg * 4;
    int b0 = tb * 4;
    float4 a0 = {0,0,0,0}, a1 = {0,0,0,0}, a2 = {0,0,0,0}, a3 = {0,0,0,0};
#pragma unroll 4
    for (int kk = 0; kk < 128; kk++) {
        float4 w = *reinterpret_cast<const float4*>(W + (size_t)kk * G4 + g);
        float x0 = xs[b0 + 0][kk], x1 = xs[b0 + 1][kk];
        float x2 = xs[b0 + 2][kk], x3 = xs[b0 + 3][kk];
        a0.x += w.x * x0; a0.y += w.y * x0; a0.z += w.z * x0; a0.w += w.w * x0;
        a1.x += w.x * x1; a1.y += w.y * x1; a1.z += w.z * x1; a1.w += w.w * x1;
        a2.x += w.x * x2; a2.y += w.y * x2; a2.z += w.z * x2; a2.w += w.w * x2;
        a3.x += w.x * x3; a3.y += w.y * x3; a3.z += w.z * x3; a3.w += w.w * x3;
    }
    float* P = g_gatepart[ks];
    *reinterpret_cast<float4*>(P + (b0 + 0) * G4 + g) = a0;
    *reinterpret_cast<float4*>(P + (b0 + 1) * G4 + g) = a1;
    *reinterpret_cast<float4*>(P + (b0 + 2) * G4 + g) = a2;
    *reinterpret_cast<float4*>(P + (b0 + 3) * G4 + g) = a3;
}

// ---------------- step kernel B: LSTM cell + attention + context (one block / batch) ----------------
__global__ void __launch_bounds__(256) kt_step_cellattn(
    int t, const float* __restrict__ enc, const int* __restrict__ mask)
{
    __shared__ float hs[HH];
    __shared__ float sc[SSRC];
    __shared__ float red[256];
    int b = blockIdx.x;
    int tid = threadIdx.x;

    // phase 1: reduce gate partials, LSTM cell
    const float* gy = g_gatesy + (size_t)(t * BB + b) * G4;
    for (int j = tid; j < HH; j += 256) {
        float v[4];
#pragma unroll
        for (int grp = 0; grp < 4; grp++) {
            int g = grp * HH + j;
            float s = gy[g];
#pragma unroll
            for (int q = 0; q < KSA; q++) s += g_gatepart[q][b * G4 + g];
            v[grp] = s;
        }
        float c  = g_c[b * HH + j];
        float ig = 1.f / (1.f + expf(-v[0]));
        float fg = 1.f / (1.f + expf(-v[1]));
        float gg = tanhf(v[2]);
        float og = 1.f / (1.f + expf(-v[3]));
        float cn = fg * c + ig * gg;
        float hn = og * tanhf(cn);
        g_c[b * HH + j] = cn;
        g_h[b * HH + j] = hn;
        hs[j] = hn;
        g_u[b * UD + K2H + j] = hn;   // h part of u
    }
    __syncthreads();

    // phase 2: scores = h . keys + mask bias
    int w = tid >> 5, lane = tid & 31;
    for (int s = w; s < SSRC; s += 8) {
        const float* kp = g_keys + (size_t)(b * SSRC + s) * HH;
        float acc = 0.f;
        for (int kk = lane; kk < HH; kk += 32) acc += hs[kk] * kp[kk];
#pragma unroll
        for (int off = 16; off; off >>= 1) acc += __shfl_down_sync(0xffffffffu, acc, off);
        if (lane == 0) {
            float bias = (mask[b * SSRC + s] > 0) ? 0.f : -1e9f;
            sc[s] = acc + bias;
        }
    }
    __syncthreads();

    // softmax over 128
    float v = (tid < SSRC) ? sc[tid] : -INFINITY;
    red[tid] = v;
    __syncthreads();
#pragma unroll
    for (int off = 128; off; off >>= 1) {
        if (tid < off) red[tid] = fmaxf(red[tid], red[tid + off]);
        __syncthreads();
    }
    float m = red[0];
    __syncthreads();
    float e = (tid < SSRC) ? expf(v - m) : 0.f;
    red[tid] = e;
    __syncthreads();
#pragma unroll
    for (int off = 128; off; off >>= 1) {
        if (tid < off) red[tid] += red[tid + off];
        __syncthreads();
    }
    float inv = 1.f / red[0];
    __syncthreads();
    if (tid < SSRC) sc[tid] = e * inv;
    __syncthreads();

    // phase 3: a = attn @ enc_out (each thread one float4 of 1024)
    int k4 = tid * 4;
    float4 acc = {0,0,0,0};
    const float* ep = enc + (size_t)(b * SSRC) * K2H + k4;
#pragma unroll 4
    for (int s = 0; s < SSRC; s++) {
        float ws = sc[s];
        float4 ev = *reinterpret_cast<const float4*>(ep + (size_t)s * K2H);
        acc.x += ws * ev.x; acc.y += ws * ev.y; acc.z += ws * ev.z; acc.w += ws * ev.w;
    }
    *reinterpret_cast<float4*>(g_u + b * UD + k4) = acc;
}

// ---------------- step kernel C: dec split-K GEMM (u @ WdecT) ----------------
// grid (8 jchunks of 64, 12 k-splits of 128)
__global__ void __launch_bounds__(256) kt_step_dec() {
    __shared__ float us[32][128];
    int jc = blockIdx.x, ks = blockIdx.y;
    int j0 = jc * 64, k0 = ks * 128;
    int tid = threadIdx.x;
    for (int i = tid; i < 32 * 128; i += 256) {
        int b = i >> 7, kk = i & 127;
        us[b][kk] = g_u[b * UD + k0 + kk];
    }
    __syncthreads();
    int tb = tid >> 5, tg = tid & 31;
    int j = j0 + tg * 2;
    int b0 = tb * 4;
    float2 a0 = {0,0}, a1 = {0,0}, a2 = {0,0}, a3 = {0,0};
#pragma unroll 4
    for (int kk = 0; kk < 128; kk++) {
        float2 wv = *reinterpret_cast<const float2*>(g_WdecT + (size_t)(k0 + kk) * HH + j);
        float x0 = us[b0][kk], x1 = us[b0 + 1][kk], x2 = us[b0 + 2][kk], x3 = us[b0 + 3][kk];
        a0.x += wv.x * x0; a0.y += wv.y * x0;
        a1.x += wv.x * x1; a1.y += wv.y * x1;
        a2.x += wv.x * x2; a2.y += wv.y * x2;
        a3.x += wv.x * x3; a3.y += wv.y * x3;
    }
    float* P = g_decpart[ks];
    *reinterpret_cast<float2*>(P + (b0 + 0) * HH + j) = a0;
    *reinterpret_cast<float2*>(P + (b0 + 1) * HH + j) = a1;
    *reinterpret_cast<float2*>(P + (b0 + 2) * HH + j) = a2;
    *reinterpret_cast<float2*>(P + (b0 + 3) * HH + j) = a3;
}

__global__ void kt_final_o(const float* __restrict__ bdec) {
    int i = blockIdx.x * 256 + threadIdx.x;
    if (i >= BB * HH) return;
    int b = i / HH, j = i % HH;
    float s = bdec[j];
#pragma unroll
    for (int q = 0; q < KSD; q++) s += g_decpart[q][i];
    g_oseq[(size_t)(b * TT + (TT - 1)) * HH + j] = tanhf(s);
}

// ---------------- bf16 converts ----------------
__global__ void kt_cvt_o() {
    int i = blockIdx.x * 256 + threadIdx.x;
    if (i < BB * TT * HH) g_obf[i] = __float2bfloat16(g_oseq[i]);
}
__global__ void kt_cvt_w(const float* __restrict__ Wv) {
    int i = blockIdx.x * 256 + threadIdx.x;
    if (i < VV * HH) g_wvb[i] = __float2bfloat16(Wv[i]);
}

// ---------------- vocab GEMM: logits = o_seq @ W_vocab^T + b_vocab (bf16 mma.sync) ----------------
#define MMA16816(d0,d1,d2,d3,A0,A1,A2,A3,B0,B1) \
    asm volatile("mma.sync.aligned.m16n8k16.row.col.f32.bf16.bf16.f32 " \
        "{%0,%1,%2,%3}, {%4,%5,%6,%7}, {%8,%9}, {%0,%1,%2,%3};" \
        : "+f"(d0), "+f"(d1), "+f"(d2), "+f"(d3) \
        : "r"(A0), "r"(A1), "r"(A2), "r"(A3), "r"(B0), "r"(B1))

__global__ void __launch_bounds__(256) kt_vocab_gemm(
    float* __restrict__ out, const float* __restrict__ bvocab)
{
    int nb = blockIdx.x;   // 0..249
    int mb = blockIdx.y;   // 0..31
    int wid = threadIdx.x >> 5;
    int lane = threadIdx.x & 31;
    int wm = wid >> 2;     // 0..1
    int wn = wid & 3;      // 0..3
    int m_warp = mb * 128 + wm * 64;
    int n_warp = nb * 128 + wn * 32;
    int gid = lane >> 2;
    int tg = lane & 3;

    float acc[4][4][4];
#pragma unroll
    for (int i = 0; i < 4; i++)
#pragma unroll
        for (int j = 0; j < 4; j++)
#pragma unroll
            for (int r = 0; r < 4; r++) acc[i][j][r] = 0.f;

#pragma unroll 2
    for (int k0 = 0; k0 < HH; k0 += 16) {
        uint32_t af[4][4];
#pragma unroll
        for (int mt = 0; mt < 4; mt++) {
            const __nv_bfloat16* ap = g_obf + (size_t)(m_warp + mt * 16 + gid) * HH + k0 + tg * 2;
            af[mt][0] = *reinterpret_cast<const uint32_t*>(ap);
            af[mt][1] = *reinterpret_cast<const uint32_t*>(ap + 8 * HH);
            af[mt][2] = *reinterpret_cast<const uint32_t*>(ap + 8);
            af[mt][3] = *reinterpret_cast<const uint32_t*>(ap + 8 * HH + 8);
        }
        uint32_t bf[4][2];
#pragma unroll
        for (int nt = 0; nt < 4; nt++) {
            const __nv_bfloat16* bp = g_wvb + (size_t)(n_warp + nt * 8 + gid) * HH + k0 + tg * 2;
            bf[nt][0] = *reinterpret_cast<const uint32_t*>(bp);
            bf[nt][1] = *reinterpret_cast<const uint32_t*>(bp + 8);
        }
#pragma unroll
        for (int mt = 0; mt < 4; mt++)
#pragma unroll
            for (int nt = 0; nt < 4; nt++)
                MMA16816(acc[mt][nt][0], acc[mt][nt][1], acc[mt][nt][2], acc[mt][nt][3],
                         af[mt][0], af[mt][1], af[mt][2], af[mt][3],
                         bf[nt][0], bf[nt][1]);
    }

#pragma unroll
    for (int mt = 0; mt < 4; mt++) {
#pragma unroll
        for (int nt = 0; nt < 4; nt++) {
            int r = m_warp + mt * 16 + gid;
            int c = n_warp + nt * 8 + tg * 2;
            float bv0 = bvocab[c], bv1 = bvocab[c + 1];
            float2 v0 = { acc[mt][nt][0] + bv0, acc[mt][nt][1] + bv1 };
            float2 v1 = { acc[mt][nt][2] + bv0, acc[mt][nt][3] + bv1 };
            *reinterpret_cast<float2*>(out + (size_t)r * VV + c) = v0;
            *reinterpret_cast<float2*>(out + (size_t)(r + 8) * VV + c) = v1;
        }
    }
}

// ---------------- fused log-softmax: one block per row, 2 passes (2nd pass L2-hot) ----------------
__global__ void __launch_bounds__(256) kt_logsoftmax(float* __restrict__ out) {
    int row = blockIdx.x;
    float* p = out + (size_t)row * VV;
    int tid = threadIdx.x;
    float m = -INFINITY, s = 0.f;
    for (int i = tid; i < VV; i += 256) {
        float x = p[i];
        if (x > m) { s = s * __expf(m - x) + 1.f; m = x; }
        else       { s += __expf(x - m); }
    }
    __shared__ float sm[256], ssum[256];
    sm[tid] = m; ssum[tid] = s;
    __syncthreads();
#pragma unroll
    for (int off = 128; off; off >>= 1) {
        if (tid < off) {
            float m2 = sm[tid + off], s2 = ssum[tid + off];
            float mm = fmaxf(sm[tid], m2);
            ssum[tid] = ssum[tid] * __expf(sm[tid] - mm) + s2 * __expf(m2 - mm);
            sm[tid] = mm;
        }
        __syncthreads();
    }
    float lse = sm[0] + logf(ssum[0]);
    __syncthreads();
    for (int i = tid * 4; i < VV; i += 256 * 4) {
        float4 v = *reinterpret_cast<float4*>(p + i);
        v.x -= lse; v.y -= lse; v.z -= lse; v.w -= lse;
        *reinterpret_cast<float4*>(p + i) = v;
    }
}

// ---------------- launch ----------------
extern "C" void kernel_launch(void* const* d_in, const int* in_sizes, int n_in,
                              void* d_out, int out_size)
{
    const float* enc     = (const float*)d_in[0];
    const int*   mask    = (const int*)  d_in[1];
    const int*   ids     = (const int*)  d_in[2];
    const float* h0      = (const float*)d_in[3];
    const float* c0      = (const float*)d_in[4];
    const float* emb     = (const float*)d_in[5];
    const float* W_ih    = (const float*)d_in[6];
    const float* b_ih    = (const float*)d_in[7];
    const float* W_hh    = (const float*)d_in[8];
    const float* b_hh    = (const float*)d_in[9];
    const float* W_att   = (const float*)d_in[10];
    const float* W_dec   = (const float*)d_in[11];
    const float* b_dec   = (const float*)d_in[12];
    const float* W_vocab = (const float*)d_in[13];
    const float* b_vocab = (const float*)d_in[14];
    float* out = (float*)d_out;

    // prep
    kt_transpose<<<(HH*G4 + 255)/256, 256>>>(W_ih, 0);
    kt_transpose<<<(HH*G4 + 255)/256, 256>>>(W_hh, 1);
    kt_transpose<<<(UD*HH + 255)/256, 256>>>(W_dec, 2);
    kt_init<<<(BB*HH + 255)/256, 256>>>(h0, c0);
    kt_gather<<<(TT*BB*EE + 255)/256, 256>>>(emb, ids);
    kt_cvt_w<<<(VV*HH + 255)/256, 256>>>(W_vocab);

    // keys = enc_out @ W_att^T : M=4096 N=512 K=1024
    {
        float* keysp; cudaGetSymbolAddress((void**)&keysp, g_keys);
        float* embp;  cudaGetSymbolAddress((void**)&embp, g_embseq);
        float* gyp;   cudaGetSymbolAddress((void**)&gyp, g_gatesy);
        kt_gemm_nt<<<dim3(512/64, 4096/64), 256>>>(enc, K2H, W_att, K2H, keysp, HH,
                                                   K2H, nullptr, nullptr);
        // gates_y = emb_seq @ W_ih[:, :256]^T + b_ih + b_hh : M=4096 N=2048 K=256
        kt_gemm_nt<<<dim3(G4/64, 4096/64), 256>>>(embp, EE, W_ih, 768, gyp, G4,
                                                  EE, b_ih, b_hh);
    }

    // sequential scan: 128 steps x 3 kernels
    for (int t = 0; t < TT; t++) {
        kt_step_gates<<<dim3(16, 8), 256>>>(t, b_dec);
        kt_step_cellattn<<<BB, 256>>>(t, enc, mask);
        kt_step_dec<<<dim3(8, KSD), 256>>>();
    }
    kt_final_o<<<(BB*HH + 255)/256, 256>>>(b_dec);

    // vocab projection + log-softmax
    kt_cvt_o<<<(BB*TT*HH + 255)/256, 256>>>();
    kt_vocab_gemm<<<dim3(VV/128, (BB*TT)/128), 256>>>(out, b_vocab);
    kt_logsoftmax<<<BB*TT, 256>>>(out);
}

// round 2
// speedup vs baseline: 1.3021x; 1.3021x over previous
#include <cuda_runtime.h>
#include <cuda_bf16.h>
#include <cstdint>
#include <math.h>

// Problem dims
#define BB 32
#define TT 128
#define SSRC 128
#define HH 512
#define EE 256
#define VV 32000
#define K2H 1024   // 2H
#define G4 2048    // 4H
#define UD 1536    // 2H + H
#define KSA 8      // k-split for gates GEMM (k=1024 -> 128 each)
#define KSD 12     // k-split for dec GEMM (k=1536 -> 128 each)
#define NBLK 128   // persistent scan grid
#define NTILE 250  // 32000/128 vocab n-blocks

// ---------------- device scratch (static, no allocation) ----------------
static __device__ float g_keys[BB*SSRC*HH];          // [b][s][h]
static __device__ float g_gatesy[TT*BB*G4];          // [t][b][g]
static __device__ float g_embseq[TT*BB*EE];          // [t][b][e]
static __device__ float g_h[BB*HH];
static __device__ float g_c[BB*HH];
static __device__ float g_u[BB*UD];                  // [a(1024), h(512)]
static __device__ float g_oseq[BB*TT*HH];            // row n = b*T+t
static __device__ float g_WihoT[HH*G4];              // [k][g]
static __device__ float g_WhhT[HH*G4];               // [k][g]
static __device__ float g_WdecT[UD*HH];              // [k][j]
static __device__ float g_gatepart[KSA][BB*G4];
static __device__ float g_decpart[KSD][BB*HH];
static __device__ uint4 g_oswz[256*32*32];           // A fragments: (mrow,kt,lane)
static __device__ uint2 g_wswz[4000*32*32];          // B fragments: (nrow,kt,lane)
static __device__ float g_partial[(size_t)BB*TT*NTILE]; // sum-exp partials
static __device__ unsigned g_bar_count = 0;
static __device__ unsigned g_bar_gen = 0;

// ---------------- helpers ----------------
static __device__ __forceinline__ uint32_t pk_bf2(float lo, float hi) {
    __nv_bfloat16 l = __float2bfloat16(lo), h = __float2bfloat16(hi);
    return (uint32_t)__bfloat16_as_ushort(l) | ((uint32_t)__bfloat16_as_ushort(h) << 16);
}

static __device__ __forceinline__ void gbar() {
    __syncthreads();
    if (threadIdx.x == 0) {
        unsigned old;
        asm volatile("ld.acquire.gpu.u32 %0, [%1];" : "=r"(old) : "l"(&g_bar_gen) : "memory");
        __threadfence();
        unsigned prev = atomicAdd(&g_bar_count, 1);
        if (prev == NBLK - 1) {
            atomicExch(&g_bar_count, 0);
            __threadfence();
            atomicAdd(&g_bar_gen, 1);
        } else {
            unsigned cur;
            do {
                asm volatile("ld.acquire.gpu.u32 %0, [%1];" : "=r"(cur) : "l"(&g_bar_gen) : "memory");
            } while (cur == old);
        }
        __threadfence();
    }
    __syncthreads();
}

// ---------------- small prep kernels ----------------
__global__ void kt_transpose(const float* __restrict__ src, int mode) {
    int i = blockIdx.x * 256 + threadIdx.x;
    if (mode == 0) {            // W_ih (2048 x 768), cols 256..767 -> WihoT[k][g]
        if (i >= HH * G4) return;
        int k = i / G4, g = i % G4;
        g_WihoT[i] = src[g * 768 + 256 + k];
    } else if (mode == 1) {     // W_hh (2048 x 512) -> WhhT[k][g]
        if (i >= HH * G4) return;
        int k = i / G4, g = i % G4;
        g_WhhT[i] = src[g * 512 + k];
    } else {                    // W_dec (512 x 1536) -> WdecT[k][j]
        if (i >= UD * HH) return;
        int k = i / HH, j = i % HH;
        g_WdecT[i] = src[j * UD + k];
    }
}

__global__ void kt_init(const float* __restrict__ h0, const float* __restrict__ c0) {
    int i = blockIdx.x * 256 + threadIdx.x;
    if (i < BB * HH) { g_h[i] = h0[i]; g_c[i] = c0[i]; }
}

__global__ void kt_gather(const float* __restrict__ emb, const int* __restrict__ ids) {
    int i = blockIdx.x * 256 + threadIdx.x;
    if (i >= TT * BB * EE) return;
    int e = i % EE; int tb = i / EE; int b = tb % BB; int t = tb / BB;
    int tok = ids[b * (TT + 1) + t];
    g_embseq[(t * BB + b) * EE + e] = emb[tok * EE + e];
}

// W_vocab -> bf16 fragment-swizzled layout
__global__ void kt_prepack_w(const float* __restrict__ Wv) {
    int i = blockIdx.x * 256 + threadIdx.x;
    if (i >= 4000 * 32 * 32) return;
    int lane = i & 31; int tile = i >> 5;
    int kt = tile & 31; int nrow = tile >> 5;
    int gid = lane >> 2, tg = lane & 3;
    int n = nrow * 8 + gid;
    int k = kt * 16 + tg * 2;
    const float* p = Wv + (size_t)n * HH + k;
    uint2 v;
    v.x = pk_bf2(p[0], p[1]);
    v.y = pk_bf2(p[8], p[9]);
    g_wswz[i] = v;
}

// o_seq -> bf16 fragment-swizzled layout
__global__ void kt_prepack_o() {
    int i = blockIdx.x * 256 + threadIdx.x;
    if (i >= 256 * 32 * 32) return;
    int lane = i & 31; int tile = i >> 5;
    int kt = tile & 31; int mrow = tile >> 5;
    int gid = lane >> 2, tg = lane & 3;
    int m = mrow * 16 + gid;
    int k = kt * 16 + tg * 2;
    const float* p = g_oseq + (size_t)m * HH + k;
    uint4 v;
    v.x = pk_bf2(p[0], p[1]);
    v.y = pk_bf2(p[8 * HH], p[8 * HH + 1]);
    v.z = pk_bf2(p[8], p[9]);
    v.w = pk_bf2(p[8 * HH + 8], p[8 * HH + 9]);
    g_oswz[i] = v;
}

// ---------------- generic fp32 GEMM: C[m][n] = sum_k A[m][k]*B[n][k] (+bias) ----------------
__global__ void __launch_bounds__(256) kt_gemm_nt(
    const float* __restrict__ A, int lda,
    const float* __restrict__ Bm, int ldb,
    float* __restrict__ C, int ldc,
    int K,
    const float* __restrict__ bias0,
    const float* __restrict__ bias1)
{
    __shared__ float As[16][65];
    __shared__ float Bs[16][65];
    int tid = threadIdx.x;
    int tx = tid & 15, ty = tid >> 4;
    int m0 = blockIdx.y * 64, n0 = blockIdx.x * 64;
    float acc[4][4];
#pragma unroll
    for (int i = 0; i < 4; i++)
#pragma unroll
        for (int j = 0; j < 4; j++) acc[i][j] = 0.f;

    for (int k0 = 0; k0 < K; k0 += 16) {
#pragma unroll
        for (int i = tid; i < 1024; i += 256) {
            int r = i >> 4, kk = i & 15;
            As[kk][r] = A[(size_t)(m0 + r) * lda + k0 + kk];
            Bs[kk][r] = Bm[(size_t)(n0 + r) * ldb + k0 + kk];
        }
        __syncthreads();
#pragma unroll
        for (int kk = 0; kk < 16; kk++) {
            float av[4], bv[4];
#pragma unroll
            for (int i = 0; i < 4; i++) av[i] = As[kk][ty * 4 + i];
#pragma unroll
            for (int j = 0; j < 4; j++) bv[j] = Bs[kk][tx * 4 + j];
#pragma unroll
            for (int i = 0; i < 4; i++)
#pragma unroll
                for (int j = 0; j < 4; j++) acc[i][j] += av[i] * bv[j];
        }
        __syncthreads();
    }
#pragma unroll
    for (int j = 0; j < 4; j++) {
        int n = n0 + tx * 4 + j;
        float bb = 0.f;
        if (bias0) bb += bias0[n];
        if (bias1) bb += bias1[n];
#pragma unroll
        for (int i = 0; i < 4; i++)
            C[(size_t)(m0 + ty * 4 + i) * ldc + n] = acc[i][j] + bb;
    }
}

// ---------------- persistent scan kernel: all 128 timesteps, 3 grid barriers/step ------------
__global__ void __launch_bounds__(256) kt_scan(
    const float* __restrict__ enc, const int* __restrict__ mask,
    const float* __restrict__ bdec)
{
    __shared__ float sh[32 * 128];   // phase A: xs / phase C: us / phase B: hs,sc,red
    int blk = blockIdx.x;
    int tid = threadIdx.x;

    for (int t = 0; t < TT; t++) {
        // ---- phase A: gates split-K GEMM (all 128 CTAs: jc=blk>>3, ks=blk&7) ----
        {
            int jc = blk >> 3, ks = blk & 7;
            int g0 = jc * 128, k0 = ks * 128;
            float* xs = sh;  // [32][128]

            for (int i = tid; i < 32 * 128; i += 256) {
                int b = i >> 7, kk = i & 127;
                int k = k0 + kk;
                float v;
                if (k < HH) {                 // o-part
                    if (t == 0) v = 0.f;
                    else {
                        float s = bdec[k];
#pragma unroll
                        for (int q = 0; q < KSD; q++) s += g_decpart[q][b * HH + k];
                        v = tanhf(s);
                        if (jc == 0) g_oseq[(size_t)(b * TT + (t - 1)) * HH + k] = v;
                    }
                } else {
                    v = g_h[b * HH + (k - HH)];
                }
                xs[b * 128 + kk] = v;
            }
            __syncthreads();

            const float* W = (k0 < HH) ? (g_WihoT + (size_t)k0 * G4)
                                       : (g_WhhT + (size_t)(k0 - HH) * G4);
            int tb = tid >> 5;
            int tg = tid & 31;
            int g = g0 + tg * 4;
            int b0 = tb * 4;
            float4 a0 = {0,0,0,0}, a1 = {0,0,0,0}, a2 = {0,0,0,0}, a3 = {0,0,0,0};
#pragma unroll 4
            for (int kk = 0; kk < 128; kk++) {
                float4 w = *reinterpret_cast<const float4*>(W + (size_t)kk * G4 + g);
                float x0 = xs[(b0 + 0) * 128 + kk], x1 = xs[(b0 + 1) * 128 + kk];
                float x2 = xs[(b0 + 2) * 128 + kk], x3 = xs[(b0 + 3) * 128 + kk];
                a0.x += w.x * x0; a0.y += w.y * x0; a0.z += w.z * x0; a0.w += w.w * x0;
                a1.x += w.x * x1; a1.y += w.y * x1; a1.z += w.z * x1; a1.w += w.w * x1;
                a2.x += w.x * x2; a2.y += w.y * x2; a2.z += w.z * x2; a2.w += w.w * x2;
                a3.x += w.x * x3; a3.y += w.y * x3; a3.z += w.z * x3; a3.w += w.w * x3;
            }
            float* P = g_gatepart[ks];
            *reinterpret_cast<float4*>(P + (b0 + 0) * G4 + g) = a0;
            *reinterpret_cast<float4*>(P + (b0 + 1) * G4 + g) = a1;
            *reinterpret_cast<float4*>(P + (b0 + 2) * G4 + g) = a2;
            *reinterpret_cast<float4*>(P + (b0 + 3) * G4 + g) = a3;
        }
        gbar();

        // ---- phase B: LSTM cell + attention + context (32 CTAs, one per batch) ----
        if (blk < BB) {
            int b = blk;
            float* hs  = sh;          // 512
            float* sc  = sh + 512;    // 128
            float* red = sh + 640;    // 256

            const float* gy = g_gatesy + (size_t)(t * BB + b) * G4;
            for (int j = tid; j < HH; j += 256) {
                float v[4];
#pragma unroll
                for (int grp = 0; grp < 4; grp++) {
                    int g = grp * HH + j;
                    float s = gy[g];
#pragma unroll
                    for (int q = 0; q < KSA; q++) s += g_gatepart[q][b * G4 + g];
                    v[grp] = s;
                }
                float c  = g_c[b * HH + j];
                float ig = 1.f / (1.f + expf(-v[0]));
                float fg = 1.f / (1.f + expf(-v[1]));
                float gg = tanhf(v[2]);
                float og = 1.f / (1.f + expf(-v[3]));
                float cn = fg * c + ig * gg;
                float hn = og * tanhf(cn);
                g_c[b * HH + j] = cn;
                g_h[b * HH + j] = hn;
                hs[j] = hn;
                g_u[b * UD + K2H + j] = hn;
            }
            __syncthreads();

            int w = tid >> 5, lane = tid & 31;
            for (int s = w; s < SSRC; s += 8) {
                const float* kp = g_keys + (size_t)(b * SSRC + s) * HH;
                float acc = 0.f;
                for (int kk = lane; kk < HH; kk += 32) acc += hs[kk] * kp[kk];
#pragma unroll
                for (int off = 16; off; off >>= 1) acc += __shfl_down_sync(0xffffffffu, acc, off);
                if (lane == 0) {
                    float bias = (mask[b * SSRC + s] > 0) ? 0.f : -1e9f;
                    sc[s] = acc + bias;
                }
            }
            __syncthreads();

            float v = (tid < SSRC) ? sc[tid] : -INFINITY;
            red[tid] = v;
            __syncthreads();
#pragma unroll
            for (int off = 128; off; off >>= 1) {
                if (tid < off) red[tid] = fmaxf(red[tid], red[tid + off]);
                __syncthreads();
            }
            float m = red[0];
            __syncthreads();
            float e = (tid < SSRC) ? expf(v - m) : 0.f;
            red[tid] = e;
            __syncthreads();
#pragma unroll
            for (int off = 128; off; off >>= 1) {
                if (tid < off) red[tid] += red[tid + off];
                __syncthreads();
            }
            float inv = 1.f / red[0];
            __syncthreads();
            if (tid < SSRC) sc[tid] = e * inv;
            __syncthreads();

            int k4 = tid * 4;
            float4 acc = {0,0,0,0};
            const float* ep = enc + (size_t)(b * SSRC) * K2H + k4;
#pragma unroll 4
            for (int s = 0; s < SSRC; s++) {
                float ws = sc[s];
                float4 ev = *reinterpret_cast<const float4*>(ep + (size_t)s * K2H);
                acc.x += ws * ev.x; acc.y += ws * ev.y; acc.z += ws * ev.z; acc.w += ws * ev.w;
            }
            *reinterpret_cast<float4*>(g_u + b * UD + k4) = acc;
        }
        gbar();

        // ---- phase C: dec split-K GEMM (96 CTAs: jc=blk&7, ks=blk>>3) ----
        if (blk < 96) {
            int jc = blk & 7, ks = blk >> 3;
            int j0 = jc * 64, k0 = ks * 128;
            float* us = sh;
            for (int i = tid; i < 32 * 128; i += 256) {
                int b = i >> 7, kk = i & 127;
                us[b * 128 + kk] = g_u[b * UD + k0 + kk];
            }
            __syncthreads();
            int tb = tid >> 5, tg = tid & 31;
            int j = j0 + tg * 2;
            int b0 = tb * 4;
            float2 a0 = {0,0}, a1 = {0,0}, a2 = {0,0}, a3 = {0,0};
#pragma unroll 4
            for (int kk = 0; kk < 128; kk++) {
                float2 wv = *reinterpret_cast<const float2*>(g_WdecT + (size_t)(k0 + kk) * HH + j);
                float x0 = us[b0 * 128 + kk], x1 = us[(b0 + 1) * 128 + kk];
                float x2 = us[(b0 + 2) * 128 + kk], x3 = us[(b0 + 3) * 128 + kk];
                a0.x += wv.x * x0; a0.y += wv.y * x0;
                a1.x += wv.x * x1; a1.y += wv.y * x1;
                a2.x += wv.x * x2; a2.y += wv.y * x2;
                a3.x += wv.x * x3; a3.y += wv.y * x3;
            }
            float* P = g_decpart[ks];
            *reinterpret_cast<float2*>(P + (b0 + 0) * HH + j) = a0;
            *reinterpret_cast<float2*>(P + (b0 + 1) * HH + j) = a1;
            *reinterpret_cast<float2*>(P + (b0 + 2) * HH + j) = a2;
            *reinterpret_cast<float2*>(P + (b0 + 3) * HH + j) = a3;
        }
        gbar();
    }

    // final o for t = TT-1
    int i = blk * 256 + tid;
    if (i < BB * HH) {
        int b = i / HH, j = i % HH;
        float s = bdec[j];
#pragma unroll
        for (int q = 0; q < KSD; q++) s += g_decpart[q][i];
        g_oseq[(size_t)(b * TT + (TT - 1)) * HH + j] = tanhf(s);
    }
}

// ---------------- vocab GEMM (preswizzled fragments) + fused sum-exp partials ----------------
#define MMA16816(d0,d1,d2,d3,A0,A1,A2,A3,B0,B1) \
    asm volatile("mma.sync.aligned.m16n8k16.row.col.f32.bf16.bf16.f32 " \
        "{%0,%1,%2,%3}, {%4,%5,%6,%7}, {%8,%9}, {%0,%1,%2,%3};" \
        : "+f"(d0), "+f"(d1), "+f"(d2), "+f"(d3) \
        : "r"(A0), "r"(A1), "r"(A2), "r"(A3), "r"(B0), "r"(B1))

__global__ void __launch_bounds__(256) kt_vocab_gemm(
    float* __restrict__ out, const float* __restrict__ bvocab)
{
    int nb = blockIdx.x;   // 0..249
    int mb = blockIdx.y;   // 0..31
    int wid = threadIdx.x >> 5;
    int lane = threadIdx.x & 31;
    int wm = wid >> 2;     // 0..1
    int wn = wid & 3;      // 0..3
    int gid = lane >> 2;
    int tg = lane & 3;

    __shared__ float rowsum[128][4];
    if (threadIdx.x < 128) {
#pragma unroll
        for (int w = 0; w < 4; w++) rowsum[threadIdx.x][w] = 0.f;
    }
    __syncthreads();

    float acc[4][4][4];
#pragma unroll
    for (int i = 0; i < 4; i++)
#pragma unroll
        for (int j = 0; j < 4; j++)
#pragma unroll
            for (int r = 0; r < 4; r++) acc[i][j][r] = 0.f;

    int mrow0 = mb * 8 + wm * 4;
    int nrow0 = nb * 16 + wn * 4;

#pragma unroll 2
    for (int kt = 0; kt < 32; kt++) {
        uint4 af[4];
        uint2 bf[4];
#pragma unroll
        for (int mt = 0; mt < 4; mt++)
            af[mt] = g_oswz[(((mrow0 + mt) * 32 + kt) << 5) + lane];
#pragma unroll
        for (int nt = 0; nt < 4; nt++)
            bf[nt] = g_wswz[(((size_t)(nrow0 + nt) * 32 + kt) << 5) + lane];
#pragma unroll
        for (int mt = 0; mt < 4; mt++)
#pragma unroll
            for (int nt = 0; nt < 4; nt++)
                MMA16816(acc[mt][nt][0], acc[mt][nt][1], acc[mt][nt][2], acc[mt][nt][3],
                         af[mt].x, af[mt].y, af[mt].z, af[mt].w,
                         bf[nt].x, bf[nt].y);
    }

    int m_warp = mb * 128 + wm * 64;
    int n_warp = nb * 128 + wn * 32;
#pragma unroll
    for (int mt = 0; mt < 4; mt++) {
        float s0 = 0.f, s1 = 0.f;
#pragma unroll
        for (int nt = 0; nt < 4; nt++) {
            int r = m_warp + mt * 16 + gid;
            int c = n_warp + nt * 8 + tg * 2;
            float bv0 = bvocab[c], bv1 = bvocab[c + 1];
            float v00 = acc[mt][nt][0] + bv0, v01 = acc[mt][nt][1] + bv1;
            float v10 = acc[mt][nt][2] + bv0, v11 = acc[mt][nt][3] + bv1;
            float2 w0 = { v00, v01 }, w1 = { v10, v11 };
            *reinterpret_cast<float2*>(out + (size_t)r * VV + c) = w0;
            *reinterpret_cast<float2*>(out + (size_t)(r + 8) * VV + c) = w1;
            s0 += __expf(v00) + __expf(v01);
            s1 += __expf(v10) + __expf(v11);
        }
        s0 += __shfl_xor_sync(0xffffffffu, s0, 1);
        s0 += __shfl_xor_sync(0xffffffffu, s0, 2);
        s1 += __shfl_xor_sync(0xffffffffu, s1, 1);
        s1 += __shfl_xor_sync(0xffffffffu, s1, 2);
        if (tg == 0) {
            rowsum[wm * 64 + mt * 16 + gid][wn] = s0;
            rowsum[wm * 64 + mt * 16 + gid + 8][wn] = s1;
        }
    }
    __syncthreads();
    if (threadIdx.x < 128) {
        float p = rowsum[threadIdx.x][0] + rowsum[threadIdx.x][1]
                + rowsum[threadIdx.x][2] + rowsum[threadIdx.x][3];
        g_partial[(size_t)(mb * 128 + threadIdx.x) * NTILE + nb] = p;
    }
}

// ---------------- final log-softmax subtract ----------------
__global__ void __launch_bounds__(256) kt_lsfinal(float* __restrict__ out) {
    int row = blockIdx.x;
    int tid = threadIdx.x;
    __shared__ float red[256];
    __shared__ float lse_s;
    float s = 0.f;
    for (int i = tid; i < NTILE; i += 256) s += g_partial[(size_t)row * NTILE + i];
    red[tid] = s;
    __syncthreads();
#pragma unroll
    for (int off = 128; off; off >>= 1) {
        if (tid < off) red[tid] += red[tid + off];
        __syncthreads();
    }
    if (tid == 0) lse_s = logf(red[0]);
    __syncthreads();
    float lse = lse_s;
    float* p = out + (size_t)row * VV;
    for (int i = tid * 4; i < VV; i += 256 * 4) {
        float4 v = *reinterpret_cast<float4*>(p + i);
        v.x -= lse; v.y -= lse; v.z -= lse; v.w -= lse;
        *reinterpret_cast<float4*>(p + i) = v;
    }
}

// ---------------- launch ----------------
extern "C" void kernel_launch(void* const* d_in, const int* in_sizes, int n_in,
                              void* d_out, int out_size)
{
    const float* enc     = (const float*)d_in[0];
    const int*   mask    = (const int*)  d_in[1];
    const int*   ids     = (const int*)  d_in[2];
    const float* h0      = (const float*)d_in[3];
    const float* c0      = (const float*)d_in[4];
    const float* emb     = (const float*)d_in[5];
    const float* W_ih    = (const float*)d_in[6];
    const float* b_ih    = (const float*)d_in[7];
    const float* W_hh    = (const float*)d_in[8];
    const float* b_hh    = (const float*)d_in[9];
    const float* W_att   = (const float*)d_in[10];
    const float* W_dec   = (const float*)d_in[11];
    const float* b_dec   = (const float*)d_in[12];
    const float* W_vocab = (const float*)d_in[13];
    const float* b_vocab = (const float*)d_in[14];
    float* out = (float*)d_out;

    // prep
    kt_transpose<<<(HH*G4 + 255)/256, 256>>>(W_ih, 0);
    kt_transpose<<<(HH*G4 + 255)/256, 256>>>(W_hh, 1);
    kt_transpose<<<(UD*HH + 255)/256, 256>>>(W_dec, 2);
    kt_init<<<(BB*HH + 255)/256, 256>>>(h0, c0);
    kt_gather<<<(TT*BB*EE + 255)/256, 256>>>(emb, ids);
    kt_prepack_w<<<(4000*32*32 + 255)/256, 256>>>(W_vocab);

    {
        float* keysp; cudaGetSymbolAddress((void**)&keysp, g_keys);
        float* embp;  cudaGetSymbolAddress((void**)&embp, g_embseq);
        float* gyp;   cudaGetSymbolAddress((void**)&gyp, g_gatesy);
        // keys = enc_out @ W_att^T : M=4096 N=512 K=1024
        kt_gemm_nt<<<dim3(512/64, 4096/64), 256>>>(enc, K2H, W_att, K2H, keysp, HH,
                                                   K2H, nullptr, nullptr);
        // gates_y = emb_seq @ W_ih[:, :256]^T + b_ih + b_hh : M=4096 N=2048 K=256
        kt_gemm_nt<<<dim3(G4/64, 4096/64), 256>>>(embp, EE, W_ih, 768, gyp, G4,
                                                  EE, b_ih, b_hh);
    }

    // persistent scan: one launch for all 128 steps
    kt_scan<<<NBLK, 256>>>(enc, mask, b_dec);

    // vocab projection + fused sum-exp + log-softmax subtract
    kt_prepack_o<<<(256*32*32 + 255)/256, 256>>>();
    kt_vocab_gemm<<<dim3(NTILE, (BB*TT)/128), 256>>>(out, b_vocab);
    kt_lsfinal<<<BB*TT, 256>>>(out);
}

// round 3
// speedup vs baseline: 1.5138x; 1.1626x over previous
#include <cuda_runtime.h>
#include <cuda_bf16.h>
#include <cstdint>
#include <math.h>

// Problem dims
#define BB 32
#define TT 128
#define SSRC 128
#define HH 512
#define EE 256
#define VV 32000
#define K2H 1024   // 2H
#define G4 2048    // 4H
#define UD 1536    // 2H + H
#define NBLK 128   // persistent scan grid
#define NTILE 250  // 32000/128 vocab n-blocks

typedef unsigned long long ull;

// ---------------- device scratch (static, no allocation) ----------------
static __device__ float g_keys[BB*SSRC*HH];          // [b][s][h]
static __device__ float g_gatesy[TT*BB*G4];          // [t][b][g] (emb part + biases)
static __device__ float g_embseq[TT*BB*EE];          // [t][b][e]
static __device__ float g_x[BB*K2H];                 // x_t = [o_{t-1}(512), h_{t-1}(512)] per b
static __device__ float g_c[BB*HH];
static __device__ float g_u[BB*UD];                  // [a(1024), h(512)]
static __device__ float g_gates[BB*G4];              // recurrent gate part [b][g]
static __device__ float g_oseq[BB*TT*HH];            // row n = b*T+t
static __device__ uint4 g_oswz[256*32*32];           // A fragments: (mrow,kt,lane)
static __device__ uint2 g_wswz[4000*32*32];          // B fragments: (nrow,kt,lane)
static __device__ float g_partial[(size_t)BB*TT*NTILE]; // sum-exp partials
static __device__ unsigned g_bar;

// ---------------- helpers ----------------
static __device__ __forceinline__ uint32_t pk_bf2(float lo, float hi) {
    __nv_bfloat16 l = __float2bfloat16(lo), h = __float2bfloat16(hi);
    return (uint32_t)__bfloat16_as_ushort(l) | ((uint32_t)__bfloat16_as_ushort(h) << 16);
}

static __device__ __forceinline__ void ffma2(ull& acc, ull a, ull b) {
    asm volatile("fma.rn.f32x2 %0, %1, %2, %0;" : "+l"(acc) : "l"(a), "l"(b));
}
static __device__ __forceinline__ float2 u2f(ull v) {
    float2 f; asm("mov.b64 {%0, %1}, %2;" : "=f"(f.x), "=f"(f.y) : "l"(v)); return f;
}

// monotonic-counter grid barrier: arrival via non-returning reduction, poll acquire
static __device__ __forceinline__ void gbar(unsigned target) {
    __syncthreads();
    if (threadIdx.x == 0) {
        asm volatile("red.release.gpu.global.add.u32 [%0], 1;" :: "l"(&g_bar) : "memory");
        unsigned v;
        do {
            asm volatile("ld.acquire.gpu.global.u32 %0, [%1];" : "=r"(v) : "l"(&g_bar) : "memory");
        } while (v < target);
    }
    __syncthreads();
}

// ---------------- small prep kernels ----------------
__global__ void kt_init(const float* __restrict__ h0, const float* __restrict__ c0) {
    int i = blockIdx.x * 256 + threadIdx.x;
    if (i == 0) g_bar = 0;
    if (i < BB * HH) {
        int b = i / HH, j = i % HH;
        g_c[i] = c0[i];
        g_x[b * K2H + j] = 0.f;           // o_{-1} = 0
        g_x[b * K2H + HH + j] = h0[i];    // h_{-1} = h0
    }
}

__global__ void kt_gather(const float* __restrict__ emb, const int* __restrict__ ids) {
    int i = blockIdx.x * 256 + threadIdx.x;
    if (i >= TT * BB * EE) return;
    int e = i % EE; int tb = i / EE; int b = tb % BB; int t = tb / BB;
    int tok = ids[b * (TT + 1) + t];
    g_embseq[(t * BB + b) * EE + e] = emb[tok * EE + e];
}

// W_vocab -> bf16 fragment-swizzled layout
__global__ void kt_prepack_w(const float* __restrict__ Wv) {
    int i = blockIdx.x * 256 + threadIdx.x;
    if (i >= 4000 * 32 * 32) return;
    int lane = i & 31; int tile = i >> 5;
    int kt = tile & 31; int nrow = tile >> 5;
    int gid = lane >> 2, tg = lane & 3;
    int n = nrow * 8 + gid;
    int k = kt * 16 + tg * 2;
    const float* p = Wv + (size_t)n * HH + k;
    uint2 v;
    v.x = pk_bf2(p[0], p[1]);
    v.y = pk_bf2(p[8], p[9]);
    g_wswz[i] = v;
}

// o_seq -> bf16 fragment-swizzled layout
__global__ void kt_prepack_o() {
    int i = blockIdx.x * 256 + threadIdx.x;
    if (i >= 256 * 32 * 32) return;
    int lane = i & 31; int tile = i >> 5;
    int kt = tile & 31; int mrow = tile >> 5;
    int gid = lane >> 2, tg = lane & 3;
    int m = mrow * 16 + gid;
    int k = kt * 16 + tg * 2;
    const float* p = g_oseq + (size_t)m * HH + k;
    uint4 v;
    v.x = pk_bf2(p[0], p[1]);
    v.y = pk_bf2(p[8 * HH], p[8 * HH + 1]);
    v.z = pk_bf2(p[8], p[9]);
    v.w = pk_bf2(p[8 * HH + 8], p[8 * HH + 9]);
    g_oswz[i] = v;
}

// ---------------- generic fp32 GEMM: C[m][n] = sum_k A[m][k]*B[n][k] (+bias) ----------------
__global__ void __launch_bounds__(256) kt_gemm_nt(
    const float* __restrict__ A, int lda,
    const float* __restrict__ Bm, int ldb,
    float* __restrict__ C, int ldc,
    int K,
    const float* __restrict__ bias0,
    const float* __restrict__ bias1)
{
    __shared__ float As[16][65];
    __shared__ float Bs[16][65];
    int tid = threadIdx.x;
    int tx = tid & 15, ty = tid >> 4;
    int m0 = blockIdx.y * 64, n0 = blockIdx.x * 64;
    float acc[4][4];
#pragma unroll
    for (int i = 0; i < 4; i++)
#pragma unroll
        for (int j = 0; j < 4; j++) acc[i][j] = 0.f;

    for (int k0 = 0; k0 < K; k0 += 16) {
#pragma unroll
        for (int i = tid; i < 1024; i += 256) {
            int r = i >> 4, kk = i & 15;
            As[kk][r] = A[(size_t)(m0 + r) * lda + k0 + kk];
            Bs[kk][r] = Bm[(size_t)(n0 + r) * ldb + k0 + kk];
        }
        __syncthreads();
#pragma unroll
        for (int kk = 0; kk < 16; kk++) {
            float av[4], bv[4];
#pragma unroll
            for (int i = 0; i < 4; i++) av[i] = As[kk][ty * 4 + i];
#pragma unroll
            for (int j = 0; j < 4; j++) bv[j] = Bs[kk][tx * 4 + j];
#pragma unroll
            for (int i = 0; i < 4; i++)
#pragma unroll
                for (int j = 0; j < 4; j++) acc[i][j] += av[i] * bv[j];
        }
        __syncthreads();
    }
#pragma unroll
    for (int j = 0; j < 4; j++) {
        int n = n0 + tx * 4 + j;
        float bb = 0.f;
        if (bias0) bb += bias0[n];
        if (bias1) bb += bias1[n];
#pragma unroll
        for (int i = 0; i < 4; i++)
            C[(size_t)(m0 + ty * 4 + i) * ldc + n] = acc[i][j] + bb;
    }
}

// =================== persistent weight-stationary scan ===================
// SMEM layout (dynamic):
//   wg2  [16][512] float2  (64 KB)  : gate rows g = c*16+gg, k-pairs (o|h)
//   wd2  [4][768]  float2  (24 KB)  : dec rows j = c*4+jj
//   stage (131584 B)                : xs2[32][514] / us2[32][258] / phaseB scratch
#define SM_WG 0
#define SM_WD 65536
#define SM_ST 90112
#define SMEM_SCAN (90112 + 32*514*8)

__global__ void __launch_bounds__(256) kt_scan(
    const float* __restrict__ enc, const int* __restrict__ mask,
    const float* __restrict__ Wih, const float* __restrict__ Whh,
    const float* __restrict__ Wdec, const float* __restrict__ bdec)
{
    extern __shared__ char smem[];
    float2* wg2 = (float2*)(smem + SM_WG);
    float2* wd2 = (float2*)(smem + SM_WD);
    float*  stage = (float*)(smem + SM_ST);
    float2* xs2 = (float2*)stage;     // [32][514]
    float2* us2 = (float2*)stage;     // [32][258]

    int c = blockIdx.x, tid = threadIdx.x;

    // ---- load stationary weights (once) ----
    for (int idx = tid; idx < 16 * 512; idx += 256) {
        int gg = idx >> 9, kp = idx & 511;
        int g = c * 16 + gg; int k = kp * 2;
        float a, b2;
        if (k < 512) { a = Wih[g * 768 + 256 + k]; b2 = Wih[g * 768 + 257 + k]; }
        else         { a = Whh[g * 512 + k - 512]; b2 = Whh[g * 512 + k - 511]; }
        wg2[idx] = make_float2(a, b2);
    }
    for (int idx = tid; idx < 4 * 768; idx += 256) {
        int jj = idx / 768, kp = idx % 768;
        int j = c * 4 + jj;
        wd2[idx] = make_float2(Wdec[j * 1536 + kp * 2], Wdec[j * 1536 + kp * 2 + 1]);
    }
    unsigned tgt = 0;
    __syncthreads();

    for (int t = 0; t < TT; t++) {
        // ======== phase A: gates_rec[b][g] = W_gate[g] . x[b]  (all 128 CTAs) ========
        {
            const float4* gx4 = (const float4*)g_x;
            for (int idx = tid; idx < 32 * 256; idx += 256) {
                int b = idx >> 8, k4 = idx & 255;
                *(float4*)(xs2 + b * 514 + k4 * 2) = gx4[b * 256 + k4];
            }
            __syncthreads();

            int gg = tid >> 4, bp = tid & 15;
            const ull* wrow = (const ull*)(wg2 + gg * 512);
            const ull* x0r  = (const ull*)(xs2 + bp * 514);
            const ull* x1r  = (const ull*)(xs2 + (bp + 16) * 514);
            ull a0e = 0, a0o = 0, a1e = 0, a1o = 0;
#pragma unroll 4
            for (int kp = 0; kp < 512; kp += 2) {
                ull w0 = wrow[kp], w1 = wrow[kp + 1];
                ffma2(a0e, w0, x0r[kp]);
                ffma2(a1e, w0, x1r[kp]);
                ffma2(a0o, w1, x0r[kp + 1]);
                ffma2(a1o, w1, x1r[kp + 1]);
            }
            float2 f0e = u2f(a0e), f0o = u2f(a0o), f1e = u2f(a1e), f1o = u2f(a1o);
            int gcol = c * 16 + gg;
            g_gates[bp * G4 + gcol]        = f0e.x + f0e.y + f0o.x + f0o.y;
            g_gates[(bp + 16) * G4 + gcol] = f1e.x + f1e.y + f1o.x + f1o.y;
        }
        gbar(tgt += NBLK);

        // ======== phase B: cell + attention + context (32 CTAs, one per batch) ========
        if (c < BB) {
            int b = c;
            float* hs  = stage;         // 512
            float* sc  = stage + 512;   // 128
            float* red = stage + 640;   // 256

            const float* gy = g_gatesy + (size_t)(t * BB + b) * G4;
            const float* gr = g_gates + b * G4;
            for (int j = tid; j < HH; j += 256) {
                float vi = gy[j]        + gr[j];
                float vf = gy[512 + j]  + gr[512 + j];
                float vg = gy[1024 + j] + gr[1024 + j];
                float vo = gy[1536 + j] + gr[1536 + j];
                float cc = g_c[b * HH + j];
                float ig = 1.f / (1.f + __expf(-vi));
                float fg = 1.f / (1.f + __expf(-vf));
                float gg = tanhf(vg);
                float og = 1.f / (1.f + __expf(-vo));
                float cn = fg * cc + ig * gg;
                float hn = og * tanhf(cn);
                g_c[b * HH + j] = cn;
                hs[j] = hn;
                g_x[b * K2H + HH + j] = hn;
                g_u[b * UD + K2H + j] = hn;
            }
            __syncthreads();

            // scores: each warp 16 s values
            int w = tid >> 5, lane = tid & 31;
            float4 hreg[4];
#pragma unroll
            for (int q = 0; q < 4; q++)
                hreg[q] = *(const float4*)(hs + (lane + q * 32) * 4);
#pragma unroll 2
            for (int si = 0; si < 16; si++) {
                int s = w * 16 + si;
                const float4* kp = (const float4*)(g_keys + (size_t)(b * SSRC + s) * HH);
                float acc = 0.f;
#pragma unroll
                for (int q = 0; q < 4; q++) {
                    float4 kv = kp[lane + q * 32];
                    acc += hreg[q].x * kv.x + hreg[q].y * kv.y
                         + hreg[q].z * kv.z + hreg[q].w * kv.w;
                }
#pragma unroll
                for (int off = 16; off; off >>= 1)
                    acc += __shfl_down_sync(0xffffffffu, acc, off);
                if (lane == 0) {
                    float bias = (mask[b * SSRC + s] > 0) ? 0.f : -1e9f;
                    sc[s] = acc + bias;
                }
            }
            __syncthreads();

            // softmax over 128
            float v = (tid < SSRC) ? sc[tid] : -INFINITY;
            red[tid] = v;
            __syncthreads();
#pragma unroll
            for (int off = 128; off; off >>= 1) {
                if (tid < off) red[tid] = fmaxf(red[tid], red[tid + off]);
                __syncthreads();
            }
            float m = red[0];
            __syncthreads();
            float e = (tid < SSRC) ? __expf(v - m) : 0.f;
            red[tid] = e;
            __syncthreads();
#pragma unroll
            for (int off = 128; off; off >>= 1) {
                if (tid < off) red[tid] += red[tid + off];
                __syncthreads();
            }
            float inv = 1.f / red[0];
            __syncthreads();
            if (tid < SSRC) sc[tid] = e * inv;
            __syncthreads();

            // context a = attn @ enc_out  (thread owns one float4 of 1024)
            int k4 = tid * 4;
            float4 acc = {0, 0, 0, 0};
            const float* ep = enc + (size_t)(b * SSRC) * K2H + k4;
#pragma unroll 4
            for (int s = 0; s < SSRC; s++) {
                float ws = sc[s];
                float4 ev = *(const float4*)(ep + (size_t)s * K2H);
                acc.x += ws * ev.x; acc.y += ws * ev.y;
                acc.z += ws * ev.z; acc.w += ws * ev.w;
            }
            *(float4*)(g_u + b * UD + k4) = acc;
        }
        gbar(tgt += NBLK);

        // ======== phase C: o_t[b][j] = tanh(W_dec[j] . u[b] + b_dec[j])  (all CTAs) ========
        {
            int jj = tid >> 6, b = (tid >> 1) & 31, kh = tid & 1;
            ull accd = 0;
            const float4* gu4 = (const float4*)g_u;
            for (int ck = 0; ck < 3; ck++) {
                for (int idx = tid; idx < 32 * 128; idx += 256) {
                    int bb = idx >> 7, k4 = idx & 127;
                    *(float4*)(us2 + bb * 258 + k4 * 2) = gu4[bb * 384 + ck * 128 + k4];
                }
                __syncthreads();
                const ull* urow = (const ull*)(us2 + b * 258 + kh * 128);
                const ull* wrow = (const ull*)(wd2 + jj * 768 + ck * 256 + kh * 128);
#pragma unroll 8
                for (int kp = 0; kp < 128; kp++)
                    ffma2(accd, wrow[kp], urow[kp]);
                __syncthreads();
            }
            float2 fd = u2f(accd);
            float sum = fd.x + fd.y;
            sum += __shfl_xor_sync(0xffffffffu, sum, 1);
            if (kh == 0) {
                int j = c * 4 + jj;
                float o = tanhf(sum + bdec[j]);
                g_x[b * K2H + j] = o;
                g_oseq[((size_t)b * TT + t) * HH + j] = o;
            }
        }
        gbar(tgt += NBLK);
    }
}

// ---------------- vocab GEMM (preswizzled fragments) + fused sum-exp partials ----------------
#define MMA16816(d0,d1,d2,d3,A0,A1,A2,A3,B0,B1) \
    asm volatile("mma.sync.aligned.m16n8k16.row.col.f32.bf16.bf16.f32 " \
        "{%0,%1,%2,%3}, {%4,%5,%6,%7}, {%8,%9}, {%0,%1,%2,%3};" \
        : "+f"(d0), "+f"(d1), "+f"(d2), "+f"(d3) \
        : "r"(A0), "r"(A1), "r"(A2), "r"(A3), "r"(B0), "r"(B1))

__global__ void __launch_bounds__(256) kt_vocab_gemm(
    float* __restrict__ out, const float* __restrict__ bvocab)
{
    int nb = blockIdx.x;   // 0..249
    int mb = blockIdx.y;   // 0..31
    int wid = threadIdx.x >> 5;
    int lane = threadIdx.x & 31;
    int wm = wid >> 2;     // 0..1
    int wn = wid & 3;      // 0..3
    int gid = lane >> 2;
    int tg = lane & 3;

    __shared__ float rowsum[128][4];
    if (threadIdx.x < 128) {
#pragma unroll
        for (int w = 0; w < 4; w++) rowsum[threadIdx.x][w] = 0.f;
    }
    __syncthreads();

    float acc[4][4][4];
#pragma unroll
    for (int i = 0; i < 4; i++)
#pragma unroll
        for (int j = 0; j < 4; j++)
#pragma unroll
            for (int r = 0; r < 4; r++) acc[i][j][r] = 0.f;

    int mrow0 = mb * 8 + wm * 4;
    int nrow0 = nb * 16 + wn * 4;

#pragma unroll 2
    for (int kt = 0; kt < 32; kt++) {
        uint4 af[4];
        uint2 bf[4];
#pragma unroll
        for (int mt = 0; mt < 4; mt++)
            af[mt] = g_oswz[(((mrow0 + mt) * 32 + kt) << 5) + lane];
#pragma unroll
        for (int nt = 0; nt < 4; nt++)
            bf[nt] = g_wswz[(((size_t)(nrow0 + nt) * 32 + kt) << 5) + lane];
#pragma unroll
        for (int mt = 0; mt < 4; mt++)
#pragma unroll
            for (int nt = 0; nt < 4; nt++)
                MMA16816(acc[mt][nt][0], acc[mt][nt][1], acc[mt][nt][2], acc[mt][nt][3],
                         af[mt].x, af[mt].y, af[mt].z, af[mt].w,
                         bf[nt].x, bf[nt].y);
    }

    int m_warp = mb * 128 + wm * 64;
    int n_warp = nb * 128 + wn * 32;
#pragma unroll
    for (int mt = 0; mt < 4; mt++) {
        float s0 = 0.f, s1 = 0.f;
#pragma unroll
        for (int nt = 0; nt < 4; nt++) {
            int r = m_warp + mt * 16 + gid;
            int cidx = n_warp + nt * 8 + tg * 2;
            float bv0 = bvocab[cidx], bv1 = bvocab[cidx + 1];
            float v00 = acc[mt][nt][0] + bv0, v01 = acc[mt][nt][1] + bv1;
            float v10 = acc[mt][nt][2] + bv0, v11 = acc[mt][nt][3] + bv1;
            float2 w0 = { v00, v01 }, w1 = { v10, v11 };
            *reinterpret_cast<float2*>(out + (size_t)r * VV + cidx) = w0;
            *reinterpret_cast<float2*>(out + (size_t)(r + 8) * VV + cidx) = w1;
            s0 += __expf(v00) + __expf(v01);
            s1 += __expf(v10) + __expf(v11);
        }
        s0 += __shfl_xor_sync(0xffffffffu, s0, 1);
        s0 += __shfl_xor_sync(0xffffffffu, s0, 2);
        s1 += __shfl_xor_sync(0xffffffffu, s1, 1);
        s1 += __shfl_xor_sync(0xffffffffu, s1, 2);
        if (tg == 0) {
            rowsum[wm * 64 + mt * 16 + gid][wn] = s0;
            rowsum[wm * 64 + mt * 16 + gid + 8][wn] = s1;
        }
    }
    __syncthreads();
    if (threadIdx.x < 128) {
        float p = rowsum[threadIdx.x][0] + rowsum[threadIdx.x][1]
                + rowsum[threadIdx.x][2] + rowsum[threadIdx.x][3];
        g_partial[(size_t)(mb * 128 + threadIdx.x) * NTILE + nb] = p;
    }
}

// ---------------- final log-softmax subtract ----------------
__global__ void __launch_bounds__(256) kt_lsfinal(float* __restrict__ out) {
    int row = blockIdx.x;
    int tid = threadIdx.x;
    __shared__ float red[256];
    __shared__ float lse_s;
    float s = 0.f;
    for (int i = tid; i < NTILE; i += 256) s += g_partial[(size_t)row * NTILE + i];
    red[tid] = s;
    __syncthreads();
#pragma unroll
    for (int off = 128; off; off >>= 1) {
        if (tid < off) red[tid] += red[tid + off];
        __syncthreads();
    }
    if (tid == 0) lse_s = logf(red[0]);
    __syncthreads();
    float lse = lse_s;
    float* p = out + (size_t)row * VV;
    for (int i = tid * 4; i < VV; i += 256 * 4) {
        float4 v = *reinterpret_cast<float4*>(p + i);
        v.x -= lse; v.y -= lse; v.z -= lse; v.w -= lse;
        *reinterpret_cast<float4*>(p + i) = v;
    }
}

// ---------------- launch ----------------
extern "C" void kernel_launch(void* const* d_in, const int* in_sizes, int n_in,
                              void* d_out, int out_size)
{
    const float* enc     = (const float*)d_in[0];
    const int*   mask    = (const int*)  d_in[1];
    const int*   ids     = (const int*)  d_in[2];
    const float* h0      = (const float*)d_in[3];
    const float* c0      = (const float*)d_in[4];
    const float* emb     = (const float*)d_in[5];
    const float* W_ih    = (const float*)d_in[6];
    const float* b_ih    = (const float*)d_in[7];
    const float* W_hh    = (const float*)d_in[8];
    const float* b_hh    = (const float*)d_in[9];
    const float* W_att   = (const float*)d_in[10];
    const float* W_dec   = (const float*)d_in[11];
    const float* b_dec   = (const float*)d_in[12];
    const float* W_vocab = (const float*)d_in[13];
    const float* b_vocab = (const float*)d_in[14];
    float* out = (float*)d_out;

    cudaFuncSetAttribute(kt_scan, cudaFuncAttributeMaxDynamicSharedMemorySize, SMEM_SCAN);

    // prep
    kt_init<<<(BB*HH + 255)/256, 256>>>(h0, c0);
    kt_gather<<<(TT*BB*EE + 255)/256, 256>>>(emb, ids);

    {
        float* keysp; cudaGetSymbolAddress((void**)&keysp, g_keys);
        float* embp;  cudaGetSymbolAddress((void**)&embp, g_embseq);
        float* gyp;   cudaGetSymbolAddress((void**)&gyp, g_gatesy);
        // keys = enc_out @ W_att^T : M=4096 N=512 K=1024
        kt_gemm_nt<<<dim3(512/64, 4096/64), 256>>>(enc, K2H, W_att, K2H, keysp, HH,
                                                   K2H, nullptr, nullptr);
        // gates_y = emb_seq @ W_ih[:, :256]^T + b_ih + b_hh : M=4096 N=2048 K=256
        kt_gemm_nt<<<dim3(G4/64, 4096/64), 256>>>(embp, EE, W_ih, 768, gyp, G4,
                                                  EE, b_ih, b_hh);
    }

    // persistent weight-stationary scan: one launch for all 128 steps
    kt_scan<<<NBLK, 256, SMEM_SCAN>>>(enc, mask, W_ih, W_hh, W_dec, b_dec);

    // vocab projection + fused sum-exp + log-softmax subtract
    kt_prepack_w<<<(4000*32*32 + 255)/256, 256>>>(W_vocab);
    kt_prepack_o<<<(256*32*32 + 255)/256, 256>>>();
    kt_vocab_gemm<<<dim3(NTILE, (BB*TT)/128), 256>>>(out, b_vocab);
    kt_lsfinal<<<BB*TT, 256>>>(out);
}

// round 4
// speedup vs baseline: 1.5350x; 1.0140x over previous
#include <cuda_runtime.h>
#include <cuda_bf16.h>
#include <cstdint>
#include <math.h>

// Problem dims
#define BB 32
#define TT 128
#define SSRC 128
#define HH 512
#define EE 256
#define VV 32000
#define K2H 1024   // 2H
#define G4 2048    // 4H
#define UD 1536    // 2H + H
#define NBLK 128   // persistent scan grid
#define NTILE 250  // 32000/128 vocab n-blocks

typedef unsigned long long ull;

// ---------------- device scratch (static, no allocation) ----------------
static __device__ float g_keys[BB*SSRC*HH];          // [b][s][h]
static __device__ float g_gatesy[TT*BB*G4];          // [t][b][g] (emb part + biases)
static __device__ float g_embseq[TT*BB*EE];          // [t][b][e]
static __device__ float g_x[BB*K2H];                 // x_t = [o_{t-1}(512), h_{t-1}(512)] per b
static __device__ float g_c[BB*HH];
static __device__ float g_u[BB*UD];                  // [a(1024), h(512)]
static __device__ float g_gates[BB*G4];              // recurrent gate part [b][g]
static __device__ float g_oseq[BB*TT*HH];            // row n = b*T+t
static __device__ uint4 g_oswz[256*32*32];           // A fragments: (mrow,kt,lane)
static __device__ uint2 g_wswz[4000*32*32];          // B fragments: (nrow,kt,lane)
static __device__ float g_partial[(size_t)BB*TT*NTILE]; // sum-exp partials
static __device__ unsigned g_bar;

// ---------------- helpers ----------------
static __device__ __forceinline__ uint32_t pk_bf2(float lo, float hi) {
    __nv_bfloat16 l = __float2bfloat16(lo), h = __float2bfloat16(hi);
    return (uint32_t)__bfloat16_as_ushort(l) | ((uint32_t)__bfloat16_as_ushort(h) << 16);
}

static __device__ __forceinline__ void ffma2(ull& acc, ull a, ull b) {
    asm volatile("fma.rn.f32x2 %0, %1, %2, %0;" : "+l"(acc) : "l"(a), "l"(b));
}
static __device__ __forceinline__ float2 u2f(ull v) {
    float2 f; asm("mov.b64 {%0, %1}, %2;" : "=f"(f.x), "=f"(f.y) : "l"(v)); return f;
}

// monotonic-counter grid barrier: arrival via non-returning reduction, poll acquire
static __device__ __forceinline__ void gbar(unsigned target) {
    __syncthreads();
    if (threadIdx.x == 0) {
        asm volatile("red.release.gpu.global.add.u32 [%0], 1;" :: "l"(&g_bar) : "memory");
        unsigned v;
        do {
            asm volatile("ld.acquire.gpu.global.u32 %0, [%1];" : "=r"(v) : "l"(&g_bar) : "memory");
        } while (v < target);
    }
    __syncthreads();
}

// ---------------- small prep kernels ----------------
__global__ void kt_init(const float* __restrict__ h0, const float* __restrict__ c0) {
    int i = blockIdx.x * 256 + threadIdx.x;
    if (i == 0) g_bar = 0;
    if (i < BB * HH) {
        int b = i / HH, j = i % HH;
        g_c[i] = c0[i];
        g_x[b * K2H + j] = 0.f;           // o_{-1} = 0
        g_x[b * K2H + HH + j] = h0[i];    // h_{-1} = h0
    }
}

__global__ void kt_gather(const float* __restrict__ emb, const int* __restrict__ ids) {
    int i = blockIdx.x * 256 + threadIdx.x;
    if (i >= TT * BB * EE) return;
    int e = i % EE; int tb = i / EE; int b = tb % BB; int t = tb / BB;
    int tok = ids[b * (TT + 1) + t];
    g_embseq[(t * BB + b) * EE + e] = emb[tok * EE + e];
}

// W_vocab -> bf16 fragment-swizzled layout
__global__ void kt_prepack_w(const float* __restrict__ Wv) {
    int i = blockIdx.x * 256 + threadIdx.x;
    if (i >= 4000 * 32 * 32) return;
    int lane = i & 31; int tile = i >> 5;
    int kt = tile & 31; int nrow = tile >> 5;
    int gid = lane >> 2, tg = lane & 3;
    int n = nrow * 8 + gid;
    int k = kt * 16 + tg * 2;
    const float* p = Wv + (size_t)n * HH + k;
    uint2 v;
    v.x = pk_bf2(p[0], p[1]);
    v.y = pk_bf2(p[8], p[9]);
    g_wswz[i] = v;
}

// o_seq -> bf16 fragment-swizzled layout
__global__ void kt_prepack_o() {
    int i = blockIdx.x * 256 + threadIdx.x;
    if (i >= 256 * 32 * 32) return;
    int lane = i & 31; int tile = i >> 5;
    int kt = tile & 31; int mrow = tile >> 5;
    int gid = lane >> 2, tg = lane & 3;
    int m = mrow * 16 + gid;
    int k = kt * 16 + tg * 2;
    const float* p = g_oseq + (size_t)m * HH + k;
    uint4 v;
    v.x = pk_bf2(p[0], p[1]);
    v.y = pk_bf2(p[8 * HH], p[8 * HH + 1]);
    v.z = pk_bf2(p[8], p[9]);
    v.w = pk_bf2(p[8 * HH + 8], p[8 * HH + 9]);
    g_oswz[i] = v;
}

// ---------------- generic fp32 GEMM: C[m][n] = sum_k A[m][k]*B[n][k] (+bias) ----------------
__global__ void __launch_bounds__(256) kt_gemm_nt(
    const float* __restrict__ A, int lda,
    const float* __restrict__ Bm, int ldb,
    float* __restrict__ C, int ldc,
    int K,
    const float* __restrict__ bias0,
    const float* __restrict__ bias1)
{
    __shared__ float As[16][65];
    __shared__ float Bs[16][65];
    int tid = threadIdx.x;
    int tx = tid & 15, ty = tid >> 4;
    int m0 = blockIdx.y * 64, n0 = blockIdx.x * 64;
    float acc[4][4];
#pragma unroll
    for (int i = 0; i < 4; i++)
#pragma unroll
        for (int j = 0; j < 4; j++) acc[i][j] = 0.f;

    for (int k0 = 0; k0 < K; k0 += 16) {
#pragma unroll
        for (int i = tid; i < 1024; i += 256) {
            int r = i >> 4, kk = i & 15;
            As[kk][r] = A[(size_t)(m0 + r) * lda + k0 + kk];
            Bs[kk][r] = Bm[(size_t)(n0 + r) * ldb + k0 + kk];
        }
        __syncthreads();
#pragma unroll
        for (int kk = 0; kk < 16; kk++) {
            float av[4], bv[4];
#pragma unroll
            for (int i = 0; i < 4; i++) av[i] = As[kk][ty * 4 + i];
#pragma unroll
            for (int j = 0; j < 4; j++) bv[j] = Bs[kk][tx * 4 + j];
#pragma unroll
            for (int i = 0; i < 4; i++)
#pragma unroll
                for (int j = 0; j < 4; j++) acc[i][j] += av[i] * bv[j];
        }
        __syncthreads();
    }
#pragma unroll
    for (int j = 0; j < 4; j++) {
        int n = n0 + tx * 4 + j;
        float bb = 0.f;
        if (bias0) bb += bias0[n];
        if (bias1) bb += bias1[n];
#pragma unroll
        for (int i = 0; i < 4; i++)
            C[(size_t)(m0 + ty * 4 + i) * ldc + n] = acc[i][j] + bb;
    }
}

// =================== persistent weight-stationary scan ===================
// SMEM layout (dynamic):
//   wg2  [16][512] float2  (64 KB)  : gate rows g = c*16+gg, k-pairs (o|h)
//   wd2  [4][768]  float2  (24 KB)  : dec rows j = c*4+jj
//   stage (131584 B)                : xs2[32][514] / us2[32][258] / phaseB scratch
#define SM_WG 0
#define SM_WD 65536
#define SM_ST 90112
#define SMEM_SCAN (90112 + 32*514*8)

__global__ void __launch_bounds__(256) kt_scan(
    const float* __restrict__ enc, const int* __restrict__ mask,
    const float* __restrict__ Wih, const float* __restrict__ Whh,
    const float* __restrict__ Wdec, const float* __restrict__ bdec)
{
    extern __shared__ char smem[];
    float2* wg2 = (float2*)(smem + SM_WG);
    float2* wd2 = (float2*)(smem + SM_WD);
    float*  stage = (float*)(smem + SM_ST);
    float2* xs2 = (float2*)stage;     // [32][514]
    float2* us2 = (float2*)stage;     // [32][258]

    int c = blockIdx.x, tid = threadIdx.x;

    // ---- load stationary weights (once) ----
    for (int idx = tid; idx < 16 * 512; idx += 256) {
        int gg = idx >> 9, kp = idx & 511;
        int g = c * 16 + gg; int k = kp * 2;
        float a, b2;
        if (k < 512) { a = Wih[g * 768 + 256 + k]; b2 = Wih[g * 768 + 257 + k]; }
        else         { a = Whh[g * 512 + k - 512]; b2 = Whh[g * 512 + k - 511]; }
        wg2[idx] = make_float2(a, b2);
    }
    for (int idx = tid; idx < 4 * 768; idx += 256) {
        int jj = idx / 768, kp = idx % 768;
        int j = c * 4 + jj;
        wd2[idx] = make_float2(Wdec[j * 1536 + kp * 2], Wdec[j * 1536 + kp * 2 + 1]);
    }
    unsigned tgt = 0;
    __syncthreads();

    for (int t = 0; t < TT; t++) {
        // ======== phase A: gates_rec[b][g] = W_gate[g] . x[b]  (all 128 CTAs) ========
        {
            const float4* gx4 = (const float4*)g_x;
            for (int idx = tid; idx < 32 * 256; idx += 256) {
                int b = idx >> 8, k4 = idx & 255;
                *(float4*)(xs2 + b * 514 + k4 * 2) = gx4[b * 256 + k4];
            }
            __syncthreads();

            int gg = tid >> 4, bp = tid & 15;
            const ull* wrow = (const ull*)(wg2 + gg * 512);
            const ull* x0r  = (const ull*)(xs2 + bp * 514);
            const ull* x1r  = (const ull*)(xs2 + (bp + 16) * 514);
            ull a0e = 0, a0o = 0, a1e = 0, a1o = 0;
#pragma unroll 4
            for (int kp = 0; kp < 512; kp += 2) {
                ull w0 = wrow[kp], w1 = wrow[kp + 1];
                ffma2(a0e, w0, x0r[kp]);
                ffma2(a1e, w0, x1r[kp]);
                ffma2(a0o, w1, x0r[kp + 1]);
                ffma2(a1o, w1, x1r[kp + 1]);
            }
            float2 f0e = u2f(a0e), f0o = u2f(a0o), f1e = u2f(a1e), f1o = u2f(a1o);
            int gcol = c * 16 + gg;
            g_gates[bp * G4 + gcol]        = f0e.x + f0e.y + f0o.x + f0o.y;
            g_gates[(bp + 16) * G4 + gcol] = f1e.x + f1e.y + f1o.x + f1o.y;
        }
        gbar(tgt += NBLK);

        // ======== phase B: cell + attention + context (32 CTAs, one per batch) ========
        if (c < BB) {
            int b = c;
            float* hs  = stage;         // 512
            float* sc  = stage + 512;   // 128
            float* red = stage + 640;   // 256

            const float* gy = g_gatesy + (size_t)(t * BB + b) * G4;
            const float* gr = g_gates + b * G4;
            for (int j = tid; j < HH; j += 256) {
                float vi = gy[j]        + gr[j];
                float vf = gy[512 + j]  + gr[512 + j];
                float vg = gy[1024 + j] + gr[1024 + j];
                float vo = gy[1536 + j] + gr[1536 + j];
                float cc = g_c[b * HH + j];
                float ig = 1.f / (1.f + __expf(-vi));
                float fg = 1.f / (1.f + __expf(-vf));
                float gg = tanhf(vg);
                float og = 1.f / (1.f + __expf(-vo));
                float cn = fg * cc + ig * gg;
                float hn = og * tanhf(cn);
                g_c[b * HH + j] = cn;
                hs[j] = hn;
                g_x[b * K2H + HH + j] = hn;
                g_u[b * UD + K2H + j] = hn;
            }
            __syncthreads();

            // scores: each warp 16 s values
            int w = tid >> 5, lane = tid & 31;
            float4 hreg[4];
#pragma unroll
            for (int q = 0; q < 4; q++)
                hreg[q] = *(const float4*)(hs + (lane + q * 32) * 4);
#pragma unroll 2
            for (int si = 0; si < 16; si++) {
                int s = w * 16 + si;
                const float4* kp = (const float4*)(g_keys + (size_t)(b * SSRC + s) * HH);
                float acc = 0.f;
#pragma unroll
                for (int q = 0; q < 4; q++) {
                    float4 kv = kp[lane + q * 32];
                    acc += hreg[q].x * kv.x + hreg[q].y * kv.y
                         + hreg[q].z * kv.z + hreg[q].w * kv.w;
                }
#pragma unroll
                for (int off = 16; off; off >>= 1)
                    acc += __shfl_down_sync(0xffffffffu, acc, off);
                if (lane == 0) {
                    float bias = (mask[b * SSRC + s] > 0) ? 0.f : -1e9f;
                    sc[s] = acc + bias;
                }
            }
            __syncthreads();

            // softmax over 128
            float v = (tid < SSRC) ? sc[tid] : -INFINITY;
            red[tid] = v;
            __syncthreads();
#pragma unroll
            for (int off = 128; off; off >>= 1) {
                if (tid < off) red[tid] = fmaxf(red[tid], red[tid + off]);
                __syncthreads();
            }
            float m = red[0];
            __syncthreads();
            float e = (tid < SSRC) ? __expf(v - m) : 0.f;
            red[tid] = e;
            __syncthreads();
#pragma unroll
            for (int off = 128; off; off >>= 1) {
                if (tid < off) red[tid] += red[tid + off];
                __syncthreads();
            }
            float inv = 1.f / red[0];
            __syncthreads();
            if (tid < SSRC) sc[tid] = e * inv;
            __syncthreads();

            // context a = attn @ enc_out  (thread owns one float4 of 1024)
            int k4 = tid * 4;
            float4 acc = {0, 0, 0, 0};
            const float* ep = enc + (size_t)(b * SSRC) * K2H + k4;
#pragma unroll 4
            for (int s = 0; s < SSRC; s++) {
                float ws = sc[s];
                float4 ev = *(const float4*)(ep + (size_t)s * K2H);
                acc.x += ws * ev.x; acc.y += ws * ev.y;
                acc.z += ws * ev.z; acc.w += ws * ev.w;
            }
            *(float4*)(g_u + b * UD + k4) = acc;
        }
        gbar(tgt += NBLK);

        // ======== phase C: o_t[b][j] = tanh(W_dec[j] . u[b] + b_dec[j])  (all CTAs) ========
        {
            int jj = tid >> 6, b = (tid >> 1) & 31, kh = tid & 1;
            ull accd = 0;
            const float4* gu4 = (const float4*)g_u;
            for (int ck = 0; ck < 3; ck++) {
                for (int idx = tid; idx < 32 * 128; idx += 256) {
                    int bb = idx >> 7, k4 = idx & 127;
                    *(float4*)(us2 + bb * 258 + k4 * 2) = gu4[bb * 384 + ck * 128 + k4];
                }
                __syncthreads();
                const ull* urow = (const ull*)(us2 + b * 258 + kh * 128);
                const ull* wrow = (const ull*)(wd2 + jj * 768 + ck * 256 + kh * 128);
#pragma unroll 8
                for (int kp = 0; kp < 128; kp++)
                    ffma2(accd, wrow[kp], urow[kp]);
                __syncthreads();
            }
            float2 fd = u2f(accd);
            float sum = fd.x + fd.y;
            sum += __shfl_xor_sync(0xffffffffu, sum, 1);
            if (kh == 0) {
                int j = c * 4 + jj;
                float o = tanhf(sum + bdec[j]);
                g_x[b * K2H + j] = o;
                g_oseq[((size_t)b * TT + t) * HH + j] = o;
            }
        }
        gbar(tgt += NBLK);
    }
}

// ---------------- vocab GEMM (preswizzled fragments) + fused sum-exp partials ----------------
#define MMA16816(d0,d1,d2,d3,A0,A1,A2,A3,B0,B1) \
    asm volatile("mma.sync.aligned.m16n8k16.row.col.f32.bf16.bf16.f32 " \
        "{%0,%1,%2,%3}, {%4,%5,%6,%7}, {%8,%9}, {%0,%1,%2,%3};" \
        : "+f"(d0), "+f"(d1), "+f"(d2), "+f"(d3) \
        : "r"(A0), "r"(A1), "r"(A2), "r"(A3), "r"(B0), "r"(B1))

__global__ void __launch_bounds__(256) kt_vocab_gemm(
    float* __restrict__ out, const float* __restrict__ bvocab)
{
    int nb = blockIdx.x;   // 0..249
    int mb = blockIdx.y;   // 0..31
    int wid = threadIdx.x >> 5;
    int lane = threadIdx.x & 31;
    int wm = wid >> 2;     // 0..1
    int wn = wid & 3;      // 0..3
    int gid = lane >> 2;
    int tg = lane & 3;

    __shared__ float rowsum[128][4];
    if (threadIdx.x < 128) {
#pragma unroll
        for (int w = 0; w < 4; w++) rowsum[threadIdx.x][w] = 0.f;
    }
    __syncthreads();

    float acc[4][4][4];
#pragma unroll
    for (int i = 0; i < 4; i++)
#pragma unroll
        for (int j = 0; j < 4; j++)
#pragma unroll
            for (int r = 0; r < 4; r++) acc[i][j][r] = 0.f;

    int mrow0 = mb * 8 + wm * 4;
    int nrow0 = nb * 16 + wn * 4;

#pragma unroll 2
    for (int kt = 0; kt < 32; kt++) {
        uint4 af[4];
        uint2 bf[4];
#pragma unroll
        for (int mt = 0; mt < 4; mt++)
            af[mt] = g_oswz[(((mrow0 + mt) * 32 + kt) << 5) + lane];
#pragma unroll
        for (int nt = 0; nt < 4; nt++)
            bf[nt] = g_wswz[(((size_t)(nrow0 + nt) * 32 + kt) << 5) + lane];
#pragma unroll
        for (int mt = 0; mt < 4; mt++)
#pragma unroll
            for (int nt = 0; nt < 4; nt++)
                MMA16816(acc[mt][nt][0], acc[mt][nt][1], acc[mt][nt][2], acc[mt][nt][3],
                         af[mt].x, af[mt].y, af[mt].z, af[mt].w,
                         bf[nt].x, bf[nt].y);
    }

    int m_warp = mb * 128 + wm * 64;
    int n_warp = nb * 128 + wn * 32;
#pragma unroll
    for (int mt = 0; mt < 4; mt++) {
        float s0 = 0.f, s1 = 0.f;
#pragma unroll
        for (int nt = 0; nt < 4; nt++) {
            int r = m_warp + mt * 16 + gid;
            int cidx = n_warp + nt * 8 + tg * 2;
            float bv0 = bvocab[cidx], bv1 = bvocab[cidx + 1];
            float v00 = acc[mt][nt][0] + bv0, v01 = acc[mt][nt][1] + bv1;
            float v10 = acc[mt][nt][2] + bv0, v11 = acc[mt][nt][3] + bv1;
            float2 w0 = { v00, v01 }, w1 = { v10, v11 };
            *reinterpret_cast<float2*>(out + (size_t)r * VV + cidx) = w0;
            *reinterpret_cast<float2*>(out + (size_t)(r + 8) * VV + cidx) = w1;
            s0 += __expf(v00) + __expf(v01);
            s1 += __expf(v10) + __expf(v11);
        }
        s0 += __shfl_xor_sync(0xffffffffu, s0, 1);
        s0 += __shfl_xor_sync(0xffffffffu, s0, 2);
        s1 += __shfl_xor_sync(0xffffffffu, s1, 1);
        s1 += __shfl_xor_sync(0xffffffffu, s1, 2);
        if (tg == 0) {
            rowsum[wm * 64 + mt * 16 + gid][wn] = s0;
            rowsum[wm * 64 + mt * 16 + gid + 8][wn] = s1;
        }
    }
    __syncthreads();
    if (threadIdx.x < 128) {
        float p = rowsum[threadIdx.x][0] + rowsum[threadIdx.x][1]
                + rowsum[threadIdx.x][2] + rowsum[threadIdx.x][3];
        g_partial[(size_t)(mb * 128 + threadIdx.x) * NTILE + nb] = p;
    }
}

// ---------------- final log-softmax subtract ----------------
__global__ void __launch_bounds__(256) kt_lsfinal(float* __restrict__ out) {
    int row = blockIdx.x;
    int tid = threadIdx.x;
    __shared__ float red[256];
    __shared__ float lse_s;
    float s = 0.f;
    for (int i = tid; i < NTILE; i += 256) s += g_partial[(size_t)row * NTILE + i];
    red[tid] = s;
    __syncthreads();
#pragma unroll
    for (int off = 128; off; off >>= 1) {
        if (tid < off) red[tid] += red[tid + off];
        __syncthreads();
    }
    if (tid == 0) lse_s = logf(red[0]);
    __syncthreads();
    float lse = lse_s;
    float* p = out + (size_t)row * VV;
    for (int i = tid * 4; i < VV; i += 256 * 4) {
        float4 v = *reinterpret_cast<float4*>(p + i);
        v.x -= lse; v.y -= lse; v.z -= lse; v.w -= lse;
        *reinterpret_cast<float4*>(p + i) = v;
    }
}

// ---------------- launch ----------------
extern "C" void kernel_launch(void* const* d_in, const int* in_sizes, int n_in,
                              void* d_out, int out_size)
{
    const float* enc     = (const float*)d_in[0];
    const int*   mask    = (const int*)  d_in[1];
    const int*   ids     = (const int*)  d_in[2];
    const float* h0      = (const float*)d_in[3];
    const float* c0      = (const float*)d_in[4];
    const float* emb     = (const float*)d_in[5];
    const float* W_ih    = (const float*)d_in[6];
    const float* b_ih    = (const float*)d_in[7];
    const float* W_hh    = (const float*)d_in[8];
    const float* b_hh    = (const float*)d_in[9];
    const float* W_att   = (const float*)d_in[10];
    const float* W_dec   = (const float*)d_in[11];
    const float* b_dec   = (const float*)d_in[12];
    const float* W_vocab = (const float*)d_in[13];
    const float* b_vocab = (const float*)d_in[14];
    float* out = (float*)d_out;

    cudaFuncSetAttribute(kt_scan, cudaFuncAttributeMaxDynamicSharedMemorySize, SMEM_SCAN);

    // prep
    kt_init<<<(BB*HH + 255)/256, 256>>>(h0, c0);
    kt_gather<<<(TT*BB*EE + 255)/256, 256>>>(emb, ids);

    {
        float* keysp; cudaGetSymbolAddress((void**)&keysp, g_keys);
        float* embp;  cudaGetSymbolAddress((void**)&embp, g_embseq);
        float* gyp;   cudaGetSymbolAddress((void**)&gyp, g_gatesy);
        // keys = enc_out @ W_att^T : M=4096 N=512 K=1024
        kt_gemm_nt<<<dim3(512/64, 4096/64), 256>>>(enc, K2H, W_att, K2H, keysp, HH,
                                                   K2H, nullptr, nullptr);
        // gates_y = emb_seq @ W_ih[:, :256]^T + b_ih + b_hh : M=4096 N=2048 K=256
        kt_gemm_nt<<<dim3(G4/64, 4096/64), 256>>>(embp, EE, W_ih, 768, gyp, G4,
                                                  EE, b_ih, b_hh);
    }

    // persistent weight-stationary scan: one launch for all 128 steps
    kt_scan<<<NBLK, 256, SMEM_SCAN>>>(enc, mask, W_ih, W_hh, W_dec, b_dec);

    // vocab projection + fused sum-exp + log-softmax subtract
    kt_prepack_w<<<(4000*32*32 + 255)/256, 256>>>(W_vocab);
    kt_prepack_o<<<(256*32*32 + 255)/256, 256>>>();
    kt_vocab_gemm<<<dim3(NTILE, (BB*TT)/128), 256>>>(out, b_vocab);
    kt_lsfinal<<<BB*TT, 256>>>(out);
}

// round 6
// speedup vs baseline: 1.7186x; 1.1196x over previous
#include <cuda_runtime.h>
#include <cuda_bf16.h>
#include <cstdint>
#include <math.h>

#define BB 32
#define TT 128
#define SSRC 128
#define HH 512
#define EE 256
#define VV 32000
#define K2H 1024
#define G4 2048
#define NBLK 128
#define NTILE 250

typedef unsigned long long ull;

// ---------------- device scratch ----------------
static __device__ float g_keys[BB*SSRC*HH];
static __device__ float g_encdec[BB*SSRC*HH];        // [b][s][j]
static __device__ float g_gatesy[TT*BB*G4];
static __device__ float g_embseq[TT*BB*EE];
static __device__ float g_x[BB*K2H];                 // [o(512), h(512)]
static __device__ float g_c[2][BB*HH];
static __device__ float g_gates[BB*G4];
static __device__ float g_pctx[4*BB*HH];             // [q][b][j]
static __device__ float2 g_bstats[4*BB];             // (m, Z)
static __device__ float g_oseq[BB*TT*HH];
static __device__ uint4 g_oswz[256*32*32];
static __device__ uint2 g_wswz[4000*32*32];
static __device__ float g_partial[(size_t)BB*TT*NTILE];
static __device__ unsigned g_flags[NBLK];

static __device__ __forceinline__ uint32_t pk_bf2(float lo, float hi) {
    __nv_bfloat16 l = __float2bfloat16(lo), h = __float2bfloat16(hi);
    return (uint32_t)__bfloat16_as_ushort(l) | ((uint32_t)__bfloat16_as_ushort(h) << 16);
}
static __device__ __forceinline__ void ffma2(ull& acc, ull a, ull b) {
    asm volatile("fma.rn.f32x2 %0, %1, %2, %0;" : "+l"(acc) : "l"(a), "l"(b));
}
static __device__ __forceinline__ float2 u2f(ull v) {
    float2 f; asm("mov.b64 {%0, %1}, %2;" : "=f"(f.x), "=f"(f.y) : "l"(v)); return f;
}

// flag-array grid barrier
static __device__ __forceinline__ void gbar(unsigned tgt) {
    __syncthreads();
    if (threadIdx.x == 0)
        asm volatile("st.release.gpu.global.u32 [%0], %1;"
                     :: "l"(&g_flags[blockIdx.x]), "r"(tgt) : "memory");
    if (threadIdx.x < NBLK) {
        unsigned v;
        do {
            asm volatile("ld.acquire.gpu.global.u32 %0, [%1];"
                         : "=r"(v) : "l"(&g_flags[threadIdx.x]) : "memory");
        } while (v < tgt);
    }
    __syncthreads();
}

// ---------------- prep kernels ----------------
__global__ void kt_init(const float* __restrict__ h0, const float* __restrict__ c0) {
    int i = blockIdx.x * 256 + threadIdx.x;
    if (i < NBLK) g_flags[i] = 0;
    if (i < BB * HH) {
        int b = i / HH, j = i % HH;
        g_c[0][i] = c0[i];
        g_x[b * K2H + j] = 0.f;
        g_x[b * K2H + HH + j] = h0[i];
    }
}

__global__ void kt_gather(const float* __restrict__ emb, const int* __restrict__ ids) {
    int i = blockIdx.x * 256 + threadIdx.x;
    if (i >= TT * BB * EE) return;
    int e = i % EE; int tb = i / EE; int b = tb % BB; int t = tb / BB;
    int tok = ids[b * (TT + 1) + t];
    g_embseq[(t * BB + b) * EE + e] = emb[tok * EE + e];
}

__global__ void kt_prepack_w(const float* __restrict__ Wv) {
    int i = blockIdx.x * 256 + threadIdx.x;
    if (i >= 4000 * 32 * 32) return;
    int lane = i & 31; int tile = i >> 5;
    int kt = tile & 31; int nrow = tile >> 5;
    int gid = lane >> 2, tg = lane & 3;
    const float* p = Wv + (size_t)(nrow * 8 + gid) * HH + kt * 16 + tg * 2;
    uint2 v; v.x = pk_bf2(p[0], p[1]); v.y = pk_bf2(p[8], p[9]);
    g_wswz[i] = v;
}

__global__ void kt_prepack_o() {
    int i = blockIdx.x * 256 + threadIdx.x;
    if (i >= 256 * 32 * 32) return;
    int lane = i & 31; int tile = i >> 5;
    int kt = tile & 31; int mrow = tile >> 5;
    int gid = lane >> 2, tg = lane & 3;
    const float* p = g_oseq + (size_t)(mrow * 16 + gid) * HH + kt * 16 + tg * 2;
    uint4 v;
    v.x = pk_bf2(p[0], p[1]);
    v.y = pk_bf2(p[8 * HH], p[8 * HH + 1]);
    v.z = pk_bf2(p[8], p[9]);
    v.w = pk_bf2(p[8 * HH + 8], p[8 * HH + 9]);
    g_oswz[i] = v;
}

// ---------------- fp32 GEMM (64x64 tile, float4 staging) ----------------
__global__ void __launch_bounds__(256) kt_gemm_nt(
    const float* __restrict__ A, int lda, const float* __restrict__ Bm, int ldb,
    float* __restrict__ C, int ldc, int K,
    const float* __restrict__ bias0, const float* __restrict__ bias1)
{
    __shared__ float As[16][68];
    __shared__ float Bs[16][68];
    int tid = threadIdx.x;
    int tx = tid & 15, ty = tid >> 4;
    int m0 = blockIdx.y * 64, n0 = blockIdx.x * 64;
    int lr = tid >> 2, lq = tid & 3;
    float acc[4][4];
#pragma unroll
    for (int i = 0; i < 4; i++)
#pragma unroll
        for (int j = 0; j < 4; j++) acc[i][j] = 0.f;

    for (int k0 = 0; k0 < K; k0 += 16) {
        float4 a4 = *(const float4*)(A + (size_t)(m0 + lr) * lda + k0 + lq * 4);
        float4 b4 = *(const float4*)(Bm + (size_t)(n0 + lr) * ldb + k0 + lq * 4);
        As[lq*4+0][lr] = a4.x; As[lq*4+1][lr] = a4.y; As[lq*4+2][lr] = a4.z; As[lq*4+3][lr] = a4.w;
        Bs[lq*4+0][lr] = b4.x; Bs[lq*4+1][lr] = b4.y; Bs[lq*4+2][lr] = b4.z; Bs[lq*4+3][lr] = b4.w;
        __syncthreads();
#pragma unroll
        for (int kk = 0; kk < 16; kk++) {
            float4 av = *(const float4*)&As[kk][ty * 4];
            float4 bv = *(const float4*)&Bs[kk][tx * 4];
            acc[0][0] += av.x*bv.x; acc[0][1] += av.x*bv.y; acc[0][2] += av.x*bv.z; acc[0][3] += av.x*bv.w;
            acc[1][0] += av.y*bv.x; acc[1][1] += av.y*bv.y; acc[1][2] += av.y*bv.z; acc[1][3] += av.y*bv.w;
            acc[2][0] += av.z*bv.x; acc[2][1] += av.z*bv.y; acc[2][2] += av.z*bv.z; acc[2][3] += av.z*bv.w;
            acc[3][0] += av.w*bv.x; acc[3][1] += av.w*bv.y; acc[3][2] += av.w*bv.z; acc[3][3] += av.w*bv.w;
        }
        __syncthreads();
    }
    float bb[4];
#pragma unroll
    for (int j = 0; j < 4; j++) {
        int n = n0 + tx * 4 + j;
        bb[j] = (bias0 ? bias0[n] : 0.f) + (bias1 ? bias1[n] : 0.f);
    }
#pragma unroll
    for (int i = 0; i < 4; i++) {
        float4 o4 = { acc[i][0]+bb[0], acc[i][1]+bb[1], acc[i][2]+bb[2], acc[i][3]+bb[3] };
        *(float4*)(C + (size_t)(m0 + ty * 4 + i) * ldc + n0 + tx * 4) = o4;
    }
}

// =================== persistent scan ===================
// smem layout (bytes):
//   wg   float2[16*513]  @ 0       (65664)
//   wdh  float[4*520]    @ 65664   (8320)
//   stage float[32*XSTR] @ 73984   (132352)   XSTR=1034 (x rows, 1024 data + pad)
//   red  float[8*520]    @ 206336  (16640)
//   mbias float[32]      @ 222976  (128)
#define XSTR 1034
#define CSTR 520
#define SM_WDH 65664
#define SM_ST  73984
#define SM_RED 206336
#define SM_MB  222976
#define SMEM_SCAN 223104

__global__ void __launch_bounds__(256) kt_scan(
    const int* __restrict__ mask,
    const float* __restrict__ Wih, const float* __restrict__ Whh,
    const float* __restrict__ Wdec, const float* __restrict__ bdec)
{
    extern __shared__ char smem[];
    float2* wg    = (float2*)smem;                 // [16][513]
    float*  wdh   = (float*)(smem + SM_WDH);       // [4][520]
    float*  stage = (float*)(smem + SM_ST);        // [32][XSTR]
    float*  red   = (float*)(smem + SM_RED);       // [8][520]
    float*  mbias = (float*)(smem + SM_MB);        // [32]

    int c = blockIdx.x, tid = threadIdx.x;
    int bB = c & 31, qB = c >> 5;

    // stationary gate weights: row g -> [Wih[g][256:768] | Whh[g][:]] as float2 pairs
    for (int idx = tid; idx < 16 * 512; idx += 256) {
        int gg = idx >> 9, kp = idx & 511;
        int g = c * 16 + gg; int k = kp * 2;
        float a, b2;
        if (k < 512) { a = Wih[g * 768 + 256 + k]; b2 = Wih[g * 768 + 257 + k]; }
        else         { a = Whh[g * 512 + k - 512]; b2 = Whh[g * 512 + k - 511]; }
        wg[gg * 513 + kp] = make_float2(a, b2);
    }
    for (int idx = tid; idx < 4 * 512; idx += 256) {
        int jl = idx >> 9, k = idx & 511;
        wdh[jl * CSTR + k] = Wdec[(size_t)(c * 4 + jl) * 1536 + 1024 + k];
    }
    if (tid < 32)
        mbias[tid] = (mask[bB * SSRC + qB * 32 + tid] > 0) ? 0.f : -1e9f;

    unsigned tgt = 0;
    __syncthreads();

    int ks = tid >> 5, gt = (tid >> 3) & 3, bt = tid & 7;   // phase A roles

    for (int t = 0; t < TT; t++) {
        int par = t & 1;
        // ======== phase A: gates_rec = W . x ========
        {
            const float2* gx2 = (const float2*)g_x;
            for (int idx = tid; idx < 32 * 512; idx += 256) {
                int b = idx >> 9, kp = idx & 511;
                *(float2*)(stage + b * XSTR + kp * 2) = gx2[b * 512 + kp];
            }
            __syncthreads();

            const ull* w0 = (const ull*)(wg + (gt*4+0)*513) + ks*64;
            const ull* w1 = (const ull*)(wg + (gt*4+1)*513) + ks*64;
            const ull* w2 = (const ull*)(wg + (gt*4+2)*513) + ks*64;
            const ull* w3 = (const ull*)(wg + (gt*4+3)*513) + ks*64;
            const ull* x0 = (const ull*)(stage + (bt*4+0)*XSTR) + ks*64;
            const ull* x1 = (const ull*)(stage + (bt*4+1)*XSTR) + ks*64;
            const ull* x2 = (const ull*)(stage + (bt*4+2)*XSTR) + ks*64;
            const ull* x3 = (const ull*)(stage + (bt*4+3)*XSTR) + ks*64;
            ull a00=0,a01=0,a02=0,a03=0, a10=0,a11=0,a12=0,a13=0;
            ull a20=0,a21=0,a22=0,a23=0, a30=0,a31=0,a32=0,a33=0;
#pragma unroll 4
            for (int kp = 0; kp < 64; kp++) {
                ull wa=w0[kp], wb=w1[kp], wc=w2[kp], wd=w3[kp];
                ull xa=x0[kp], xb=x1[kp], xc=x2[kp], xd=x3[kp];
                ffma2(a00,wa,xa); ffma2(a01,wa,xb); ffma2(a02,wa,xc); ffma2(a03,wa,xd);
                ffma2(a10,wb,xa); ffma2(a11,wb,xb); ffma2(a12,wb,xc); ffma2(a13,wb,xd);
                ffma2(a20,wc,xa); ffma2(a21,wc,xb); ffma2(a22,wc,xc); ffma2(a23,wc,xd);
                ffma2(a30,wd,xa); ffma2(a31,wd,xb); ffma2(a32,wd,xc); ffma2(a33,wd,xd);
            }
            __syncthreads();
#define RSUM(v) ({ float2 f_ = u2f(v); f_.x + f_.y; })
            {
                float4 r0 = { RSUM(a00), RSUM(a01), RSUM(a02), RSUM(a03) };
                float4 r1 = { RSUM(a10), RSUM(a11), RSUM(a12), RSUM(a13) };
                float4 r2 = { RSUM(a20), RSUM(a21), RSUM(a22), RSUM(a23) };
                float4 r3 = { RSUM(a30), RSUM(a31), RSUM(a32), RSUM(a33) };
                *(float4*)(red + ks*520 + (gt*4+0)*32 + bt*4) = r0;
                *(float4*)(red + ks*520 + (gt*4+1)*32 + bt*4) = r1;
                *(float4*)(red + ks*520 + (gt*4+2)*32 + bt*4) = r2;
                *(float4*)(red + ks*520 + (gt*4+3)*32 + bt*4) = r3;
            }
#undef RSUM
            __syncthreads();
            for (int cc = tid; cc < 512; cc += 256) {
                float s = 0.f;
#pragma unroll
                for (int q = 0; q < 8; q++) s += red[q*520 + cc];
                int g = cc >> 5, b = cc & 31;
                g_gates[b * G4 + c * 16 + g] = s;
            }
        }
        gbar(++tgt);

        // ======== phase B: cell + scores + split-softmax + partial ctx ========
        {
            float* hs = stage;            // 512
            float* sc = red;              // 32
            float* es = red + 64;         // 32

            const float* gy = g_gatesy + (size_t)(t * BB + bB) * G4;
            const float* gr = g_gates + bB * G4;
#pragma unroll
            for (int jj = 0; jj < 2; jj++) {
                int j = tid + jj * 256;
                float vi = gy[j]        + gr[j];
                float vf = gy[HH+j]     + gr[HH+j];
                float vg = gy[2*HH+j]   + gr[2*HH+j];
                float vo = gy[3*HH+j]   + gr[3*HH+j];
                float cc = g_c[par][bB * HH + j];
                float ig = 1.f / (1.f + __expf(-vi));
                float fg = 1.f / (1.f + __expf(-vf));
                float gg = tanhf(vg);
                float og = 1.f / (1.f + __expf(-vo));
                float cn = fg * cc + ig * gg;
                float hn = og * tanhf(cn);
                hs[j] = hn;
                if (qB == 0) {
                    g_c[par ^ 1][bB * HH + j] = cn;
                    g_x[bB * K2H + HH + j] = hn;
                }
            }
            __syncthreads();

            int w = tid >> 5, lane = tid & 31;
            float4 hreg[4];
#pragma unroll
            for (int p = 0; p < 4; p++)
                hreg[p] = *(const float4*)(hs + (lane + p * 32) * 4);
#pragma unroll
            for (int si = 0; si < 4; si++) {
                int sl = w * 4 + si;
                const float4* kp = (const float4*)(g_keys +
                    ((size_t)bB * SSRC + qB * 32 + sl) * HH);
                float acc = 0.f;
#pragma unroll
                for (int p = 0; p < 4; p++) {
                    float4 kv = kp[lane + p * 32];
                    acc += hreg[p].x*kv.x + hreg[p].y*kv.y + hreg[p].z*kv.z + hreg[p].w*kv.w;
                }
#pragma unroll
                for (int off = 16; off; off >>= 1)
                    acc += __shfl_down_sync(0xffffffffu, acc, off);
                if (lane == 0) sc[sl] = acc + mbias[sl];
            }
            __syncthreads();

            if (tid < 32) {
                float v = sc[tid];
                float m = v;
#pragma unroll
                for (int off = 16; off; off >>= 1)
                    m = fmaxf(m, __shfl_xor_sync(0xffffffffu, m, off));
                float e = __expf(v - m);
                es[tid] = e;
                float Z = e;
#pragma unroll
                for (int off = 16; off; off >>= 1)
                    Z += __shfl_xor_sync(0xffffffffu, Z, off);
                if (tid == 0) g_bstats[qB * 32 + bB] = make_float2(m, Z);
            }
            __syncthreads();

            {
                int j = tid;
                const float* ed = g_encdec + ((size_t)bB * SSRC + qB * 32) * HH;
                float p0 = 0.f, p1 = 0.f;
#pragma unroll 8
                for (int s = 0; s < 32; s++) {
                    float e = es[s];
                    p0 += e * ed[(size_t)s * HH + j];
                    p1 += e * ed[(size_t)s * HH + j + 256];
                }
                g_pctx[(qB * 32 + bB) * HH + j] = p0;
                g_pctx[(qB * 32 + bB) * HH + j + 256] = p1;
            }
        }
        gbar(++tgt);

        // ======== phase C: combine + Wdh.h + tanh ========
        {
            for (int idx = tid; idx < 32 * 128; idx += 256) {
                int b = idx >> 7, k4 = idx & 127;
                *(float4*)(stage + b * CSTR + k4 * 4) =
                    *(const float4*)(g_x + b * K2H + HH + k4 * 4);
            }
            __syncthreads();
            int kk = tid >> 7, cell = tid & 127, bC = cell >> 2, jl = cell & 3;
            {
                const float4* wp = (const float4*)(wdh + jl * CSTR + kk * 256);
                const float4* hp = (const float4*)(stage + bC * CSTR + kk * 256);
                float acc = 0.f;
#pragma unroll 8
                for (int k4 = 0; k4 < 64; k4++) {
                    float4 wv = wp[k4], hv = hp[k4];
                    acc += wv.x*hv.x + wv.y*hv.y + wv.z*hv.z + wv.w*hv.w;
                }
                red[kk * 128 + cell] = acc;
            }
            __syncthreads();
            if (tid < 128) {
                float wsum = red[tid] + red[128 + tid];
                int b = bC, j = c * 4 + jl;
                float2 st0 = g_bstats[b], st1 = g_bstats[32 + b];
                float2 st2 = g_bstats[64 + b], st3 = g_bstats[96 + b];
                float M = fmaxf(fmaxf(st0.x, st1.x), fmaxf(st2.x, st3.x));
                float w0 = __expf(st0.x - M), w1 = __expf(st1.x - M);
                float w2 = __expf(st2.x - M), w3 = __expf(st3.x - M);
                float den = st0.y*w0 + st1.y*w1 + st2.y*w2 + st3.y*w3;
                float num = w0 * g_pctx[(0*32+b)*HH + j] + w1 * g_pctx[(1*32+b)*HH + j]
                          + w2 * g_pctx[(2*32+b)*HH + j] + w3 * g_pctx[(3*32+b)*HH + j];
                float o = tanhf(num / den + wsum + bdec[j]);
                g_x[b * K2H + j] = o;
                g_oseq[((size_t)b * TT + t) * HH + j] = o;
            }
        }
        gbar(++tgt);
    }
}

// ---------------- vocab GEMM + fused sum-exp partials ----------------
#define MMA16816(d0,d1,d2,d3,A0,A1,A2,A3,B0,B1) \
    asm volatile("mma.sync.aligned.m16n8k16.row.col.f32.bf16.bf16.f32 " \
        "{%0,%1,%2,%3}, {%4,%5,%6,%7}, {%8,%9}, {%0,%1,%2,%3};" \
        : "+f"(d0), "+f"(d1), "+f"(d2), "+f"(d3) \
        : "r"(A0), "r"(A1), "r"(A2), "r"(A3), "r"(B0), "r"(B1))

__global__ void __launch_bounds__(256) kt_vocab_gemm(
    float* __restrict__ out, const float* __restrict__ bvocab)
{
    int nb = blockIdx.x, mb = blockIdx.y;
    int wid = threadIdx.x >> 5, lane = threadIdx.x & 31;
    int wm = wid >> 2, wn = wid & 3;
    int gid = lane >> 2, tg = lane & 3;

    __shared__ float rowsum[128][4];
    if (threadIdx.x < 128) {
#pragma unroll
        for (int w = 0; w < 4; w++) rowsum[threadIdx.x][w] = 0.f;
    }
    __syncthreads();

    float acc[4][4][4];
#pragma unroll
    for (int i = 0; i < 4; i++)
#pragma unroll
        for (int j = 0; j < 4; j++)
#pragma unroll
            for (int r = 0; r < 4; r++) acc[i][j][r] = 0.f;

    int mrow0 = mb * 8 + wm * 4;
    int nrow0 = nb * 16 + wn * 4;

#pragma unroll 2
    for (int kt = 0; kt < 32; kt++) {
        uint4 af[4];
        uint2 bf[4];
#pragma unroll
        for (int mt = 0; mt < 4; mt++)
            af[mt] = g_oswz[(((mrow0 + mt) * 32 + kt) << 5) + lane];
#pragma unroll
        for (int nt = 0; nt < 4; nt++)
            bf[nt] = g_wswz[(((size_t)(nrow0 + nt) * 32 + kt) << 5) + lane];
#pragma unroll
        for (int mt = 0; mt < 4; mt++)
#pragma unroll
            for (int nt = 0; nt < 4; nt++)
                MMA16816(acc[mt][nt][0], acc[mt][nt][1], acc[mt][nt][2], acc[mt][nt][3],
                         af[mt].x, af[mt].y, af[mt].z, af[mt].w, bf[nt].x, bf[nt].y);
    }

    int m_warp = mb * 128 + wm * 64;
    int n_warp = nb * 128 + wn * 32;
#pragma unroll
    for (int mt = 0; mt < 4; mt++) {
        float s0 = 0.f, s1 = 0.f;
#pragma unroll
        for (int nt = 0; nt < 4; nt++) {
            int r = m_warp + mt * 16 + gid;
            int ci = n_warp + nt * 8 + tg * 2;
            float bv0 = bvocab[ci], bv1 = bvocab[ci + 1];
            float v00 = acc[mt][nt][0] + bv0, v01 = acc[mt][nt][1] + bv1;
            float v10 = acc[mt][nt][2] + bv0, v11 = acc[mt][nt][3] + bv1;
            float2 w0 = { v00, v01 }, w1 = { v10, v11 };
            *reinterpret_cast<float2*>(out + (size_t)r * VV + ci) = w0;
            *reinterpret_cast<float2*>(out + (size_t)(r + 8) * VV + ci) = w1;
            s0 += __expf(v00) + __expf(v01);
            s1 += __expf(v10) + __expf(v11);
        }
        s0 += __shfl_xor_sync(0xffffffffu, s0, 1);
        s0 += __shfl_xor_sync(0xffffffffu, s0, 2);
        s1 += __shfl_xor_sync(0xffffffffu, s1, 1);
        s1 += __shfl_xor_sync(0xffffffffu, s1, 2);
        if (tg == 0) {
            rowsum[wm * 64 + mt * 16 + gid][wn] = s0;
            rowsum[wm * 64 + mt * 16 + gid + 8][wn] = s1;
        }
    }
    __syncthreads();
    if (threadIdx.x < 128) {
        float p = rowsum[threadIdx.x][0] + rowsum[threadIdx.x][1]
                + rowsum[threadIdx.x][2] + rowsum[threadIdx.x][3];
        g_partial[(size_t)(mb * 128 + threadIdx.x) * NTILE + nb] = p;
    }
}

__global__ void __launch_bounds__(256) kt_lsfinal(float* __restrict__ out) {
    int row = blockIdx.x, tid = threadIdx.x;
    __shared__ float red[256];
    __shared__ float lse_s;
    float s = 0.f;
    for (int i = tid; i < NTILE; i += 256) s += g_partial[(size_t)row * NTILE + i];
    red[tid] = s;
    __syncthreads();
#pragma unroll
    for (int off = 128; off; off >>= 1) {
        if (tid < off) red[tid] += red[tid + off];
        __syncthreads();
    }
    if (tid == 0) lse_s = logf(red[0]);
    __syncthreads();
    float lse = lse_s;
    float* p = out + (size_t)row * VV;
    for (int i = tid * 4; i < VV; i += 256 * 4) {
        float4 v = *reinterpret_cast<float4*>(p + i);
        v.x -= lse; v.y -= lse; v.z -= lse; v.w -= lse;
        *reinterpret_cast<float4*>(p + i) = v;
    }
}

// ---------------- launch ----------------
extern "C" void kernel_launch(void* const* d_in, const int* in_sizes, int n_in,
                              void* d_out, int out_size)
{
    const float* enc     = (const float*)d_in[0];
    const int*   mask    = (const int*)  d_in[1];
    const int*   ids     = (const int*)  d_in[2];
    const float* h0      = (const float*)d_in[3];
    const float* c0      = (const float*)d_in[4];
    const float* emb     = (const float*)d_in[5];
    const float* W_ih    = (const float*)d_in[6];
    const float* b_ih    = (const float*)d_in[7];
    const float* W_hh    = (const float*)d_in[8];
    const float* b_hh    = (const float*)d_in[9];
    const float* W_att   = (const float*)d_in[10];
    const float* W_dec   = (const float*)d_in[11];
    const float* b_dec   = (const float*)d_in[12];
    const float* W_vocab = (const float*)d_in[13];
    const float* b_vocab = (const float*)d_in[14];
    float* out = (float*)d_out;

    cudaFuncSetAttribute(kt_scan, cudaFuncAttributeMaxDynamicSharedMemorySize, SMEM_SCAN);

    kt_init<<<(BB*HH + 255)/256, 256>>>(h0, c0);
    kt_gather<<<(TT*BB*EE + 255)/256, 256>>>(emb, ids);

    {
        float* keysp; cudaGetSymbolAddress((void**)&keysp, g_keys);
        float* edp;   cudaGetSymbolAddress((void**)&edp, g_encdec);
        float* embp;  cudaGetSymbolAddress((void**)&embp, g_embseq);
        float* gyp;   cudaGetSymbolAddress((void**)&gyp, g_gatesy);
        // keys = enc @ W_att^T : M=4096 N=512 K=1024
        kt_gemm_nt<<<dim3(8, 64), 256>>>(enc, K2H, W_att, K2H, keysp, HH, K2H, nullptr, nullptr);
        // encdec = enc @ W_dec[:, :1024]^T : M=4096 N=512 K=1024 (ldb=1536)
        kt_gemm_nt<<<dim3(8, 64), 256>>>(enc, K2H, W_dec, 1536, edp, HH, K2H, nullptr, nullptr);
        // gates_y = emb_seq @ W_ih[:, :256]^T + b_ih + b_hh : M=4096 N=2048 K=256
        kt_gemm_nt<<<dim3(32, 64), 256>>>(embp, EE, W_ih, 768, gyp, G4, EE, b_ih, b_hh);
    }

    kt_scan<<<NBLK, 256, SMEM_SCAN>>>(mask, W_ih, W_hh, W_dec, b_dec);

    kt_prepack_w<<<(4000*32*32 + 255)/256, 256>>>(W_vocab);
    kt_prepack_o<<<(256*32*32 + 255)/256, 256>>>();
    kt_vocab_gemm<<<dim3(NTILE, (BB*TT)/128), 256>>>(out, b_vocab);
    kt_lsfinal<<<BB*TT, 256>>>(out);
}

// round 7
// speedup vs baseline: 1.7361x; 1.0102x over previous
#include <cuda_runtime.h>
#include <cuda_bf16.h>
#include <cstdint>
#include <math.h>

#define BB 32
#define TT 128
#define SSRC 128
#define HH 512
#define EE 256
#define VV 32000
#define K2H 1024
#define G4 2048
#define NBLK 128
#define NTILE 250

typedef unsigned long long ull;

// ---------------- device scratch ----------------
static __device__ float g_keys[BB*SSRC*HH];
static __device__ float g_encdec[BB*SSRC*HH];        // [b][s][j]
static __device__ float g_gatesy[TT*BB*G4];
static __device__ float g_embseq[TT*BB*EE];
static __device__ float g_x[BB*K2H];                 // [o(512), h(512)]
static __device__ float g_c[2][BB*HH];
static __device__ float g_gates[BB*G4];
static __device__ float g_pctx[4*BB*HH];             // [q][b][j]
static __device__ float2 g_bstats[4*BB];             // (m, Z)
static __device__ float g_oseq[BB*TT*HH];
static __device__ uint4 g_oswz[256*32*32];
static __device__ uint2 g_wswz[4000*32*32];
static __device__ float g_partial[(size_t)BB*TT*NTILE];
static __device__ unsigned g_flags[NBLK];

static __device__ __forceinline__ uint32_t pk_bf2(float lo, float hi) {
    __nv_bfloat16 l = __float2bfloat16(lo), h = __float2bfloat16(hi);
    return (uint32_t)__bfloat16_as_ushort(l) | ((uint32_t)__bfloat16_as_ushort(h) << 16);
}
static __device__ __forceinline__ void ffma2(ull& acc, ull a, ull b) {
    asm volatile("fma.rn.f32x2 %0, %1, %2, %0;" : "+l"(acc) : "l"(a), "l"(b));
}
static __device__ __forceinline__ float2 u2f(ull v) {
    float2 f; asm("mov.b64 {%0, %1}, %2;" : "=f"(f.x), "=f"(f.y) : "l"(v)); return f;
}

// flag-array grid barrier
static __device__ __forceinline__ void gbar(unsigned tgt) {
    __syncthreads();
    if (threadIdx.x == 0)
        asm volatile("st.release.gpu.global.u32 [%0], %1;"
                     :: "l"(&g_flags[blockIdx.x]), "r"(tgt) : "memory");
    if (threadIdx.x < NBLK) {
        unsigned v;
        do {
            asm volatile("ld.acquire.gpu.global.u32 %0, [%1];"
                         : "=r"(v) : "l"(&g_flags[threadIdx.x]) : "memory");
        } while (v < tgt);
    }
    __syncthreads();
}

// ---------------- prep kernels ----------------
__global__ void kt_init(const float* __restrict__ h0, const float* __restrict__ c0) {
    int i = blockIdx.x * 256 + threadIdx.x;
    if (i < NBLK) g_flags[i] = 0;
    if (i < BB * HH) {
        int b = i / HH, j = i % HH;
        g_c[0][i] = c0[i];
        g_x[b * K2H + j] = 0.f;
        g_x[b * K2H + HH + j] = h0[i];
    }
}

__global__ void kt_gather(const float* __restrict__ emb, const int* __restrict__ ids) {
    int i = blockIdx.x * 256 + threadIdx.x;
    if (i >= TT * BB * EE) return;
    int e = i % EE; int tb = i / EE; int b = tb % BB; int t = tb / BB;
    int tok = ids[b * (TT + 1) + t];
    g_embseq[(t * BB + b) * EE + e] = emb[tok * EE + e];
}

__global__ void kt_prepack_w(const float* __restrict__ Wv) {
    int i = blockIdx.x * 256 + threadIdx.x;
    if (i >= 4000 * 32 * 32) return;
    int lane = i & 31; int tile = i >> 5;
    int kt = tile & 31; int nrow = tile >> 5;
    int gid = lane >> 2, tg = lane & 3;
    const float* p = Wv + (size_t)(nrow * 8 + gid) * HH + kt * 16 + tg * 2;
    uint2 v; v.x = pk_bf2(p[0], p[1]); v.y = pk_bf2(p[8], p[9]);
    g_wswz[i] = v;
}

__global__ void kt_prepack_o() {
    int i = blockIdx.x * 256 + threadIdx.x;
    if (i >= 256 * 32 * 32) return;
    int lane = i & 31; int tile = i >> 5;
    int kt = tile & 31; int mrow = tile >> 5;
    int gid = lane >> 2, tg = lane & 3;
    const float* p = g_oseq + (size_t)(mrow * 16 + gid) * HH + kt * 16 + tg * 2;
    uint4 v;
    v.x = pk_bf2(p[0], p[1]);
    v.y = pk_bf2(p[8 * HH], p[8 * HH + 1]);
    v.z = pk_bf2(p[8], p[9]);
    v.w = pk_bf2(p[8 * HH + 8], p[8 * HH + 9]);
    g_oswz[i] = v;
}

// ---------------- fp32 GEMM (64x64 tile, float4 staging) ----------------
__global__ void __launch_bounds__(256) kt_gemm_nt(
    const float* __restrict__ A, int lda, const float* __restrict__ Bm, int ldb,
    float* __restrict__ C, int ldc, int K,
    const float* __restrict__ bias0, const float* __restrict__ bias1)
{
    __shared__ float As[16][68];
    __shared__ float Bs[16][68];
    int tid = threadIdx.x;
    int tx = tid & 15, ty = tid >> 4;
    int m0 = blockIdx.y * 64, n0 = blockIdx.x * 64;
    int lr = tid >> 2, lq = tid & 3;
    float acc[4][4];
#pragma unroll
    for (int i = 0; i < 4; i++)
#pragma unroll
        for (int j = 0; j < 4; j++) acc[i][j] = 0.f;

    for (int k0 = 0; k0 < K; k0 += 16) {
        float4 a4 = *(const float4*)(A + (size_t)(m0 + lr) * lda + k0 + lq * 4);
        float4 b4 = *(const float4*)(Bm + (size_t)(n0 + lr) * ldb + k0 + lq * 4);
        As[lq*4+0][lr] = a4.x; As[lq*4+1][lr] = a4.y; As[lq*4+2][lr] = a4.z; As[lq*4+3][lr] = a4.w;
        Bs[lq*4+0][lr] = b4.x; Bs[lq*4+1][lr] = b4.y; Bs[lq*4+2][lr] = b4.z; Bs[lq*4+3][lr] = b4.w;
        __syncthreads();
#pragma unroll
        for (int kk = 0; kk < 16; kk++) {
            float4 av = *(const float4*)&As[kk][ty * 4];
            float4 bv = *(const float4*)&Bs[kk][tx * 4];
            acc[0][0] += av.x*bv.x; acc[0][1] += av.x*bv.y; acc[0][2] += av.x*bv.z; acc[0][3] += av.x*bv.w;
            acc[1][0] += av.y*bv.x; acc[1][1] += av.y*bv.y; acc[1][2] += av.y*bv.z; acc[1][3] += av.y*bv.w;
            acc[2][0] += av.z*bv.x; acc[2][1] += av.z*bv.y; acc[2][2] += av.z*bv.z; acc[2][3] += av.z*bv.w;
            acc[3][0] += av.w*bv.x; acc[3][1] += av.w*bv.y; acc[3][2] += av.w*bv.z; acc[3][3] += av.w*bv.w;
        }
        __syncthreads();
    }
    float bb[4];
#pragma unroll
    for (int j = 0; j < 4; j++) {
        int n = n0 + tx * 4 + j;
        bb[j] = (bias0 ? bias0[n] : 0.f) + (bias1 ? bias1[n] : 0.f);
    }
#pragma unroll
    for (int i = 0; i < 4; i++) {
        float4 o4 = { acc[i][0]+bb[0], acc[i][1]+bb[1], acc[i][2]+bb[2], acc[i][3]+bb[3] };
        *(float4*)(C + (size_t)(m0 + ty * 4 + i) * ldc + n0 + tx * 4) = o4;
    }
}

// =================== persistent scan ===================
// smem layout (bytes):
//   wg   float2[16*513]  @ 0       (65664)
//   wdh  float[4*520]    @ 65664   (8320)
//   stage float[32*XSTR] @ 73984   (132352)   XSTR=1034 (x rows, 1024 data + pad)
//   red  float[8*520]    @ 206336  (16640)
//   mbias float[32]      @ 222976  (128)
#define XSTR 1034
#define CSTR 520
#define SM_WDH 65664
#define SM_ST  73984
#define SM_RED 206336
#define SM_MB  222976
#define SMEM_SCAN 223104

__global__ void __launch_bounds__(256) kt_scan(
    const int* __restrict__ mask,
    const float* __restrict__ Wih, const float* __restrict__ Whh,
    const float* __restrict__ Wdec, const float* __restrict__ bdec)
{
    extern __shared__ char smem[];
    float2* wg    = (float2*)smem;                 // [16][513]
    float*  wdh   = (float*)(smem + SM_WDH);       // [4][520]
    float*  stage = (float*)(smem + SM_ST);        // [32][XSTR]
    float*  red   = (float*)(smem + SM_RED);       // [8][520]
    float*  mbias = (float*)(smem + SM_MB);        // [32]

    int c = blockIdx.x, tid = threadIdx.x;
    int bB = c & 31, qB = c >> 5;

    // stationary gate weights: row g -> [Wih[g][256:768] | Whh[g][:]] as float2 pairs
    for (int idx = tid; idx < 16 * 512; idx += 256) {
        int gg = idx >> 9, kp = idx & 511;
        int g = c * 16 + gg; int k = kp * 2;
        float a, b2;
        if (k < 512) { a = Wih[g * 768 + 256 + k]; b2 = Wih[g * 768 + 257 + k]; }
        else         { a = Whh[g * 512 + k - 512]; b2 = Whh[g * 512 + k - 511]; }
        wg[gg * 513 + kp] = make_float2(a, b2);
    }
    for (int idx = tid; idx < 4 * 512; idx += 256) {
        int jl = idx >> 9, k = idx & 511;
        wdh[jl * CSTR + k] = Wdec[(size_t)(c * 4 + jl) * 1536 + 1024 + k];
    }
    if (tid < 32)
        mbias[tid] = (mask[bB * SSRC + qB * 32 + tid] > 0) ? 0.f : -1e9f;

    unsigned tgt = 0;
    __syncthreads();

    int ks = tid >> 5, gt = (tid >> 3) & 3, bt = tid & 7;   // phase A roles

    for (int t = 0; t < TT; t++) {
        int par = t & 1;
        // ======== phase A: gates_rec = W . x ========
        {
            const float2* gx2 = (const float2*)g_x;
            for (int idx = tid; idx < 32 * 512; idx += 256) {
                int b = idx >> 9, kp = idx & 511;
                *(float2*)(stage + b * XSTR + kp * 2) = gx2[b * 512 + kp];
            }
            __syncthreads();

            const ull* w0 = (const ull*)(wg + (gt*4+0)*513) + ks*64;
            const ull* w1 = (const ull*)(wg + (gt*4+1)*513) + ks*64;
            const ull* w2 = (const ull*)(wg + (gt*4+2)*513) + ks*64;
            const ull* w3 = (const ull*)(wg + (gt*4+3)*513) + ks*64;
            const ull* x0 = (const ull*)(stage + (bt*4+0)*XSTR) + ks*64;
            const ull* x1 = (const ull*)(stage + (bt*4+1)*XSTR) + ks*64;
            const ull* x2 = (const ull*)(stage + (bt*4+2)*XSTR) + ks*64;
            const ull* x3 = (const ull*)(stage + (bt*4+3)*XSTR) + ks*64;
            ull a00=0,a01=0,a02=0,a03=0, a10=0,a11=0,a12=0,a13=0;
            ull a20=0,a21=0,a22=0,a23=0, a30=0,a31=0,a32=0,a33=0;
#pragma unroll 4
            for (int kp = 0; kp < 64; kp++) {
                ull wa=w0[kp], wb=w1[kp], wc=w2[kp], wd=w3[kp];
                ull xa=x0[kp], xb=x1[kp], xc=x2[kp], xd=x3[kp];
                ffma2(a00,wa,xa); ffma2(a01,wa,xb); ffma2(a02,wa,xc); ffma2(a03,wa,xd);
                ffma2(a10,wb,xa); ffma2(a11,wb,xb); ffma2(a12,wb,xc); ffma2(a13,wb,xd);
                ffma2(a20,wc,xa); ffma2(a21,wc,xb); ffma2(a22,wc,xc); ffma2(a23,wc,xd);
                ffma2(a30,wd,xa); ffma2(a31,wd,xb); ffma2(a32,wd,xc); ffma2(a33,wd,xd);
            }
            __syncthreads();
#define RSUM(v) ({ float2 f_ = u2f(v); f_.x + f_.y; })
            {
                float4 r0 = { RSUM(a00), RSUM(a01), RSUM(a02), RSUM(a03) };
                float4 r1 = { RSUM(a10), RSUM(a11), RSUM(a12), RSUM(a13) };
                float4 r2 = { RSUM(a20), RSUM(a21), RSUM(a22), RSUM(a23) };
                float4 r3 = { RSUM(a30), RSUM(a31), RSUM(a32), RSUM(a33) };
                *(float4*)(red + ks*520 + (gt*4+0)*32 + bt*4) = r0;
                *(float4*)(red + ks*520 + (gt*4+1)*32 + bt*4) = r1;
                *(float4*)(red + ks*520 + (gt*4+2)*32 + bt*4) = r2;
                *(float4*)(red + ks*520 + (gt*4+3)*32 + bt*4) = r3;
            }
#undef RSUM
            __syncthreads();
            for (int cc = tid; cc < 512; cc += 256) {
                float s = 0.f;
#pragma unroll
                for (int q = 0; q < 8; q++) s += red[q*520 + cc];
                int g = cc >> 5, b = cc & 31;
                g_gates[b * G4 + c * 16 + g] = s;
            }
        }
        gbar(++tgt);

        // ======== phase B: cell + scores + split-softmax + partial ctx ========
        {
            float* hs = stage;            // 512
            float* sc = red;              // 32
            float* es = red + 64;         // 32

            const float* gy = g_gatesy + (size_t)(t * BB + bB) * G4;
            const float* gr = g_gates + bB * G4;
#pragma unroll
            for (int jj = 0; jj < 2; jj++) {
                int j = tid + jj * 256;
                float vi = gy[j]        + gr[j];
                float vf = gy[HH+j]     + gr[HH+j];
                float vg = gy[2*HH+j]   + gr[2*HH+j];
                float vo = gy[3*HH+j]   + gr[3*HH+j];
                float cc = g_c[par][bB * HH + j];
                float ig = 1.f / (1.f + __expf(-vi));
                float fg = 1.f / (1.f + __expf(-vf));
                float gg = tanhf(vg);
                float og = 1.f / (1.f + __expf(-vo));
                float cn = fg * cc + ig * gg;
                float hn = og * tanhf(cn);
                hs[j] = hn;
                if (qB == 0) {
                    g_c[par ^ 1][bB * HH + j] = cn;
                    g_x[bB * K2H + HH + j] = hn;
                }
            }
            __syncthreads();

            int w = tid >> 5, lane = tid & 31;
            float4 hreg[4];
#pragma unroll
            for (int p = 0; p < 4; p++)
                hreg[p] = *(const float4*)(hs + (lane + p * 32) * 4);
#pragma unroll
            for (int si = 0; si < 4; si++) {
                int sl = w * 4 + si;
                const float4* kp = (const float4*)(g_keys +
                    ((size_t)bB * SSRC + qB * 32 + sl) * HH);
                float acc = 0.f;
#pragma unroll
                for (int p = 0; p < 4; p++) {
                    float4 kv = kp[lane + p * 32];
                    acc += hreg[p].x*kv.x + hreg[p].y*kv.y + hreg[p].z*kv.z + hreg[p].w*kv.w;
                }
#pragma unroll
                for (int off = 16; off; off >>= 1)
                    acc += __shfl_down_sync(0xffffffffu, acc, off);
                if (lane == 0) sc[sl] = acc + mbias[sl];
            }
            __syncthreads();

            if (tid < 32) {
                float v = sc[tid];
                float m = v;
#pragma unroll
                for (int off = 16; off; off >>= 1)
                    m = fmaxf(m, __shfl_xor_sync(0xffffffffu, m, off));
                float e = __expf(v - m);
                es[tid] = e;
                float Z = e;
#pragma unroll
                for (int off = 16; off; off >>= 1)
                    Z += __shfl_xor_sync(0xffffffffu, Z, off);
                if (tid == 0) g_bstats[qB * 32 + bB] = make_float2(m, Z);
            }
            __syncthreads();

            {
                int j = tid;
                const float* ed = g_encdec + ((size_t)bB * SSRC + qB * 32) * HH;
                float p0 = 0.f, p1 = 0.f;
#pragma unroll 8
                for (int s = 0; s < 32; s++) {
                    float e = es[s];
                    p0 += e * ed[(size_t)s * HH + j];
                    p1 += e * ed[(size_t)s * HH + j + 256];
                }
                g_pctx[(qB * 32 + bB) * HH + j] = p0;
                g_pctx[(qB * 32 + bB) * HH + j + 256] = p1;
            }
        }
        gbar(++tgt);

        // ======== phase C: combine + Wdh.h + tanh ========
        {
            for (int idx = tid; idx < 32 * 128; idx += 256) {
                int b = idx >> 7, k4 = idx & 127;
                *(float4*)(stage + b * CSTR + k4 * 4) =
                    *(const float4*)(g_x + b * K2H + HH + k4 * 4);
            }
            __syncthreads();
            int kk = tid >> 7, cell = tid & 127, bC = cell >> 2, jl = cell & 3;
            {
                const float4* wp = (const float4*)(wdh + jl * CSTR + kk * 256);
                const float4* hp = (const float4*)(stage + bC * CSTR + kk * 256);
                float acc = 0.f;
#pragma unroll 8
                for (int k4 = 0; k4 < 64; k4++) {
                    float4 wv = wp[k4], hv = hp[k4];
                    acc += wv.x*hv.x + wv.y*hv.y + wv.z*hv.z + wv.w*hv.w;
                }
                red[kk * 128 + cell] = acc;
            }
            __syncthreads();
            if (tid < 128) {
                float wsum = red[tid] + red[128 + tid];
                int b = bC, j = c * 4 + jl;
                float2 st0 = g_bstats[b], st1 = g_bstats[32 + b];
                float2 st2 = g_bstats[64 + b], st3 = g_bstats[96 + b];
                float M = fmaxf(fmaxf(st0.x, st1.x), fmaxf(st2.x, st3.x));
                float w0 = __expf(st0.x - M), w1 = __expf(st1.x - M);
                float w2 = __expf(st2.x - M), w3 = __expf(st3.x - M);
                float den = st0.y*w0 + st1.y*w1 + st2.y*w2 + st3.y*w3;
                float num = w0 * g_pctx[(0*32+b)*HH + j] + w1 * g_pctx[(1*32+b)*HH + j]
                          + w2 * g_pctx[(2*32+b)*HH + j] + w3 * g_pctx[(3*32+b)*HH + j];
                float o = tanhf(num / den + wsum + bdec[j]);
                g_x[b * K2H + j] = o;
                g_oseq[((size_t)b * TT + t) * HH + j] = o;
            }
        }
        gbar(++tgt);
    }
}

// ---------------- vocab GEMM + fused sum-exp partials ----------------
#define MMA16816(d0,d1,d2,d3,A0,A1,A2,A3,B0,B1) \
    asm volatile("mma.sync.aligned.m16n8k16.row.col.f32.bf16.bf16.f32 " \
        "{%0,%1,%2,%3}, {%4,%5,%6,%7}, {%8,%9}, {%0,%1,%2,%3};" \
        : "+f"(d0), "+f"(d1), "+f"(d2), "+f"(d3) \
        : "r"(A0), "r"(A1), "r"(A2), "r"(A3), "r"(B0), "r"(B1))

__global__ void __launch_bounds__(256) kt_vocab_gemm(
    float* __restrict__ out, const float* __restrict__ bvocab)
{
    int nb = blockIdx.x, mb = blockIdx.y;
    int wid = threadIdx.x >> 5, lane = threadIdx.x & 31;
    int wm = wid >> 2, wn = wid & 3;
    int gid = lane >> 2, tg = lane & 3;

    __shared__ float rowsum[128][4];
    if (threadIdx.x < 128) {
#pragma unroll
        for (int w = 0; w < 4; w++) rowsum[threadIdx.x][w] = 0.f;
    }
    __syncthreads();

    float acc[4][4][4];
#pragma unroll
    for (int i = 0; i < 4; i++)
#pragma unroll
        for (int j = 0; j < 4; j++)
#pragma unroll
            for (int r = 0; r < 4; r++) acc[i][j][r] = 0.f;

    int mrow0 = mb * 8 + wm * 4;
    int nrow0 = nb * 16 + wn * 4;

#pragma unroll 2
    for (int kt = 0; kt < 32; kt++) {
        uint4 af[4];
        uint2 bf[4];
#pragma unroll
        for (int mt = 0; mt < 4; mt++)
            af[mt] = g_oswz[(((mrow0 + mt) * 32 + kt) << 5) + lane];
#pragma unroll
        for (int nt = 0; nt < 4; nt++)
            bf[nt] = g_wswz[(((size_t)(nrow0 + nt) * 32 + kt) << 5) + lane];
#pragma unroll
        for (int mt = 0; mt < 4; mt++)
#pragma unroll
            for (int nt = 0; nt < 4; nt++)
                MMA16816(acc[mt][nt][0], acc[mt][nt][1], acc[mt][nt][2], acc[mt][nt][3],
                         af[mt].x, af[mt].y, af[mt].z, af[mt].w, bf[nt].x, bf[nt].y);
    }

    int m_warp = mb * 128 + wm * 64;
    int n_warp = nb * 128 + wn * 32;
#pragma unroll
    for (int mt = 0; mt < 4; mt++) {
        float s0 = 0.f, s1 = 0.f;
#pragma unroll
        for (int nt = 0; nt < 4; nt++) {
            int r = m_warp + mt * 16 + gid;
            int ci = n_warp + nt * 8 + tg * 2;
            float bv0 = bvocab[ci], bv1 = bvocab[ci + 1];
            float v00 = acc[mt][nt][0] + bv0, v01 = acc[mt][nt][1] + bv1;
            float v10 = acc[mt][nt][2] + bv0, v11 = acc[mt][nt][3] + bv1;
            float2 w0 = { v00, v01 }, w1 = { v10, v11 };
            *reinterpret_cast<float2*>(out + (size_t)r * VV + ci) = w0;
            *reinterpret_cast<float2*>(out + (size_t)(r + 8) * VV + ci) = w1;
            s0 += __expf(v00) + __expf(v01);
            s1 += __expf(v10) + __expf(v11);
        }
        s0 += __shfl_xor_sync(0xffffffffu, s0, 1);
        s0 += __shfl_xor_sync(0xffffffffu, s0, 2);
        s1 += __shfl_xor_sync(0xffffffffu, s1, 1);
        s1 += __shfl_xor_sync(0xffffffffu, s1, 2);
        if (tg == 0) {
            rowsum[wm * 64 + mt * 16 + gid][wn] = s0;
            rowsum[wm * 64 + mt * 16 + gid + 8][wn] = s1;
        }
    }
    __syncthreads();
    if (threadIdx.x < 128) {
        float p = rowsum[threadIdx.x][0] + rowsum[threadIdx.x][1]
                + rowsum[threadIdx.x][2] + rowsum[threadIdx.x][3];
        g_partial[(size_t)(mb * 128 + threadIdx.x) * NTILE + nb] = p;
    }
}

__global__ void __launch_bounds__(256) kt_lsfinal(float* __restrict__ out) {
    int row = blockIdx.x, tid = threadIdx.x;
    __shared__ float red[256];
    __shared__ float lse_s;
    float s = 0.f;
    for (int i = tid; i < NTILE; i += 256) s += g_partial[(size_t)row * NTILE + i];
    red[tid] = s;
    __syncthreads();
#pragma unroll
    for (int off = 128; off; off >>= 1) {
        if (tid < off) red[tid] += red[tid + off];
        __syncthreads();
    }
    if (tid == 0) lse_s = logf(red[0]);
    __syncthreads();
    float lse = lse_s;
    float* p = out + (size_t)row * VV;
    for (int i = tid * 4; i < VV; i += 256 * 4) {
        float4 v = *reinterpret_cast<float4*>(p + i);
        v.x -= lse; v.y -= lse; v.z -= lse; v.w -= lse;
        *reinterpret_cast<float4*>(p + i) = v;
    }
}

// ---------------- launch ----------------
extern "C" void kernel_launch(void* const* d_in, const int* in_sizes, int n_in,
                              void* d_out, int out_size)
{
    const float* enc     = (const float*)d_in[0];
    const int*   mask    = (const int*)  d_in[1];
    const int*   ids     = (const int*)  d_in[2];
    const float* h0      = (const float*)d_in[3];
    const float* c0      = (const float*)d_in[4];
    const float* emb     = (const float*)d_in[5];
    const float* W_ih    = (const float*)d_in[6];
    const float* b_ih    = (const float*)d_in[7];
    const float* W_hh    = (const float*)d_in[8];
    const float* b_hh    = (const float*)d_in[9];
    const float* W_att   = (const float*)d_in[10];
    const float* W_dec   = (const float*)d_in[11];
    const float* b_dec   = (const float*)d_in[12];
    const float* W_vocab = (const float*)d_in[13];
    const float* b_vocab = (const float*)d_in[14];
    float* out = (float*)d_out;

    cudaFuncSetAttribute(kt_scan, cudaFuncAttributeMaxDynamicSharedMemorySize, SMEM_SCAN);

    kt_init<<<(BB*HH + 255)/256, 256>>>(h0, c0);
    kt_gather<<<(TT*BB*EE + 255)/256, 256>>>(emb, ids);

    {
        float* keysp; cudaGetSymbolAddress((void**)&keysp, g_keys);
        float* edp;   cudaGetSymbolAddress((void**)&edp, g_encdec);
        float* embp;  cudaGetSymbolAddress((void**)&embp, g_embseq);
        float* gyp;   cudaGetSymbolAddress((void**)&gyp, g_gatesy);
        // keys = enc @ W_att^T : M=4096 N=512 K=1024
        kt_gemm_nt<<<dim3(8, 64), 256>>>(enc, K2H, W_att, K2H, keysp, HH, K2H, nullptr, nullptr);
        // encdec = enc @ W_dec[:, :1024]^T : M=4096 N=512 K=1024 (ldb=1536)
        kt_gemm_nt<<<dim3(8, 64), 256>>>(enc, K2H, W_dec, 1536, edp, HH, K2H, nullptr, nullptr);
        // gates_y = emb_seq @ W_ih[:, :256]^T + b_ih + b_hh : M=4096 N=2048 K=256
        kt_gemm_nt<<<dim3(32, 64), 256>>>(embp, EE, W_ih, 768, gyp, G4, EE, b_ih, b_hh);
    }

    kt_scan<<<NBLK, 256, SMEM_SCAN>>>(mask, W_ih, W_hh, W_dec, b_dec);

    kt_prepack_w<<<(4000*32*32 + 255)/256, 256>>>(W_vocab);
    kt_prepack_o<<<(256*32*32 + 255)/256, 256>>>();
    kt_vocab_gemm<<<dim3(NTILE, (BB*TT)/128), 256>>>(out, b_vocab);
    kt_lsfinal<<<BB*TT, 256>>>(out);
}

// round 8
// speedup vs baseline: 2.4795x; 1.4282x over previous
#include <cuda_runtime.h>
#include <cuda_bf16.h>
#include <cstdint>
#include <math.h>

#define BB 32
#define TT 128
#define SSRC 128
#define HH 512
#define EE 256
#define VV 32000
#define K2H 1024
#define G4 2048
#define NBLK 128
#define NTILE 250
#define FSTR 32    // flag stride in u32 (one 128B line per flag)

typedef unsigned long long ull;

// ---------------- device scratch ----------------
static __device__ float g_keys[BB*SSRC*HH];
static __device__ float g_encdec[BB*SSRC*HH];        // [b][s][j]
static __device__ float g_gatesy[TT*BB*G4];
static __device__ float g_embseq[TT*BB*EE];
static __device__ float g_x[BB*K2H];                 // [o(512), h(512)]
static __device__ float g_c[2][BB*HH];
static __device__ float g_gates[BB*G4];
static __device__ float g_pctx[4*BB*HH];             // [q][b][j]
static __device__ float2 g_bstats[4*BB];             // (m, Z)
static __device__ float g_oseq[BB*TT*HH];
static __device__ uint4 g_oswz[256*32*32];
static __device__ uint2 g_wswz[4000*32*32];
static __device__ float g_partial[(size_t)BB*TT*NTILE];
static __device__ unsigned g_flags[NBLK*FSTR];

static __device__ __forceinline__ uint32_t pk_bf2(float lo, float hi) {
    __nv_bfloat16 l = __float2bfloat16(lo), h = __float2bfloat16(hi);
    return (uint32_t)__bfloat16_as_ushort(l) | ((uint32_t)__bfloat16_as_ushort(h) << 16);
}
static __device__ __forceinline__ void ffma2(ull& acc, ull a, ull b) {
    asm volatile("fma.rn.f32x2 %0, %1, %2, %0;" : "+l"(acc) : "l"(a), "l"(b));
}
static __device__ __forceinline__ float2 u2f(ull v) {
    float2 f; asm("mov.b64 {%0, %1}, %2;" : "=f"(f.x), "=f"(f.y) : "l"(v)); return f;
}

// flag-array grid barrier: one 128B line per CTA flag, relaxed polls + backoff
static __device__ __forceinline__ void gbar(unsigned tgt) {
    __syncthreads();
    if (threadIdx.x == 0)
        asm volatile("st.release.gpu.global.u32 [%0], %1;"
                     :: "l"(&g_flags[blockIdx.x * FSTR]), "r"(tgt) : "memory");
    if (threadIdx.x < NBLK) {
        const unsigned* fp = &g_flags[threadIdx.x * FSTR];
        unsigned v;
        asm volatile("ld.relaxed.gpu.global.u32 %0, [%1];" : "=r"(v) : "l"(fp) : "memory");
        while (v < tgt) {
            __nanosleep(128);
            asm volatile("ld.relaxed.gpu.global.u32 %0, [%1];" : "=r"(v) : "l"(fp) : "memory");
        }
    }
    asm volatile("fence.acq_rel.gpu;" ::: "memory");
    __syncthreads();
}

// ---------------- prep kernels ----------------
__global__ void kt_init(const float* __restrict__ h0, const float* __restrict__ c0) {
    int i = blockIdx.x * 256 + threadIdx.x;
    if (i < NBLK * FSTR) g_flags[i] = 0;
    if (i < BB * HH) {
        int b = i / HH, j = i % HH;
        g_c[0][i] = c0[i];
        g_x[b * K2H + j] = 0.f;
        g_x[b * K2H + HH + j] = h0[i];
    }
}

__global__ void kt_gather(const float* __restrict__ emb, const int* __restrict__ ids) {
    int i = blockIdx.x * 256 + threadIdx.x;
    if (i >= TT * BB * EE) return;
    int e = i % EE; int tb = i / EE; int b = tb % BB; int t = tb / BB;
    int tok = ids[b * (TT + 1) + t];
    g_embseq[(t * BB + b) * EE + e] = emb[tok * EE + e];
}

__global__ void kt_prepack_w(const float* __restrict__ Wv) {
    int i = blockIdx.x * 256 + threadIdx.x;
    if (i >= 4000 * 32 * 32) return;
    int lane = i & 31; int tile = i >> 5;
    int kt = tile & 31; int nrow = tile >> 5;
    int gid = lane >> 2, tg = lane & 3;
    const float* p = Wv + (size_t)(nrow * 8 + gid) * HH + kt * 16 + tg * 2;
    uint2 v; v.x = pk_bf2(p[0], p[1]); v.y = pk_bf2(p[8], p[9]);
    g_wswz[i] = v;
}

__global__ void kt_prepack_o() {
    int i = blockIdx.x * 256 + threadIdx.x;
    if (i >= 256 * 32 * 32) return;
    int lane = i & 31; int tile = i >> 5;
    int kt = tile & 31; int mrow = tile >> 5;
    int gid = lane >> 2, tg = lane & 3;
    const float* p = g_oseq + (size_t)(mrow * 16 + gid) * HH + kt * 16 + tg * 2;
    uint4 v;
    v.x = pk_bf2(p[0], p[1]);
    v.y = pk_bf2(p[8 * HH], p[8 * HH + 1]);
    v.z = pk_bf2(p[8], p[9]);
    v.w = pk_bf2(p[8 * HH + 8], p[8 * HH + 9]);
    g_oswz[i] = v;
}

// ---------------- fp32 GEMM (64x64 tile, float4 staging) ----------------
__global__ void __launch_bounds__(256) kt_gemm_nt(
    const float* __restrict__ A, int lda, const float* __restrict__ Bm, int ldb,
    float* __restrict__ C, int ldc, int K,
    const float* __restrict__ bias0, const float* __restrict__ bias1)
{
    __shared__ float As[16][68];
    __shared__ float Bs[16][68];
    int tid = threadIdx.x;
    int tx = tid & 15, ty = tid >> 4;
    int m0 = blockIdx.y * 64, n0 = blockIdx.x * 64;
    int lr = tid >> 2, lq = tid & 3;
    float acc[4][4];
#pragma unroll
    for (int i = 0; i < 4; i++)
#pragma unroll
        for (int j = 0; j < 4; j++) acc[i][j] = 0.f;

    for (int k0 = 0; k0 < K; k0 += 16) {
        float4 a4 = *(const float4*)(A + (size_t)(m0 + lr) * lda + k0 + lq * 4);
        float4 b4 = *(const float4*)(Bm + (size_t)(n0 + lr) * ldb + k0 + lq * 4);
        As[lq*4+0][lr] = a4.x; As[lq*4+1][lr] = a4.y; As[lq*4+2][lr] = a4.z; As[lq*4+3][lr] = a4.w;
        Bs[lq*4+0][lr] = b4.x; Bs[lq*4+1][lr] = b4.y; Bs[lq*4+2][lr] = b4.z; Bs[lq*4+3][lr] = b4.w;
        __syncthreads();
#pragma unroll
        for (int kk = 0; kk < 16; kk++) {
            float4 av = *(const float4*)&As[kk][ty * 4];
            float4 bv = *(const float4*)&Bs[kk][tx * 4];
            acc[0][0] += av.x*bv.x; acc[0][1] += av.x*bv.y; acc[0][2] += av.x*bv.z; acc[0][3] += av.x*bv.w;
            acc[1][0] += av.y*bv.x; acc[1][1] += av.y*bv.y; acc[1][2] += av.y*bv.z; acc[1][3] += av.y*bv.w;
            acc[2][0] += av.z*bv.x; acc[2][1] += av.z*bv.y; acc[2][2] += av.z*bv.z; acc[2][3] += av.z*bv.w;
            acc[3][0] += av.w*bv.x; acc[3][1] += av.w*bv.y; acc[3][2] += av.w*bv.z; acc[3][3] += av.w*bv.w;
        }
        __syncthreads();
    }
    float bb[4];
#pragma unroll
    for (int j = 0; j < 4; j++) {
        int n = n0 + tx * 4 + j;
        bb[j] = (bias0 ? bias0[n] : 0.f) + (bias1 ? bias1[n] : 0.f);
    }
#pragma unroll
    for (int i = 0; i < 4; i++) {
        float4 o4 = { acc[i][0]+bb[0], acc[i][1]+bb[1], acc[i][2]+bb[2], acc[i][3]+bb[3] };
        *(float4*)(C + (size_t)(m0 + ty * 4 + i) * ldc + n0 + tx * 4) = o4;
    }
}

// =================== persistent scan ===================
// smem layout (bytes):
//   wg   float2[16*513]  @ 0       (65664)
//   wdh  float[4*520]    @ 65664   (8320)
//   stage float[32*XSTR] @ 73984   (132352)   XSTR=1034 (x rows, 1024 data + pad)
//   red  float[8*520]    @ 206336  (16640)
//   mbias float[32]      @ 222976  (128)
#define XSTR 1034
#define CSTR 520
#define SM_WDH 65664
#define SM_ST  73984
#define SM_RED 206336
#define SM_MB  222976
#define SMEM_SCAN 223104

__global__ void __launch_bounds__(256) kt_scan(
    const int* __restrict__ mask,
    const float* __restrict__ Wih, const float* __restrict__ Whh,
    const float* __restrict__ Wdec, const float* __restrict__ bdec)
{
    extern __shared__ char smem[];
    float2* wg    = (float2*)smem;                 // [16][513]
    float*  wdh   = (float*)(smem + SM_WDH);       // [4][520]
    float*  stage = (float*)(smem + SM_ST);        // [32][XSTR]
    float*  red   = (float*)(smem + SM_RED);       // [8][520]
    float*  mbias = (float*)(smem + SM_MB);        // [32]

    int c = blockIdx.x, tid = threadIdx.x;
    int bB = c & 31, qB = c >> 5;

    // stationary gate weights: row g -> [Wih[g][256:768] | Whh[g][:]] as float2 pairs
    for (int idx = tid; idx < 16 * 512; idx += 256) {
        int gg = idx >> 9, kp = idx & 511;
        int g = c * 16 + gg; int k = kp * 2;
        float a, b2;
        if (k < 512) { a = Wih[g * 768 + 256 + k]; b2 = Wih[g * 768 + 257 + k]; }
        else         { a = Whh[g * 512 + k - 512]; b2 = Whh[g * 512 + k - 511]; }
        wg[gg * 513 + kp] = make_float2(a, b2);
    }
    for (int idx = tid; idx < 4 * 512; idx += 256) {
        int jl = idx >> 9, k = idx & 511;
        wdh[jl * CSTR + k] = Wdec[(size_t)(c * 4 + jl) * 1536 + 1024 + k];
    }
    if (tid < 32)
        mbias[tid] = (mask[bB * SSRC + qB * 32 + tid] > 0) ? 0.f : -1e9f;

    unsigned tgt = 0;
    __syncthreads();

    int ks = tid >> 5, gt = (tid >> 3) & 3, bt = tid & 7;   // phase A roles

    for (int t = 0; t < TT; t++) {
        int par = t & 1;
        // ======== phase A: gates_rec = W . x ========
        {
            const float2* gx2 = (const float2*)g_x;
            for (int idx = tid; idx < 32 * 512; idx += 256) {
                int b = idx >> 9, kp = idx & 511;
                *(float2*)(stage + b * XSTR + kp * 2) = gx2[b * 512 + kp];
            }
            __syncthreads();

            const ull* w0 = (const ull*)(wg + (gt*4+0)*513) + ks*64;
            const ull* w1 = (const ull*)(wg + (gt*4+1)*513) + ks*64;
            const ull* w2 = (const ull*)(wg + (gt*4+2)*513) + ks*64;
            const ull* w3 = (const ull*)(wg + (gt*4+3)*513) + ks*64;
            const ull* x0 = (const ull*)(stage + (bt*4+0)*XSTR) + ks*64;
            const ull* x1 = (const ull*)(stage + (bt*4+1)*XSTR) + ks*64;
            const ull* x2 = (const ull*)(stage + (bt*4+2)*XSTR) + ks*64;
            const ull* x3 = (const ull*)(stage + (bt*4+3)*XSTR) + ks*64;
            ull a00=0,a01=0,a02=0,a03=0, a10=0,a11=0,a12=0,a13=0;
            ull a20=0,a21=0,a22=0,a23=0, a30=0,a31=0,a32=0,a33=0;
#pragma unroll 4
            for (int kp = 0; kp < 64; kp++) {
                ull wa=w0[kp], wb=w1[kp], wc=w2[kp], wd=w3[kp];
                ull xa=x0[kp], xb=x1[kp], xc=x2[kp], xd=x3[kp];
                ffma2(a00,wa,xa); ffma2(a01,wa,xb); ffma2(a02,wa,xc); ffma2(a03,wa,xd);
                ffma2(a10,wb,xa); ffma2(a11,wb,xb); ffma2(a12,wb,xc); ffma2(a13,wb,xd);
                ffma2(a20,wc,xa); ffma2(a21,wc,xb); ffma2(a22,wc,xc); ffma2(a23,wc,xd);
                ffma2(a30,wd,xa); ffma2(a31,wd,xb); ffma2(a32,wd,xc); ffma2(a33,wd,xd);
            }
            __syncthreads();
#define RSUM(v) ({ float2 f_ = u2f(v); f_.x + f_.y; })
            {
                float4 r0 = { RSUM(a00), RSUM(a01), RSUM(a02), RSUM(a03) };
                float4 r1 = { RSUM(a10), RSUM(a11), RSUM(a12), RSUM(a13) };
                float4 r2 = { RSUM(a20), RSUM(a21), RSUM(a22), RSUM(a23) };
                float4 r3 = { RSUM(a30), RSUM(a31), RSUM(a32), RSUM(a33) };
                *(float4*)(red + ks*520 + (gt*4+0)*32 + bt*4) = r0;
                *(float4*)(red + ks*520 + (gt*4+1)*32 + bt*4) = r1;
                *(float4*)(red + ks*520 + (gt*4+2)*32 + bt*4) = r2;
                *(float4*)(red + ks*520 + (gt*4+3)*32 + bt*4) = r3;
            }
#undef RSUM
            __syncthreads();
            for (int cc = tid; cc < 512; cc += 256) {
                float s = 0.f;
#pragma unroll
                for (int q = 0; q < 8; q++) s += red[q*520 + cc];
                int g = cc >> 5, b = cc & 31;
                g_gates[b * G4 + c * 16 + g] = s;
            }
        }
        gbar(++tgt);

        // ======== phase B: cell + scores + split-softmax + partial ctx ========
        {
            float* hs = stage;            // 512
            float* sc = red;              // 32
            float* es = red + 64;         // 32

            const float* gy = g_gatesy + (size_t)(t * BB + bB) * G4;
            const float* gr = g_gates + bB * G4;
#pragma unroll
            for (int jj = 0; jj < 2; jj++) {
                int j = tid + jj * 256;
                float vi = gy[j]        + gr[j];
                float vf = gy[HH+j]     + gr[HH+j];
                float vg = gy[2*HH+j]   + gr[2*HH+j];
                float vo = gy[3*HH+j]   + gr[3*HH+j];
                float cc = g_c[par][bB * HH + j];
                float ig = 1.f / (1.f + __expf(-vi));
                float fg = 1.f / (1.f + __expf(-vf));
                float gg = tanhf(vg);
                float og = 1.f / (1.f + __expf(-vo));
                float cn = fg * cc + ig * gg;
                float hn = og * tanhf(cn);
                hs[j] = hn;
                if (qB == 0) {
                    g_c[par ^ 1][bB * HH + j] = cn;
                    g_x[bB * K2H + HH + j] = hn;
                }
            }
            __syncthreads();

            int w = tid >> 5, lane = tid & 31;
            float4 hreg[4];
#pragma unroll
            for (int p = 0; p < 4; p++)
                hreg[p] = *(const float4*)(hs + (lane + p * 32) * 4);
#pragma unroll
            for (int si = 0; si < 4; si++) {
                int sl = w * 4 + si;
                const float4* kp = (const float4*)(g_keys +
                    ((size_t)bB * SSRC + qB * 32 + sl) * HH);
                float acc = 0.f;
#pragma unroll
                for (int p = 0; p < 4; p++) {
                    float4 kv = kp[lane + p * 32];
                    acc += hreg[p].x*kv.x + hreg[p].y*kv.y + hreg[p].z*kv.z + hreg[p].w*kv.w;
                }
#pragma unroll
                for (int off = 16; off; off >>= 1)
                    acc += __shfl_down_sync(0xffffffffu, acc, off);
                if (lane == 0) sc[sl] = acc + mbias[sl];
            }
            __syncthreads();

            if (tid < 32) {
                float v = sc[tid];
                float m = v;
#pragma unroll
                for (int off = 16; off; off >>= 1)
                    m = fmaxf(m, __shfl_xor_sync(0xffffffffu, m, off));
                float e = __expf(v - m);
                es[tid] = e;
                float Z = e;
#pragma unroll
                for (int off = 16; off; off >>= 1)
                    Z += __shfl_xor_sync(0xffffffffu, Z, off);
                if (tid == 0) g_bstats[qB * 32 + bB] = make_float2(m, Z);
            }
            __syncthreads();

            {
                int j = tid;
                const float* ed = g_encdec + ((size_t)bB * SSRC + qB * 32) * HH;
                float p0 = 0.f, p1 = 0.f;
#pragma unroll 8
                for (int s = 0; s < 32; s++) {
                    float e = es[s];
                    p0 += e * ed[(size_t)s * HH + j];
                    p1 += e * ed[(size_t)s * HH + j + 256];
                }
                g_pctx[(qB * 32 + bB) * HH + j] = p0;
                g_pctx[(qB * 32 + bB) * HH + j + 256] = p1;
            }
        }
        gbar(++tgt);

        // ======== phase C: combine + Wdh.h + tanh ========
        {
            for (int idx = tid; idx < 32 * 128; idx += 256) {
                int b = idx >> 7, k4 = idx & 127;
                *(float4*)(stage + b * CSTR + k4 * 4) =
                    *(const float4*)(g_x + b * K2H + HH + k4 * 4);
            }
            __syncthreads();
            int kk = tid >> 7, cell = tid & 127, bC = cell >> 2, jl = cell & 3;
            {
                const float4* wp = (const float4*)(wdh + jl * CSTR + kk * 256);
                const float4* hp = (const float4*)(stage + bC * CSTR + kk * 256);
                float acc = 0.f;
#pragma unroll 8
                for (int k4 = 0; k4 < 64; k4++) {
                    float4 wv = wp[k4], hv = hp[k4];
                    acc += wv.x*hv.x + wv.y*hv.y + wv.z*hv.z + wv.w*hv.w;
                }
                red[kk * 128 + cell] = acc;
            }
            __syncthreads();
            if (tid < 128) {
                float wsum = red[tid] + red[128 + tid];
                int b = bC, j = c * 4 + jl;
                float2 st0 = g_bstats[b], st1 = g_bstats[32 + b];
                float2 st2 = g_bstats[64 + b], st3 = g_bstats[96 + b];
                float M = fmaxf(fmaxf(st0.x, st1.x), fmaxf(st2.x, st3.x));
                float w0 = __expf(st0.x - M), w1 = __expf(st1.x - M);
                float w2 = __expf(st2.x - M), w3 = __expf(st3.x - M);
                float den = st0.y*w0 + st1.y*w1 + st2.y*w2 + st3.y*w3;
                float num = w0 * g_pctx[(0*32+b)*HH + j] + w1 * g_pctx[(1*32+b)*HH + j]
                          + w2 * g_pctx[(2*32+b)*HH + j] + w3 * g_pctx[(3*32+b)*HH + j];
                float o = tanhf(num / den + wsum + bdec[j]);
                g_x[b * K2H + j] = o;
                g_oseq[((size_t)b * TT + t) * HH + j] = o;
            }
        }
        gbar(++tgt);
    }
}

// ---------------- vocab GEMM + fused sum-exp partials ----------------
#define MMA16816(d0,d1,d2,d3,A0,A1,A2,A3,B0,B1) \
    asm volatile("mma.sync.aligned.m16n8k16.row.col.f32.bf16.bf16.f32 " \
        "{%0,%1,%2,%3}, {%4,%5,%6,%7}, {%8,%9}, {%0,%1,%2,%3};" \
        : "+f"(d0), "+f"(d1), "+f"(d2), "+f"(d3) \
        : "r"(A0), "r"(A1), "r"(A2), "r"(A3), "r"(B0), "r"(B1))

__global__ void __launch_bounds__(256) kt_vocab_gemm(
    float* __restrict__ out, const float* __restrict__ bvocab)
{
    int nb = blockIdx.x, mb = blockIdx.y;
    int wid = threadIdx.x >> 5, lane = threadIdx.x & 31;
    int wm = wid >> 2, wn = wid & 3;
    int gid = lane >> 2, tg = lane & 3;

    __shared__ float rowsum[128][4];
    if (threadIdx.x < 128) {
#pragma unroll
        for (int w = 0; w < 4; w++) rowsum[threadIdx.x][w] = 0.f;
    }
    __syncthreads();

    float acc[4][4][4];
#pragma unroll
    for (int i = 0; i < 4; i++)
#pragma unroll
        for (int j = 0; j < 4; j++)
#pragma unroll
            for (int r = 0; r < 4; r++) acc[i][j][r] = 0.f;

    int mrow0 = mb * 8 + wm * 4;
    int nrow0 = nb * 16 + wn * 4;

#pragma unroll 2
    for (int kt = 0; kt < 32; kt++) {
        uint4 af[4];
        uint2 bf[4];
#pragma unroll
        for (int mt = 0; mt < 4; mt++)
            af[mt] = g_oswz[(((mrow0 + mt) * 32 + kt) << 5) + lane];
#pragma unroll
        for (int nt = 0; nt < 4; nt++)
            bf[nt] = g_wswz[(((size_t)(nrow0 + nt) * 32 + kt) << 5) + lane];
#pragma unroll
        for (int mt = 0; mt < 4; mt++)
#pragma unroll
            for (int nt = 0; nt < 4; nt++)
                MMA16816(acc[mt][nt][0], acc[mt][nt][1], acc[mt][nt][2], acc[mt][nt][3],
                         af[mt].x, af[mt].y, af[mt].z, af[mt].w, bf[nt].x, bf[nt].y);
    }

    int m_warp = mb * 128 + wm * 64;
    int n_warp = nb * 128 + wn * 32;
#pragma unroll
    for (int mt = 0; mt < 4; mt++) {
        float s0 = 0.f, s1 = 0.f;
#pragma unroll
        for (int nt = 0; nt < 4; nt++) {
            int r = m_warp + mt * 16 + gid;
            int ci = n_warp + nt * 8 + tg * 2;
            float bv0 = bvocab[ci], bv1 = bvocab[ci + 1];
            float v00 = acc[mt][nt][0] + bv0, v01 = acc[mt][nt][1] + bv1;
            float v10 = acc[mt][nt][2] + bv0, v11 = acc[mt][nt][3] + bv1;
            float2 w0 = { v00, v01 }, w1 = { v10, v11 };
            *reinterpret_cast<float2*>(out + (size_t)r * VV + ci) = w0;
            *reinterpret_cast<float2*>(out + (size_t)(r + 8) * VV + ci) = w1;
            s0 += __expf(v00) + __expf(v01);
            s1 += __expf(v10) + __expf(v11);
        }
        s0 += __shfl_xor_sync(0xffffffffu, s0, 1);
        s0 += __shfl_xor_sync(0xffffffffu, s0, 2);
        s1 += __shfl_xor_sync(0xffffffffu, s1, 1);
        s1 += __shfl_xor_sync(0xffffffffu, s1, 2);
        if (tg == 0) {
            rowsum[wm * 64 + mt * 16 + gid][wn] = s0;
            rowsum[wm * 64 + mt * 16 + gid + 8][wn] = s1;
        }
    }
    __syncthreads();
    if (threadIdx.x < 128) {
        float p = rowsum[threadIdx.x][0] + rowsum[threadIdx.x][1]
                + rowsum[threadIdx.x][2] + rowsum[threadIdx.x][3];
        g_partial[(size_t)(mb * 128 + threadIdx.x) * NTILE + nb] = p;
    }
}

__global__ void __launch_bounds__(256) kt_lsfinal(float* __restrict__ out) {
    int row = blockIdx.x, tid = threadIdx.x;
    __shared__ float red[256];
    __shared__ float lse_s;
    float s = 0.f;
    for (int i = tid; i < NTILE; i += 256) s += g_partial[(size_t)row * NTILE + i];
    red[tid] = s;
    __syncthreads();
#pragma unroll
    for (int off = 128; off; off >>= 1) {
        if (tid < off) red[tid] += red[tid + off];
        __syncthreads();
    }
    if (tid == 0) lse_s = logf(red[0]);
    __syncthreads();
    float lse = lse_s;
    float* p = out + (size_t)row * VV;
    for (int i = tid * 4; i < VV; i += 256 * 4) {
        float4 v = *reinterpret_cast<float4*>(p + i);
        v.x -= lse; v.y -= lse; v.z -= lse; v.w -= lse;
        *reinterpret_cast<float4*>(p + i) = v;
    }
}

// ---------------- launch ----------------
extern "C" void kernel_launch(void* const* d_in, const int* in_sizes, int n_in,
                              void* d_out, int out_size)
{
    const float* enc     = (const float*)d_in[0];
    const int*   mask    = (const int*)  d_in[1];
    const int*   ids     = (const int*)  d_in[2];
    const float* h0      = (const float*)d_in[3];
    const float* c0      = (const float*)d_in[4];
    const float* emb     = (const float*)d_in[5];
    const float* W_ih    = (const float*)d_in[6];
    const float* b_ih    = (const float*)d_in[7];
    const float* W_hh    = (const float*)d_in[8];
    const float* b_hh    = (const float*)d_in[9];
    const float* W_att   = (const float*)d_in[10];
    const float* W_dec   = (const float*)d_in[11];
    const float* b_dec   = (const float*)d_in[12];
    const float* W_vocab = (const float*)d_in[13];
    const float* b_vocab = (const float*)d_in[14];
    float* out = (float*)d_out;

    cudaFuncSetAttribute(kt_scan, cudaFuncAttributeMaxDynamicSharedMemorySize, SMEM_SCAN);

    kt_init<<<(BB*HH + 255)/256, 256>>>(h0, c0);
    kt_gather<<<(TT*BB*EE + 255)/256, 256>>>(emb, ids);

    {
        float* keysp; cudaGetSymbolAddress((void**)&keysp, g_keys);
        float* edp;   cudaGetSymbolAddress((void**)&edp, g_encdec);
        float* embp;  cudaGetSymbolAddress((void**)&embp, g_embseq);
        float* gyp;   cudaGetSymbolAddress((void**)&gyp, g_gatesy);
        // keys = enc @ W_att^T : M=4096 N=512 K=1024
        kt_gemm_nt<<<dim3(8, 64), 256>>>(enc, K2H, W_att, K2H, keysp, HH, K2H, nullptr, nullptr);
        // encdec = enc @ W_dec[:, :1024]^T : M=4096 N=512 K=1024 (ldb=1536)
        kt_gemm_nt<<<dim3(8, 64), 256>>>(enc, K2H, W_dec, 1536, edp, HH, K2H, nullptr, nullptr);
        // gates_y = emb_seq @ W_ih[:, :256]^T + b_ih + b_hh : M=4096 N=2048 K=256
        kt_gemm_nt<<<dim3(32, 64), 256>>>(embp, EE, W_ih, 768, gyp, G4, EE, b_ih, b_hh);
    }

    kt_scan<<<NBLK, 256, SMEM_SCAN>>>(mask, W_ih, W_hh, W_dec, b_dec);

    kt_prepack_w<<<(4000*32*32 + 255)/256, 256>>>(W_vocab);
    kt_prepack_o<<<(256*32*32 + 255)/256, 256>>>();
    kt_vocab_gemm<<<dim3(NTILE, (BB*TT)/128), 256>>>(out, b_vocab);
    kt_lsfinal<<<BB*TT, 256>>>(out);
}

// round 9
// speedup vs baseline: 2.4847x; 1.0021x over previous
#include <cuda_runtime.h>
#include <cuda_bf16.h>
#include <cstdint>
#include <math.h>

#define BB 32
#define TT 128
#define SSRC 128
#define HH 512
#define EE 256
#define VV 32000
#define K2H 1024
#define G4 2048
#define NBLK 128
#define NTILE 250
#define FSTR 32    // flag stride in u32 (one 128B line per flag)

typedef unsigned long long ull;

// ---------------- device scratch ----------------
static __device__ float g_keys[BB*SSRC*HH];
static __device__ float g_encdec[BB*SSRC*HH];        // [b][s][j]
static __device__ float g_gatesy[TT*BB*G4];
static __device__ float g_embseq[TT*BB*EE];
static __device__ float g_x[BB*K2H];                 // [o(512), h(512)]
static __device__ float g_c[2][BB*HH];
static __device__ float g_gates[BB*G4];
static __device__ float g_pctx[4*BB*HH];             // [q][b][j]
static __device__ float2 g_bstats[4*BB];             // (m, Z)
static __device__ float g_oseq[BB*TT*HH];
static __device__ uint4 g_oswz[256*32*32];
static __device__ uint2 g_wswz[4000*32*32];
static __device__ float g_partial[(size_t)BB*TT*NTILE];
static __device__ unsigned g_flags[NBLK*FSTR];

static __device__ __forceinline__ uint32_t pk_bf2(float lo, float hi) {
    __nv_bfloat16 l = __float2bfloat16(lo), h = __float2bfloat16(hi);
    return (uint32_t)__bfloat16_as_ushort(l) | ((uint32_t)__bfloat16_as_ushort(h) << 16);
}
static __device__ __forceinline__ void ffma2(ull& acc, ull a, ull b) {
    asm volatile("fma.rn.f32x2 %0, %1, %2, %0;" : "+l"(acc) : "l"(a), "l"(b));
}
static __device__ __forceinline__ float2 u2f(ull v) {
    float2 f; asm("mov.b64 {%0, %1}, %2;" : "=f"(f.x), "=f"(f.y) : "l"(v)); return f;
}

// flag-array grid barrier: one 128B line per CTA flag, relaxed polls + backoff
static __device__ __forceinline__ void gbar(unsigned tgt) {
    __syncthreads();
    if (threadIdx.x == 0)
        asm volatile("st.release.gpu.global.u32 [%0], %1;"
                     :: "l"(&g_flags[blockIdx.x * FSTR]), "r"(tgt) : "memory");
    if (threadIdx.x < NBLK) {
        const unsigned* fp = &g_flags[threadIdx.x * FSTR];
        unsigned v;
        asm volatile("ld.relaxed.gpu.global.u32 %0, [%1];" : "=r"(v) : "l"(fp) : "memory");
        while (v < tgt) {
            __nanosleep(128);
            asm volatile("ld.relaxed.gpu.global.u32 %0, [%1];" : "=r"(v) : "l"(fp) : "memory");
        }
    }
    asm volatile("fence.acq_rel.gpu;" ::: "memory");
    __syncthreads();
}

// ---------------- prep kernels ----------------
__global__ void kt_init(const float* __restrict__ h0, const float* __restrict__ c0) {
    int i = blockIdx.x * 256 + threadIdx.x;
    if (i < NBLK * FSTR) g_flags[i] = 0;
    if (i < BB * HH) {
        int b = i / HH, j = i % HH;
        g_c[0][i] = c0[i];
        g_x[b * K2H + j] = 0.f;
        g_x[b * K2H + HH + j] = h0[i];
    }
}

__global__ void kt_gather(const float* __restrict__ emb, const int* __restrict__ ids) {
    int i = blockIdx.x * 256 + threadIdx.x;
    if (i >= TT * BB * EE) return;
    int e = i % EE; int tb = i / EE; int b = tb % BB; int t = tb / BB;
    int tok = ids[b * (TT + 1) + t];
    g_embseq[(t * BB + b) * EE + e] = emb[tok * EE + e];
}

__global__ void kt_prepack_w(const float* __restrict__ Wv) {
    int i = blockIdx.x * 256 + threadIdx.x;
    if (i >= 4000 * 32 * 32) return;
    int lane = i & 31; int tile = i >> 5;
    int kt = tile & 31; int nrow = tile >> 5;
    int gid = lane >> 2, tg = lane & 3;
    const float* p = Wv + (size_t)(nrow * 8 + gid) * HH + kt * 16 + tg * 2;
    uint2 v; v.x = pk_bf2(p[0], p[1]); v.y = pk_bf2(p[8], p[9]);
    g_wswz[i] = v;
}

__global__ void kt_prepack_o() {
    int i = blockIdx.x * 256 + threadIdx.x;
    if (i >= 256 * 32 * 32) return;
    int lane = i & 31; int tile = i >> 5;
    int kt = tile & 31; int mrow = tile >> 5;
    int gid = lane >> 2, tg = lane & 3;
    const float* p = g_oseq + (size_t)(mrow * 16 + gid) * HH + kt * 16 + tg * 2;
    uint4 v;
    v.x = pk_bf2(p[0], p[1]);
    v.y = pk_bf2(p[8 * HH], p[8 * HH + 1]);
    v.z = pk_bf2(p[8], p[9]);
    v.w = pk_bf2(p[8 * HH + 8], p[8 * HH + 9]);
    g_oswz[i] = v;
}

// ---------------- fp32 GEMM (64x64 tile, float4 staging) ----------------
__global__ void __launch_bounds__(256) kt_gemm_nt(
    const float* __restrict__ A, int lda, const float* __restrict__ Bm, int ldb,
    float* __restrict__ C, int ldc, int K,
    const float* __restrict__ bias0, const float* __restrict__ bias1)
{
    __shared__ float As[16][68];
    __shared__ float Bs[16][68];
    int tid = threadIdx.x;
    int tx = tid & 15, ty = tid >> 4;
    int m0 = blockIdx.y * 64, n0 = blockIdx.x * 64;
    int lr = tid >> 2, lq = tid & 3;
    float acc[4][4];
#pragma unroll
    for (int i = 0; i < 4; i++)
#pragma unroll
        for (int j = 0; j < 4; j++) acc[i][j] = 0.f;

    for (int k0 = 0; k0 < K; k0 += 16) {
        float4 a4 = *(const float4*)(A + (size_t)(m0 + lr) * lda + k0 + lq * 4);
        float4 b4 = *(const float4*)(Bm + (size_t)(n0 + lr) * ldb + k0 + lq * 4);
        As[lq*4+0][lr] = a4.x; As[lq*4+1][lr] = a4.y; As[lq*4+2][lr] = a4.z; As[lq*4+3][lr] = a4.w;
        Bs[lq*4+0][lr] = b4.x; Bs[lq*4+1][lr] = b4.y; Bs[lq*4+2][lr] = b4.z; Bs[lq*4+3][lr] = b4.w;
        __syncthreads();
#pragma unroll
        for (int kk = 0; kk < 16; kk++) {
            float4 av = *(const float4*)&As[kk][ty * 4];
            float4 bv = *(const float4*)&Bs[kk][tx * 4];
            acc[0][0] += av.x*bv.x; acc[0][1] += av.x*bv.y; acc[0][2] += av.x*bv.z; acc[0][3] += av.x*bv.w;
            acc[1][0] += av.y*bv.x; acc[1][1] += av.y*bv.y; acc[1][2] += av.y*bv.z; acc[1][3] += av.y*bv.w;
            acc[2][0] += av.z*bv.x; acc[2][1] += av.z*bv.y; acc[2][2] += av.z*bv.z; acc[2][3] += av.z*bv.w;
            acc[3][0] += av.w*bv.x; acc[3][1] += av.w*bv.y; acc[3][2] += av.w*bv.z; acc[3][3] += av.w*bv.w;
        }
        __syncthreads();
    }
    float bb[4];
#pragma unroll
    for (int j = 0; j < 4; j++) {
        int n = n0 + tx * 4 + j;
        bb[j] = (bias0 ? bias0[n] : 0.f) + (bias1 ? bias1[n] : 0.f);
    }
#pragma unroll
    for (int i = 0; i < 4; i++) {
        float4 o4 = { acc[i][0]+bb[0], acc[i][1]+bb[1], acc[i][2]+bb[2], acc[i][3]+bb[3] };
        *(float4*)(C + (size_t)(m0 + ty * 4 + i) * ldc + n0 + tx * 4) = o4;
    }
}

// =================== persistent scan ===================
// smem layout (bytes):
//   wg   float2[16*513]  @ 0       (65664)
//   wdh  float[4*520]    @ 65664   (8320)
//   stage float[32*XSTR] @ 73984   (132352)   XSTR=1034 (x rows, 1024 data + pad)
//   red  float[8*520]    @ 206336  (16640)
//   mbias float[32]      @ 222976  (128)
#define XSTR 1034
#define CSTR 520
#define SM_WDH 65664
#define SM_ST  73984
#define SM_RED 206336
#define SM_MB  222976
#define SMEM_SCAN 223104

__global__ void __launch_bounds__(256) kt_scan(
    const int* __restrict__ mask,
    const float* __restrict__ Wih, const float* __restrict__ Whh,
    const float* __restrict__ Wdec, const float* __restrict__ bdec)
{
    extern __shared__ char smem[];
    float2* wg    = (float2*)smem;                 // [16][513]
    float*  wdh   = (float*)(smem + SM_WDH);       // [4][520]
    float*  stage = (float*)(smem + SM_ST);        // [32][XSTR]
    float*  red   = (float*)(smem + SM_RED);       // [8][520]
    float*  mbias = (float*)(smem + SM_MB);        // [32]

    int c = blockIdx.x, tid = threadIdx.x;
    int bB = c & 31, qB = c >> 5;

    // stationary gate weights: row g -> [Wih[g][256:768] | Whh[g][:]] as float2 pairs
    for (int idx = tid; idx < 16 * 512; idx += 256) {
        int gg = idx >> 9, kp = idx & 511;
        int g = c * 16 + gg; int k = kp * 2;
        float a, b2;
        if (k < 512) { a = Wih[g * 768 + 256 + k]; b2 = Wih[g * 768 + 257 + k]; }
        else         { a = Whh[g * 512 + k - 512]; b2 = Whh[g * 512 + k - 511]; }
        wg[gg * 513 + kp] = make_float2(a, b2);
    }
    for (int idx = tid; idx < 4 * 512; idx += 256) {
        int jl = idx >> 9, k = idx & 511;
        wdh[jl * CSTR + k] = Wdec[(size_t)(c * 4 + jl) * 1536 + 1024 + k];
    }
    if (tid < 32)
        mbias[tid] = (mask[bB * SSRC + qB * 32 + tid] > 0) ? 0.f : -1e9f;

    unsigned tgt = 0;
    __syncthreads();

    int ks = tid >> 5, gt = (tid >> 3) & 3, bt = tid & 7;   // phase A roles

    for (int t = 0; t < TT; t++) {
        int par = t & 1;
        // ======== phase A: gates_rec = W . x ========
        {
            const float2* gx2 = (const float2*)g_x;
            for (int idx = tid; idx < 32 * 512; idx += 256) {
                int b = idx >> 9, kp = idx & 511;
                *(float2*)(stage + b * XSTR + kp * 2) = gx2[b * 512 + kp];
            }
            __syncthreads();

            const ull* w0 = (const ull*)(wg + (gt*4+0)*513) + ks*64;
            const ull* w1 = (const ull*)(wg + (gt*4+1)*513) + ks*64;
            const ull* w2 = (const ull*)(wg + (gt*4+2)*513) + ks*64;
            const ull* w3 = (const ull*)(wg + (gt*4+3)*513) + ks*64;
            const ull* x0 = (const ull*)(stage + (bt*4+0)*XSTR) + ks*64;
            const ull* x1 = (const ull*)(stage + (bt*4+1)*XSTR) + ks*64;
            const ull* x2 = (const ull*)(stage + (bt*4+2)*XSTR) + ks*64;
            const ull* x3 = (const ull*)(stage + (bt*4+3)*XSTR) + ks*64;
            ull a00=0,a01=0,a02=0,a03=0, a10=0,a11=0,a12=0,a13=0;
            ull a20=0,a21=0,a22=0,a23=0, a30=0,a31=0,a32=0,a33=0;
#pragma unroll 4
            for (int kp = 0; kp < 64; kp++) {
                ull wa=w0[kp], wb=w1[kp], wc=w2[kp], wd=w3[kp];
                ull xa=x0[kp], xb=x1[kp], xc=x2[kp], xd=x3[kp];
                ffma2(a00,wa,xa); ffma2(a01,wa,xb); ffma2(a02,wa,xc); ffma2(a03,wa,xd);
                ffma2(a10,wb,xa); ffma2(a11,wb,xb); ffma2(a12,wb,xc); ffma2(a13,wb,xd);
                ffma2(a20,wc,xa); ffma2(a21,wc,xb); ffma2(a22,wc,xc); ffma2(a23,wc,xd);
                ffma2(a30,wd,xa); ffma2(a31,wd,xb); ffma2(a32,wd,xc); ffma2(a33,wd,xd);
            }
            __syncthreads();
#define RSUM(v) ({ float2 f_ = u2f(v); f_.x + f_.y; })
            {
                float4 r0 = { RSUM(a00), RSUM(a01), RSUM(a02), RSUM(a03) };
                float4 r1 = { RSUM(a10), RSUM(a11), RSUM(a12), RSUM(a13) };
                float4 r2 = { RSUM(a20), RSUM(a21), RSUM(a22), RSUM(a23) };
                float4 r3 = { RSUM(a30), RSUM(a31), RSUM(a32), RSUM(a33) };
                *(float4*)(red + ks*520 + (gt*4+0)*32 + bt*4) = r0;
                *(float4*)(red + ks*520 + (gt*4+1)*32 + bt*4) = r1;
                *(float4*)(red + ks*520 + (gt*4+2)*32 + bt*4) = r2;
                *(float4*)(red + ks*520 + (gt*4+3)*32 + bt*4) = r3;
            }
#undef RSUM
            __syncthreads();
            for (int cc = tid; cc < 512; cc += 256) {
                float s = 0.f;
#pragma unroll
                for (int q = 0; q < 8; q++) s += red[q*520 + cc];
                int g = cc >> 5, b = cc & 31;
                g_gates[b * G4 + c * 16 + g] = s;
            }
        }
        gbar(++tgt);

        // ======== phase B: cell + scores + split-softmax + partial ctx ========
        {
            float* hs = stage;            // 512
            float* sc = red;              // 32
            float* es = red + 64;         // 32

            const float* gy = g_gatesy + (size_t)(t * BB + bB) * G4;
            const float* gr = g_gates + bB * G4;
#pragma unroll
            for (int jj = 0; jj < 2; jj++) {
                int j = tid + jj * 256;
                float vi = gy[j]        + gr[j];
                float vf = gy[HH+j]     + gr[HH+j];
                float vg = gy[2*HH+j]   + gr[2*HH+j];
                float vo = gy[3*HH+j]   + gr[3*HH+j];
                float cc = g_c[par][bB * HH + j];
                float ig = 1.f / (1.f + __expf(-vi));
                float fg = 1.f / (1.f + __expf(-vf));
                float gg = tanhf(vg);
                float og = 1.f / (1.f + __expf(-vo));
                float cn = fg * cc + ig * gg;
                float hn = og * tanhf(cn);
                hs[j] = hn;
                if (qB == 0) {
                    g_c[par ^ 1][bB * HH + j] = cn;
                    g_x[bB * K2H + HH + j] = hn;
                }
            }
            __syncthreads();

            int w = tid >> 5, lane = tid & 31;
            float4 hreg[4];
#pragma unroll
            for (int p = 0; p < 4; p++)
                hreg[p] = *(const float4*)(hs + (lane + p * 32) * 4);
#pragma unroll
            for (int si = 0; si < 4; si++) {
                int sl = w * 4 + si;
                const float4* kp = (const float4*)(g_keys +
                    ((size_t)bB * SSRC + qB * 32 + sl) * HH);
                float acc = 0.f;
#pragma unroll
                for (int p = 0; p < 4; p++) {
                    float4 kv = kp[lane + p * 32];
                    acc += hreg[p].x*kv.x + hreg[p].y*kv.y + hreg[p].z*kv.z + hreg[p].w*kv.w;
                }
#pragma unroll
                for (int off = 16; off; off >>= 1)
                    acc += __shfl_down_sync(0xffffffffu, acc, off);
                if (lane == 0) sc[sl] = acc + mbias[sl];
            }
            __syncthreads();

            if (tid < 32) {
                float v = sc[tid];
                float m = v;
#pragma unroll
                for (int off = 16; off; off >>= 1)
                    m = fmaxf(m, __shfl_xor_sync(0xffffffffu, m, off));
                float e = __expf(v - m);
                es[tid] = e;
                float Z = e;
#pragma unroll
                for (int off = 16; off; off >>= 1)
                    Z += __shfl_xor_sync(0xffffffffu, Z, off);
                if (tid == 0) g_bstats[qB * 32 + bB] = make_float2(m, Z);
            }
            __syncthreads();

            {
                int j = tid;
                const float* ed = g_encdec + ((size_t)bB * SSRC + qB * 32) * HH;
                float p0 = 0.f, p1 = 0.f;
#pragma unroll 8
                for (int s = 0; s < 32; s++) {
                    float e = es[s];
                    p0 += e * ed[(size_t)s * HH + j];
                    p1 += e * ed[(size_t)s * HH + j + 256];
                }
                g_pctx[(qB * 32 + bB) * HH + j] = p0;
                g_pctx[(qB * 32 + bB) * HH + j + 256] = p1;
            }
        }
        gbar(++tgt);

        // ======== phase C: combine + Wdh.h + tanh ========
        {
            for (int idx = tid; idx < 32 * 128; idx += 256) {
                int b = idx >> 7, k4 = idx & 127;
                *(float4*)(stage + b * CSTR + k4 * 4) =
                    *(const float4*)(g_x + b * K2H + HH + k4 * 4);
            }
            __syncthreads();
            int kk = tid >> 7, cell = tid & 127, bC = cell >> 2, jl = cell & 3;
            {
                const float4* wp = (const float4*)(wdh + jl * CSTR + kk * 256);
                const float4* hp = (const float4*)(stage + bC * CSTR + kk * 256);
                float acc = 0.f;
#pragma unroll 8
                for (int k4 = 0; k4 < 64; k4++) {
                    float4 wv = wp[k4], hv = hp[k4];
                    acc += wv.x*hv.x + wv.y*hv.y + wv.z*hv.z + wv.w*hv.w;
                }
                red[kk * 128 + cell] = acc;
            }
            __syncthreads();
            if (tid < 128) {
                float wsum = red[tid] + red[128 + tid];
                int b = bC, j = c * 4 + jl;
                float2 st0 = g_bstats[b], st1 = g_bstats[32 + b];
                float2 st2 = g_bstats[64 + b], st3 = g_bstats[96 + b];
                float M = fmaxf(fmaxf(st0.x, st1.x), fmaxf(st2.x, st3.x));
                float w0 = __expf(st0.x - M), w1 = __expf(st1.x - M);
                float w2 = __expf(st2.x - M), w3 = __expf(st3.x - M);
                float den = st0.y*w0 + st1.y*w1 + st2.y*w2 + st3.y*w3;
                float num = w0 * g_pctx[(0*32+b)*HH + j] + w1 * g_pctx[(1*32+b)*HH + j]
                          + w2 * g_pctx[(2*32+b)*HH + j] + w3 * g_pctx[(3*32+b)*HH + j];
                float o = tanhf(num / den + wsum + bdec[j]);
                g_x[b * K2H + j] = o;
                g_oseq[((size_t)b * TT + t) * HH + j] = o;
            }
        }
        gbar(++tgt);
    }
}

// ---------------- vocab GEMM + fused sum-exp partials ----------------
#define MMA16816(d0,d1,d2,d3,A0,A1,A2,A3,B0,B1) \
    asm volatile("mma.sync.aligned.m16n8k16.row.col.f32.bf16.bf16.f32 " \
        "{%0,%1,%2,%3}, {%4,%5,%6,%7}, {%8,%9}, {%0,%1,%2,%3};" \
        : "+f"(d0), "+f"(d1), "+f"(d2), "+f"(d3) \
        : "r"(A0), "r"(A1), "r"(A2), "r"(A3), "r"(B0), "r"(B1))

__global__ void __launch_bounds__(256) kt_vocab_gemm(
    float* __restrict__ out, const float* __restrict__ bvocab)
{
    int nb = blockIdx.x, mb = blockIdx.y;
    int wid = threadIdx.x >> 5, lane = threadIdx.x & 31;
    int wm = wid >> 2, wn = wid & 3;
    int gid = lane >> 2, tg = lane & 3;

    __shared__ float rowsum[128][4];
    if (threadIdx.x < 128) {
#pragma unroll
        for (int w = 0; w < 4; w++) rowsum[threadIdx.x][w] = 0.f;
    }
    __syncthreads();

    float acc[4][4][4];
#pragma unroll
    for (int i = 0; i < 4; i++)
#pragma unroll
        for (int j = 0; j < 4; j++)
#pragma unroll
            for (int r = 0; r < 4; r++) acc[i][j][r] = 0.f;

    int mrow0 = mb * 8 + wm * 4;
    int nrow0 = nb * 16 + wn * 4;

#pragma unroll 2
    for (int kt = 0; kt < 32; kt++) {
        uint4 af[4];
        uint2 bf[4];
#pragma unroll
        for (int mt = 0; mt < 4; mt++)
            af[mt] = g_oswz[(((mrow0 + mt) * 32 + kt) << 5) + lane];
#pragma unroll
        for (int nt = 0; nt < 4; nt++)
            bf[nt] = g_wswz[(((size_t)(nrow0 + nt) * 32 + kt) << 5) + lane];
#pragma unroll
        for (int mt = 0; mt < 4; mt++)
#pragma unroll
            for (int nt = 0; nt < 4; nt++)
                MMA16816(acc[mt][nt][0], acc[mt][nt][1], acc[mt][nt][2], acc[mt][nt][3],
                         af[mt].x, af[mt].y, af[mt].z, af[mt].w, bf[nt].x, bf[nt].y);
    }

    int m_warp = mb * 128 + wm * 64;
    int n_warp = nb * 128 + wn * 32;
#pragma unroll
    for (int mt = 0; mt < 4; mt++) {
        float s0 = 0.f, s1 = 0.f;
#pragma unroll
        for (int nt = 0; nt < 4; nt++) {
            int r = m_warp + mt * 16 + gid;
            int ci = n_warp + nt * 8 + tg * 2;
            float bv0 = bvocab[ci], bv1 = bvocab[ci + 1];
            float v00 = acc[mt][nt][0] + bv0, v01 = acc[mt][nt][1] + bv1;
            float v10 = acc[mt][nt][2] + bv0, v11 = acc[mt][nt][3] + bv1;
            float2 w0 = { v00, v01 }, w1 = { v10, v11 };
            *reinterpret_cast<float2*>(out + (size_t)r * VV + ci) = w0;
            *reinterpret_cast<float2*>(out + (size_t)(r + 8) * VV + ci) = w1;
            s0 += __expf(v00) + __expf(v01);
            s1 += __expf(v10) + __expf(v11);
        }
        s0 += __shfl_xor_sync(0xffffffffu, s0, 1);
        s0 += __shfl_xor_sync(0xffffffffu, s0, 2);
        s1 += __shfl_xor_sync(0xffffffffu, s1, 1);
        s1 += __shfl_xor_sync(0xffffffffu, s1, 2);
        if (tg == 0) {
            rowsum[wm * 64 + mt * 16 + gid][wn] = s0;
            rowsum[wm * 64 + mt * 16 + gid + 8][wn] = s1;
        }
    }
    __syncthreads();
    if (threadIdx.x < 128) {
        float p = rowsum[threadIdx.x][0] + rowsum[threadIdx.x][1]
                + rowsum[threadIdx.x][2] + rowsum[threadIdx.x][3];
        g_partial[(size_t)(mb * 128 + threadIdx.x) * NTILE + nb] = p;
    }
}

__global__ void __launch_bounds__(256) kt_lsfinal(float* __restrict__ out) {
    int row = blockIdx.x, tid = threadIdx.x;
    __shared__ float red[256];
    __shared__ float lse_s;
    float s = 0.f;
    for (int i = tid; i < NTILE; i += 256) s += g_partial[(size_t)row * NTILE + i];
    red[tid] = s;
    __syncthreads();
#pragma unroll
    for (int off = 128; off; off >>= 1) {
        if (tid < off) red[tid] += red[tid + off];
        __syncthreads();
    }
    if (tid == 0) lse_s = logf(red[0]);
    __syncthreads();
    float lse = lse_s;
    float* p = out + (size_t)row * VV;
    for (int i = tid * 4; i < VV; i += 256 * 4) {
        float4 v = *reinterpret_cast<float4*>(p + i);
        v.x -= lse; v.y -= lse; v.z -= lse; v.w -= lse;
        *reinterpret_cast<float4*>(p + i) = v;
    }
}

// ---------------- launch ----------------
extern "C" void kernel_launch(void* const* d_in, const int* in_sizes, int n_in,
                              void* d_out, int out_size)
{
    const float* enc     = (const float*)d_in[0];
    const int*   mask    = (const int*)  d_in[1];
    const int*   ids     = (const int*)  d_in[2];
    const float* h0      = (const float*)d_in[3];
    const float* c0      = (const float*)d_in[4];
    const float* emb     = (const float*)d_in[5];
    const float* W_ih    = (const float*)d_in[6];
    const float* b_ih    = (const float*)d_in[7];
    const float* W_hh    = (const float*)d_in[8];
    const float* b_hh    = (const float*)d_in[9];
    const float* W_att   = (const float*)d_in[10];
    const float* W_dec   = (const float*)d_in[11];
    const float* b_dec   = (const float*)d_in[12];
    const float* W_vocab = (const float*)d_in[13];
    const float* b_vocab = (const float*)d_in[14];
    float* out = (float*)d_out;

    cudaFuncSetAttribute(kt_scan, cudaFuncAttributeMaxDynamicSharedMemorySize, SMEM_SCAN);

    kt_init<<<(BB*HH + 255)/256, 256>>>(h0, c0);
    kt_gather<<<(TT*BB*EE + 255)/256, 256>>>(emb, ids);

    {
        float* keysp; cudaGetSymbolAddress((void**)&keysp, g_keys);
        float* edp;   cudaGetSymbolAddress((void**)&edp, g_encdec);
        float* embp;  cudaGetSymbolAddress((void**)&embp, g_embseq);
        float* gyp;   cudaGetSymbolAddress((void**)&gyp, g_gatesy);
        // keys = enc @ W_att^T : M=4096 N=512 K=1024
        kt_gemm_nt<<<dim3(8, 64), 256>>>(enc, K2H, W_att, K2H, keysp, HH, K2H, nullptr, nullptr);
        // encdec = enc @ W_dec[:, :1024]^T : M=4096 N=512 K=1024 (ldb=1536)
        kt_gemm_nt<<<dim3(8, 64), 256>>>(enc, K2H, W_dec, 1536, edp, HH, K2H, nullptr, nullptr);
        // gates_y = emb_seq @ W_ih[:, :256]^T + b_ih + b_hh : M=4096 N=2048 K=256
        kt_gemm_nt<<<dim3(32, 64), 256>>>(embp, EE, W_ih, 768, gyp, G4, EE, b_ih, b_hh);
    }

    kt_scan<<<NBLK, 256, SMEM_SCAN>>>(mask, W_ih, W_hh, W_dec, b_dec);

    kt_prepack_w<<<(4000*32*32 + 255)/256, 256>>>(W_vocab);
    kt_prepack_o<<<(256*32*32 + 255)/256, 256>>>();
    kt_vocab_gemm<<<dim3(NTILE, (BB*TT)/128), 256>>>(out, b_vocab);
    kt_lsfinal<<<BB*TT, 256>>>(out);
}

// round 10
// speedup vs baseline: 2.4850x; 1.0001x over previous
#include <cuda_runtime.h>
#include <cuda_bf16.h>
#include <cstdint>
#include <math.h>

#define BB 32
#define TT 128
#define SSRC 128
#define HH 512
#define EE 256
#define VV 32000
#define K2H 1024
#define G4 2048
#define NBLK 128
#define NTILE 250
#define FSTR 32    // flag stride in u32 (one 128B line per flag)

typedef unsigned long long ull;

// ---------------- device scratch ----------------
static __device__ float g_keys[BB*SSRC*HH];
static __device__ float g_encdec[BB*SSRC*HH];        // [b][s][j]
static __device__ float g_gatesy[TT*BB*G4];
static __device__ float g_embseq[TT*BB*EE];
static __device__ float g_x[BB*K2H];                 // [o(512), h(512)]
static __device__ float g_c[2][BB*HH];
static __device__ float g_gates[BB*G4];
static __device__ float g_pctx[4*BB*HH];             // [q][b][j]
static __device__ float2 g_bstats[4*BB];             // (m, Z)
static __device__ float g_oseq[BB*TT*HH];
static __device__ uint4 g_oswz[256*32*32];
static __device__ uint2 g_wswz[4000*32*32];
static __device__ float g_partial[(size_t)BB*TT*NTILE];
static __device__ unsigned g_flags[NBLK*FSTR];

static __device__ __forceinline__ uint32_t pk_bf2(float lo, float hi) {
    __nv_bfloat16 l = __float2bfloat16(lo), h = __float2bfloat16(hi);
    return (uint32_t)__bfloat16_as_ushort(l) | ((uint32_t)__bfloat16_as_ushort(h) << 16);
}
static __device__ __forceinline__ void ffma2(ull& acc, ull a, ull b) {
    asm volatile("fma.rn.f32x2 %0, %1, %2, %0;" : "+l"(acc) : "l"(a), "l"(b));
}
static __device__ __forceinline__ float2 u2f(ull v) {
    float2 f; asm("mov.b64 {%0, %1}, %2;" : "=f"(f.x), "=f"(f.y) : "l"(v)); return f;
}

// flag-array grid barrier: one 128B line per CTA flag, relaxed polls + backoff
static __device__ __forceinline__ void gbar(unsigned tgt) {
    __syncthreads();
    if (threadIdx.x == 0)
        asm volatile("st.release.gpu.global.u32 [%0], %1;"
                     :: "l"(&g_flags[blockIdx.x * FSTR]), "r"(tgt) : "memory");
    if (threadIdx.x < NBLK) {
        const unsigned* fp = &g_flags[threadIdx.x * FSTR];
        unsigned v;
        asm volatile("ld.relaxed.gpu.global.u32 %0, [%1];" : "=r"(v) : "l"(fp) : "memory");
        while (v < tgt) {
            __nanosleep(128);
            asm volatile("ld.relaxed.gpu.global.u32 %0, [%1];" : "=r"(v) : "l"(fp) : "memory");
        }
    }
    asm volatile("fence.acq_rel.gpu;" ::: "memory");
    __syncthreads();
}

// ---------------- prep kernels ----------------
__global__ void kt_init(const float* __restrict__ h0, const float* __restrict__ c0) {
    int i = blockIdx.x * 256 + threadIdx.x;
    if (i < NBLK * FSTR) g_flags[i] = 0;
    if (i < BB * HH) {
        int b = i / HH, j = i % HH;
        g_c[0][i] = c0[i];
        g_x[b * K2H + j] = 0.f;
        g_x[b * K2H + HH + j] = h0[i];
    }
}

__global__ void kt_gather(const float* __restrict__ emb, const int* __restrict__ ids) {
    int i = blockIdx.x * 256 + threadIdx.x;
    if (i >= TT * BB * EE) return;
    int e = i % EE; int tb = i / EE; int b = tb % BB; int t = tb / BB;
    int tok = ids[b * (TT + 1) + t];
    g_embseq[(t * BB + b) * EE + e] = emb[tok * EE + e];
}

__global__ void kt_prepack_w(const float* __restrict__ Wv) {
    int i = blockIdx.x * 256 + threadIdx.x;
    if (i >= 4000 * 32 * 32) return;
    int lane = i & 31; int tile = i >> 5;
    int kt = tile & 31; int nrow = tile >> 5;
    int gid = lane >> 2, tg = lane & 3;
    const float* p = Wv + (size_t)(nrow * 8 + gid) * HH + kt * 16 + tg * 2;
    uint2 v; v.x = pk_bf2(p[0], p[1]); v.y = pk_bf2(p[8], p[9]);
    g_wswz[i] = v;
}

__global__ void kt_prepack_o() {
    int i = blockIdx.x * 256 + threadIdx.x;
    if (i >= 256 * 32 * 32) return;
    int lane = i & 31; int tile = i >> 5;
    int kt = tile & 31; int mrow = tile >> 5;
    int gid = lane >> 2, tg = lane & 3;
    const float* p = g_oseq + (size_t)(mrow * 16 + gid) * HH + kt * 16 + tg * 2;
    uint4 v;
    v.x = pk_bf2(p[0], p[1]);
    v.y = pk_bf2(p[8 * HH], p[8 * HH + 1]);
    v.z = pk_bf2(p[8], p[9]);
    v.w = pk_bf2(p[8 * HH + 8], p[8 * HH + 9]);
    g_oswz[i] = v;
}

// ---------------- fp32 GEMM (64x64 tile, float4 staging) ----------------
__global__ void __launch_bounds__(256) kt_gemm_nt(
    const float* __restrict__ A, int lda, const float* __restrict__ Bm, int ldb,
    float* __restrict__ C, int ldc, int K,
    const float* __restrict__ bias0, const float* __restrict__ bias1)
{
    __shared__ float As[16][68];
    __shared__ float Bs[16][68];
    int tid = threadIdx.x;
    int tx = tid & 15, ty = tid >> 4;
    int m0 = blockIdx.y * 64, n0 = blockIdx.x * 64;
    int lr = tid >> 2, lq = tid & 3;
    float acc[4][4];
#pragma unroll
    for (int i = 0; i < 4; i++)
#pragma unroll
        for (int j = 0; j < 4; j++) acc[i][j] = 0.f;

    for (int k0 = 0; k0 < K; k0 += 16) {
        float4 a4 = *(const float4*)(A + (size_t)(m0 + lr) * lda + k0 + lq * 4);
        float4 b4 = *(const float4*)(Bm + (size_t)(n0 + lr) * ldb + k0 + lq * 4);
        As[lq*4+0][lr] = a4.x; As[lq*4+1][lr] = a4.y; As[lq*4+2][lr] = a4.z; As[lq*4+3][lr] = a4.w;
        Bs[lq*4+0][lr] = b4.x; Bs[lq*4+1][lr] = b4.y; Bs[lq*4+2][lr] = b4.z; Bs[lq*4+3][lr] = b4.w;
        __syncthreads();
#pragma unroll
        for (int kk = 0; kk < 16; kk++) {
            float4 av = *(const float4*)&As[kk][ty * 4];
            float4 bv = *(const float4*)&Bs[kk][tx * 4];
            acc[0][0] += av.x*bv.x; acc[0][1] += av.x*bv.y; acc[0][2] += av.x*bv.z; acc[0][3] += av.x*bv.w;
            acc[1][0] += av.y*bv.x; acc[1][1] += av.y*bv.y; acc[1][2] += av.y*bv.z; acc[1][3] += av.y*bv.w;
            acc[2][0] += av.z*bv.x; acc[2][1] += av.z*bv.y; acc[2][2] += av.z*bv.z; acc[2][3] += av.z*bv.w;
            acc[3][0] += av.w*bv.x; acc[3][1] += av.w*bv.y; acc[3][2] += av.w*bv.z; acc[3][3] += av.w*bv.w;
        }
        __syncthreads();
    }
    float bb[4];
#pragma unroll
    for (int j = 0; j < 4; j++) {
        int n = n0 + tx * 4 + j;
        bb[j] = (bias0 ? bias0[n] : 0.f) + (bias1 ? bias1[n] : 0.f);
    }
#pragma unroll
    for (int i = 0; i < 4; i++) {
        float4 o4 = { acc[i][0]+bb[0], acc[i][1]+bb[1], acc[i][2]+bb[2], acc[i][3]+bb[3] };
        *(float4*)(C + (size_t)(m0 + ty * 4 + i) * ldc + n0 + tx * 4) = o4;
    }
}

// =================== persistent scan ===================
// smem layout (bytes):
//   wg   float2[16*513]  @ 0       (65664)
//   wdh  float[4*520]    @ 65664   (8320)
//   stage float[32*XSTR] @ 73984   (132352)   XSTR=1034 (x rows, 1024 data + pad)
//   red  float[8*520]    @ 206336  (16640)
//   mbias float[32]      @ 222976  (128)
#define XSTR 1034
#define CSTR 520
#define SM_WDH 65664
#define SM_ST  73984
#define SM_RED 206336
#define SM_MB  222976
#define SMEM_SCAN 223104

__global__ void __launch_bounds__(256) kt_scan(
    const int* __restrict__ mask,
    const float* __restrict__ Wih, const float* __restrict__ Whh,
    const float* __restrict__ Wdec, const float* __restrict__ bdec)
{
    extern __shared__ char smem[];
    float2* wg    = (float2*)smem;                 // [16][513]
    float*  wdh   = (float*)(smem + SM_WDH);       // [4][520]
    float*  stage = (float*)(smem + SM_ST);        // [32][XSTR]
    float*  red   = (float*)(smem + SM_RED);       // [8][520]
    float*  mbias = (float*)(smem + SM_MB);        // [32]

    int c = blockIdx.x, tid = threadIdx.x;
    int bB = c & 31, qB = c >> 5;

    // stationary gate weights: row g -> [Wih[g][256:768] | Whh[g][:]] as float2 pairs
    for (int idx = tid; idx < 16 * 512; idx += 256) {
        int gg = idx >> 9, kp = idx & 511;
        int g = c * 16 + gg; int k = kp * 2;
        float a, b2;
        if (k < 512) { a = Wih[g * 768 + 256 + k]; b2 = Wih[g * 768 + 257 + k]; }
        else         { a = Whh[g * 512 + k - 512]; b2 = Whh[g * 512 + k - 511]; }
        wg[gg * 513 + kp] = make_float2(a, b2);
    }
    for (int idx = tid; idx < 4 * 512; idx += 256) {
        int jl = idx >> 9, k = idx & 511;
        wdh[jl * CSTR + k] = Wdec[(size_t)(c * 4 + jl) * 1536 + 1024 + k];
    }
    if (tid < 32)
        mbias[tid] = (mask[bB * SSRC + qB * 32 + tid] > 0) ? 0.f : -1e9f;

    unsigned tgt = 0;
    __syncthreads();

    int ks = tid >> 5, gt = (tid >> 3) & 3, bt = tid & 7;   // phase A roles

    for (int t = 0; t < TT; t++) {
        int par = t & 1;
        // ======== phase A: gates_rec = W . x ========
        {
            const float2* gx2 = (const float2*)g_x;
            for (int idx = tid; idx < 32 * 512; idx += 256) {
                int b = idx >> 9, kp = idx & 511;
                *(float2*)(stage + b * XSTR + kp * 2) = gx2[b * 512 + kp];
            }
            __syncthreads();

            const ull* w0 = (const ull*)(wg + (gt*4+0)*513) + ks*64;
            const ull* w1 = (const ull*)(wg + (gt*4+1)*513) + ks*64;
            const ull* w2 = (const ull*)(wg + (gt*4+2)*513) + ks*64;
            const ull* w3 = (const ull*)(wg + (gt*4+3)*513) + ks*64;
            const ull* x0 = (const ull*)(stage + (bt*4+0)*XSTR) + ks*64;
            const ull* x1 = (const ull*)(stage + (bt*4+1)*XSTR) + ks*64;
            const ull* x2 = (const ull*)(stage + (bt*4+2)*XSTR) + ks*64;
            const ull* x3 = (const ull*)(stage + (bt*4+3)*XSTR) + ks*64;
            ull a00=0,a01=0,a02=0,a03=0, a10=0,a11=0,a12=0,a13=0;
            ull a20=0,a21=0,a22=0,a23=0, a30=0,a31=0,a32=0,a33=0;
#pragma unroll 4
            for (int kp = 0; kp < 64; kp++) {
                ull wa=w0[kp], wb=w1[kp], wc=w2[kp], wd=w3[kp];
                ull xa=x0[kp], xb=x1[kp], xc=x2[kp], xd=x3[kp];
                ffma2(a00,wa,xa); ffma2(a01,wa,xb); ffma2(a02,wa,xc); ffma2(a03,wa,xd);
                ffma2(a10,wb,xa); ffma2(a11,wb,xb); ffma2(a12,wb,xc); ffma2(a13,wb,xd);
                ffma2(a20,wc,xa); ffma2(a21,wc,xb); ffma2(a22,wc,xc); ffma2(a23,wc,xd);
                ffma2(a30,wd,xa); ffma2(a31,wd,xb); ffma2(a32,wd,xc); ffma2(a33,wd,xd);
            }
            __syncthreads();
#define RSUM(v) ({ float2 f_ = u2f(v); f_.x + f_.y; })
            {
                float4 r0 = { RSUM(a00), RSUM(a01), RSUM(a02), RSUM(a03) };
                float4 r1 = { RSUM(a10), RSUM(a11), RSUM(a12), RSUM(a13) };
                float4 r2 = { RSUM(a20), RSUM(a21), RSUM(a22), RSUM(a23) };
                float4 r3 = { RSUM(a30), RSUM(a31), RSUM(a32), RSUM(a33) };
                *(float4*)(red + ks*520 + (gt*4+0)*32 + bt*4) = r0;
                *(float4*)(red + ks*520 + (gt*4+1)*32 + bt*4) = r1;
                *(float4*)(red + ks*520 + (gt*4+2)*32 + bt*4) = r2;
                *(float4*)(red + ks*520 + (gt*4+3)*32 + bt*4) = r3;
            }
#undef RSUM
            __syncthreads();
            for (int cc = tid; cc < 512; cc += 256) {
                float s = 0.f;
#pragma unroll
                for (int q = 0; q < 8; q++) s += red[q*520 + cc];
                int g = cc >> 5, b = cc & 31;
                g_gates[b * G4 + c * 16 + g] = s;
            }
        }
        gbar(++tgt);

        // ======== phase B: cell + scores + split-softmax + partial ctx ========
        {
            float* hs = stage;            // 512
            float* sc = red;              // 32
            float* es = red + 64;         // 32

            const float* gy = g_gatesy + (size_t)(t * BB + bB) * G4;
            const float* gr = g_gates + bB * G4;
#pragma unroll
            for (int jj = 0; jj < 2; jj++) {
                int j = tid + jj * 256;
                float vi = gy[j]        + gr[j];
                float vf = gy[HH+j]     + gr[HH+j];
                float vg = gy[2*HH+j]   + gr[2*HH+j];
                float vo = gy[3*HH+j]   + gr[3*HH+j];
                float cc = g_c[par][bB * HH + j];
                float ig = 1.f / (1.f + __expf(-vi));
                float fg = 1.f / (1.f + __expf(-vf));
                float gg = tanhf(vg);
                float og = 1.f / (1.f + __expf(-vo));
                float cn = fg * cc + ig * gg;
                float hn = og * tanhf(cn);
                hs[j] = hn;
                if (qB == 0) {
                    g_c[par ^ 1][bB * HH + j] = cn;
                    g_x[bB * K2H + HH + j] = hn;
                }
            }
            __syncthreads();

            int w = tid >> 5, lane = tid & 31;
            float4 hreg[4];
#pragma unroll
            for (int p = 0; p < 4; p++)
                hreg[p] = *(const float4*)(hs + (lane + p * 32) * 4);
#pragma unroll
            for (int si = 0; si < 4; si++) {
                int sl = w * 4 + si;
                const float4* kp = (const float4*)(g_keys +
                    ((size_t)bB * SSRC + qB * 32 + sl) * HH);
                float acc = 0.f;
#pragma unroll
                for (int p = 0; p < 4; p++) {
                    float4 kv = kp[lane + p * 32];
                    acc += hreg[p].x*kv.x + hreg[p].y*kv.y + hreg[p].z*kv.z + hreg[p].w*kv.w;
                }
#pragma unroll
                for (int off = 16; off; off >>= 1)
                    acc += __shfl_down_sync(0xffffffffu, acc, off);
                if (lane == 0) sc[sl] = acc + mbias[sl];
            }
            __syncthreads();

            if (tid < 32) {
                float v = sc[tid];
                float m = v;
#pragma unroll
                for (int off = 16; off; off >>= 1)
                    m = fmaxf(m, __shfl_xor_sync(0xffffffffu, m, off));
                float e = __expf(v - m);
                es[tid] = e;
                float Z = e;
#pragma unroll
                for (int off = 16; off; off >>= 1)
                    Z += __shfl_xor_sync(0xffffffffu, Z, off);
                if (tid == 0) g_bstats[qB * 32 + bB] = make_float2(m, Z);
            }
            __syncthreads();

            {
                int j = tid;
                const float* ed = g_encdec + ((size_t)bB * SSRC + qB * 32) * HH;
                float p0 = 0.f, p1 = 0.f;
#pragma unroll 8
                for (int s = 0; s < 32; s++) {
                    float e = es[s];
                    p0 += e * ed[(size_t)s * HH + j];
                    p1 += e * ed[(size_t)s * HH + j + 256];
                }
                g_pctx[(qB * 32 + bB) * HH + j] = p0;
                g_pctx[(qB * 32 + bB) * HH + j + 256] = p1;
            }
        }
        gbar(++tgt);

        // ======== phase C: combine + Wdh.h + tanh ========
        {
            for (int idx = tid; idx < 32 * 128; idx += 256) {
                int b = idx >> 7, k4 = idx & 127;
                *(float4*)(stage + b * CSTR + k4 * 4) =
                    *(const float4*)(g_x + b * K2H + HH + k4 * 4);
            }
            __syncthreads();
            int kk = tid >> 7, cell = tid & 127, bC = cell >> 2, jl = cell & 3;
            {
                const float4* wp = (const float4*)(wdh + jl * CSTR + kk * 256);
                const float4* hp = (const float4*)(stage + bC * CSTR + kk * 256);
                float acc = 0.f;
#pragma unroll 8
                for (int k4 = 0; k4 < 64; k4++) {
                    float4 wv = wp[k4], hv = hp[k4];
                    acc += wv.x*hv.x + wv.y*hv.y + wv.z*hv.z + wv.w*hv.w;
                }
                red[kk * 128 + cell] = acc;
            }
            __syncthreads();
            if (tid < 128) {
                float wsum = red[tid] + red[128 + tid];
                int b = bC, j = c * 4 + jl;
                float2 st0 = g_bstats[b], st1 = g_bstats[32 + b];
                float2 st2 = g_bstats[64 + b], st3 = g_bstats[96 + b];
                float M = fmaxf(fmaxf(st0.x, st1.x), fmaxf(st2.x, st3.x));
                float w0 = __expf(st0.x - M), w1 = __expf(st1.x - M);
                float w2 = __expf(st2.x - M), w3 = __expf(st3.x - M);
                float den = st0.y*w0 + st1.y*w1 + st2.y*w2 + st3.y*w3;
                float num = w0 * g_pctx[(0*32+b)*HH + j] + w1 * g_pctx[(1*32+b)*HH + j]
                          + w2 * g_pctx[(2*32+b)*HH + j] + w3 * g_pctx[(3*32+b)*HH + j];
                float o = tanhf(num / den + wsum + bdec[j]);
                g_x[b * K2H + j] = o;
                g_oseq[((size_t)b * TT + t) * HH + j] = o;
            }
        }
        gbar(++tgt);
    }
}

// ---------------- vocab GEMM + fused sum-exp partials ----------------
#define MMA16816(d0,d1,d2,d3,A0,A1,A2,A3,B0,B1) \
    asm volatile("mma.sync.aligned.m16n8k16.row.col.f32.bf16.bf16.f32 " \
        "{%0,%1,%2,%3}, {%4,%5,%6,%7}, {%8,%9}, {%0,%1,%2,%3};" \
        : "+f"(d0), "+f"(d1), "+f"(d2), "+f"(d3) \
        : "r"(A0), "r"(A1), "r"(A2), "r"(A3), "r"(B0), "r"(B1))

__global__ void __launch_bounds__(256) kt_vocab_gemm(
    float* __restrict__ out, const float* __restrict__ bvocab)
{
    int nb = blockIdx.x, mb = blockIdx.y;
    int wid = threadIdx.x >> 5, lane = threadIdx.x & 31;
    int wm = wid >> 2, wn = wid & 3;
    int gid = lane >> 2, tg = lane & 3;

    __shared__ float rowsum[128][4];
    if (threadIdx.x < 128) {
#pragma unroll
        for (int w = 0; w < 4; w++) rowsum[threadIdx.x][w] = 0.f;
    }
    __syncthreads();

    float acc[4][4][4];
#pragma unroll
    for (int i = 0; i < 4; i++)
#pragma unroll
        for (int j = 0; j < 4; j++)
#pragma unroll
            for (int r = 0; r < 4; r++) acc[i][j][r] = 0.f;

    int mrow0 = mb * 8 + wm * 4;
    int nrow0 = nb * 16 + wn * 4;

#pragma unroll 2
    for (int kt = 0; kt < 32; kt++) {
        uint4 af[4];
        uint2 bf[4];
#pragma unroll
        for (int mt = 0; mt < 4; mt++)
            af[mt] = g_oswz[(((mrow0 + mt) * 32 + kt) << 5) + lane];
#pragma unroll
        for (int nt = 0; nt < 4; nt++)
            bf[nt] = g_wswz[(((size_t)(nrow0 + nt) * 32 + kt) << 5) + lane];
#pragma unroll
        for (int mt = 0; mt < 4; mt++)
#pragma unroll
            for (int nt = 0; nt < 4; nt++)
                MMA16816(acc[mt][nt][0], acc[mt][nt][1], acc[mt][nt][2], acc[mt][nt][3],
                         af[mt].x, af[mt].y, af[mt].z, af[mt].w, bf[nt].x, bf[nt].y);
    }

    int m_warp = mb * 128 + wm * 64;
    int n_warp = nb * 128 + wn * 32;
#pragma unroll
    for (int mt = 0; mt < 4; mt++) {
        float s0 = 0.f, s1 = 0.f;
#pragma unroll
        for (int nt = 0; nt < 4; nt++) {
            int r = m_warp + mt * 16 + gid;
            int ci = n_warp + nt * 8 + tg * 2;
            float bv0 = bvocab[ci], bv1 = bvocab[ci + 1];
            float v00 = acc[mt][nt][0] + bv0, v01 = acc[mt][nt][1] + bv1;
            float v10 = acc[mt][nt][2] + bv0, v11 = acc[mt][nt][3] + bv1;
            float2 w0 = { v00, v01 }, w1 = { v10, v11 };
            *reinterpret_cast<float2*>(out + (size_t)r * VV + ci) = w0;
            *reinterpret_cast<float2*>(out + (size_t)(r + 8) * VV + ci) = w1;
            s0 += __expf(v00) + __expf(v01);
            s1 += __expf(v10) + __expf(v11);
        }
        s0 += __shfl_xor_sync(0xffffffffu, s0, 1);
        s0 += __shfl_xor_sync(0xffffffffu, s0, 2);
        s1 += __shfl_xor_sync(0xffffffffu, s1, 1);
        s1 += __shfl_xor_sync(0xffffffffu, s1, 2);
        if (tg == 0) {
            rowsum[wm * 64 + mt * 16 + gid][wn] = s0;
            rowsum[wm * 64 + mt * 16 + gid + 8][wn] = s1;
        }
    }
    __syncthreads();
    if (threadIdx.x < 128) {
        float p = rowsum[threadIdx.x][0] + rowsum[threadIdx.x][1]
                + rowsum[threadIdx.x][2] + rowsum[threadIdx.x][3];
        g_partial[(size_t)(mb * 128 + threadIdx.x) * NTILE + nb] = p;
    }
}

__global__ void __launch_bounds__(256) kt_lsfinal(float* __restrict__ out) {
    int row = blockIdx.x, tid = threadIdx.x;
    __shared__ float red[256];
    __shared__ float lse_s;
    float s = 0.f;
    for (int i = tid; i < NTILE; i += 256) s += g_partial[(size_t)row * NTILE + i];
    red[tid] = s;
    __syncthreads();
#pragma unroll
    for (int off = 128; off; off >>= 1) {
        if (tid < off) red[tid] += red[tid + off];
        __syncthreads();
    }
    if (tid == 0) lse_s = logf(red[0]);
    __syncthreads();
    float lse = lse_s;
    float* p = out + (size_t)row * VV;
    for (int i = tid * 4; i < VV; i += 256 * 4) {
        float4 v = *reinterpret_cast<float4*>(p + i);
        v.x -= lse; v.y -= lse; v.z -= lse; v.w -= lse;
        *reinterpret_cast<float4*>(p + i) = v;
    }
}

// ---------------- launch ----------------
extern "C" void kernel_launch(void* const* d_in, const int* in_sizes, int n_in,
                              void* d_out, int out_size)
{
    const float* enc     = (const float*)d_in[0];
    const int*   mask    = (const int*)  d_in[1];
    const int*   ids     = (const int*)  d_in[2];
    const float* h0      = (const float*)d_in[3];
    const float* c0      = (const float*)d_in[4];
    const float* emb     = (const float*)d_in[5];
    const float* W_ih    = (const float*)d_in[6];
    const float* b_ih    = (const float*)d_in[7];
    const float* W_hh    = (const float*)d_in[8];
    const float* b_hh    = (const float*)d_in[9];
    const float* W_att   = (const float*)d_in[10];
    const float* W_dec   = (const float*)d_in[11];
    const float* b_dec   = (const float*)d_in[12];
    const float* W_vocab = (const float*)d_in[13];
    const float* b_vocab = (const float*)d_in[14];
    float* out = (float*)d_out;

    cudaFuncSetAttribute(kt_scan, cudaFuncAttributeMaxDynamicSharedMemorySize, SMEM_SCAN);

    kt_init<<<(BB*HH + 255)/256, 256>>>(h0, c0);
    kt_gather<<<(TT*BB*EE + 255)/256, 256>>>(emb, ids);

    {
        float* keysp; cudaGetSymbolAddress((void**)&keysp, g_keys);
        float* edp;   cudaGetSymbolAddress((void**)&edp, g_encdec);
        float* embp;  cudaGetSymbolAddress((void**)&embp, g_embseq);
        float* gyp;   cudaGetSymbolAddress((void**)&gyp, g_gatesy);
        // keys = enc @ W_att^T : M=4096 N=512 K=1024
        kt_gemm_nt<<<dim3(8, 64), 256>>>(enc, K2H, W_att, K2H, keysp, HH, K2H, nullptr, nullptr);
        // encdec = enc @ W_dec[:, :1024]^T : M=4096 N=512 K=1024 (ldb=1536)
        kt_gemm_nt<<<dim3(8, 64), 256>>>(enc, K2H, W_dec, 1536, edp, HH, K2H, nullptr, nullptr);
        // gates_y = emb_seq @ W_ih[:, :256]^T + b_ih + b_hh : M=4096 N=2048 K=256
        kt_gemm_nt<<<dim3(32, 64), 256>>>(embp, EE, W_ih, 768, gyp, G4, EE, b_ih, b_hh);
    }

    kt_scan<<<NBLK, 256, SMEM_SCAN>>>(mask, W_ih, W_hh, W_dec, b_dec);

    kt_prepack_w<<<(4000*32*32 + 255)/256, 256>>>(W_vocab);
    kt_prepack_o<<<(256*32*32 + 255)/256, 256>>>();
    kt_vocab_gemm<<<dim3(NTILE, (BB*TT)/128), 256>>>(out, b_vocab);
    kt_lsfinal<<<BB*TT, 256>>>(out);
}

// round 11
// speedup vs baseline: 2.4853x; 1.0001x over previous
#include <cuda_runtime.h>
#include <cuda_bf16.h>
#include <cstdint>
#include <math.h>

#define BB 32
#define TT 128
#define SSRC 128
#define HH 512
#define EE 256
#define VV 32000
#define K2H 1024
#define G4 2048
#define NBLK 128
#define NTILE 250
#define FSTR 32    // flag stride in u32 (one 128B line per flag)

typedef unsigned long long ull;

// ---------------- device scratch ----------------
static __device__ float g_keys[BB*SSRC*HH];
static __device__ float g_encdec[BB*SSRC*HH];        // [b][s][j]
static __device__ float g_gatesy[TT*BB*G4];
static __device__ float g_embseq[TT*BB*EE];
static __device__ float g_x[BB*K2H];                 // [o(512), h(512)]
static __device__ float g_c[2][BB*HH];
static __device__ float g_gates[BB*G4];
static __device__ float g_pctx[4*BB*HH];             // [q][b][j]
static __device__ float2 g_bstats[4*BB];             // (m, Z)
static __device__ float g_oseq[BB*TT*HH];
static __device__ uint4 g_oswz[256*32*32];
static __device__ uint2 g_wswz[4000*32*32];
static __device__ float g_partial[(size_t)BB*TT*NTILE];
static __device__ unsigned g_flags[NBLK*FSTR];

static __device__ __forceinline__ uint32_t pk_bf2(float lo, float hi) {
    __nv_bfloat16 l = __float2bfloat16(lo), h = __float2bfloat16(hi);
    return (uint32_t)__bfloat16_as_ushort(l) | ((uint32_t)__bfloat16_as_ushort(h) << 16);
}
static __device__ __forceinline__ void ffma2(ull& acc, ull a, ull b) {
    asm volatile("fma.rn.f32x2 %0, %1, %2, %0;" : "+l"(acc) : "l"(a), "l"(b));
}
static __device__ __forceinline__ float2 u2f(ull v) {
    float2 f; asm("mov.b64 {%0, %1}, %2;" : "=f"(f.x), "=f"(f.y) : "l"(v)); return f;
}

// flag-array grid barrier: one 128B line per CTA flag, relaxed polls + backoff
static __device__ __forceinline__ void gbar(unsigned tgt) {
    __syncthreads();
    if (threadIdx.x == 0)
        asm volatile("st.release.gpu.global.u32 [%0], %1;"
                     :: "l"(&g_flags[blockIdx.x * FSTR]), "r"(tgt) : "memory");
    if (threadIdx.x < NBLK) {
        const unsigned* fp = &g_flags[threadIdx.x * FSTR];
        unsigned v;
        asm volatile("ld.relaxed.gpu.global.u32 %0, [%1];" : "=r"(v) : "l"(fp) : "memory");
        while (v < tgt) {
            __nanosleep(128);
            asm volatile("ld.relaxed.gpu.global.u32 %0, [%1];" : "=r"(v) : "l"(fp) : "memory");
        }
    }
    asm volatile("fence.acq_rel.gpu;" ::: "memory");
    __syncthreads();
}

// ---------------- prep kernels ----------------
__global__ void kt_init(const float* __restrict__ h0, const float* __restrict__ c0) {
    int i = blockIdx.x * 256 + threadIdx.x;
    if (i < NBLK * FSTR) g_flags[i] = 0;
    if (i < BB * HH) {
        int b = i / HH, j = i % HH;
        g_c[0][i] = c0[i];
        g_x[b * K2H + j] = 0.f;
        g_x[b * K2H + HH + j] = h0[i];
    }
}

__global__ void kt_gather(const float* __restrict__ emb, const int* __restrict__ ids) {
    int i = blockIdx.x * 256 + threadIdx.x;
    if (i >= TT * BB * EE) return;
    int e = i % EE; int tb = i / EE; int b = tb % BB; int t = tb / BB;
    int tok = ids[b * (TT + 1) + t];
    g_embseq[(t * BB + b) * EE + e] = emb[tok * EE + e];
}

__global__ void kt_prepack_w(const float* __restrict__ Wv) {
    int i = blockIdx.x * 256 + threadIdx.x;
    if (i >= 4000 * 32 * 32) return;
    int lane = i & 31; int tile = i >> 5;
    int kt = tile & 31; int nrow = tile >> 5;
    int gid = lane >> 2, tg = lane & 3;
    const float* p = Wv + (size_t)(nrow * 8 + gid) * HH + kt * 16 + tg * 2;
    uint2 v; v.x = pk_bf2(p[0], p[1]); v.y = pk_bf2(p[8], p[9]);
    g_wswz[i] = v;
}

__global__ void kt_prepack_o() {
    int i = blockIdx.x * 256 + threadIdx.x;
    if (i >= 256 * 32 * 32) return;
    int lane = i & 31; int tile = i >> 5;
    int kt = tile & 31; int mrow = tile >> 5;
    int gid = lane >> 2, tg = lane & 3;
    const float* p = g_oseq + (size_t)(mrow * 16 + gid) * HH + kt * 16 + tg * 2;
    uint4 v;
    v.x = pk_bf2(p[0], p[1]);
    v.y = pk_bf2(p[8 * HH], p[8 * HH + 1]);
    v.z = pk_bf2(p[8], p[9]);
    v.w = pk_bf2(p[8 * HH + 8], p[8 * HH + 9]);
    g_oswz[i] = v;
}

// ---------------- fp32 GEMM (64x64 tile, float4 staging) ----------------
__global__ void __launch_bounds__(256) kt_gemm_nt(
    const float* __restrict__ A, int lda, const float* __restrict__ Bm, int ldb,
    float* __restrict__ C, int ldc, int K,
    const float* __restrict__ bias0, const float* __restrict__ bias1)
{
    __shared__ float As[16][68];
    __shared__ float Bs[16][68];
    int tid = threadIdx.x;
    int tx = tid & 15, ty = tid >> 4;
    int m0 = blockIdx.y * 64, n0 = blockIdx.x * 64;
    int lr = tid >> 2, lq = tid & 3;
    float acc[4][4];
#pragma unroll
    for (int i = 0; i < 4; i++)
#pragma unroll
        for (int j = 0; j < 4; j++) acc[i][j] = 0.f;

    for (int k0 = 0; k0 < K; k0 += 16) {
        float4 a4 = *(const float4*)(A + (size_t)(m0 + lr) * lda + k0 + lq * 4);
        float4 b4 = *(const float4*)(Bm + (size_t)(n0 + lr) * ldb + k0 + lq * 4);
        As[lq*4+0][lr] = a4.x; As[lq*4+1][lr] = a4.y; As[lq*4+2][lr] = a4.z; As[lq*4+3][lr] = a4.w;
        Bs[lq*4+0][lr] = b4.x; Bs[lq*4+1][lr] = b4.y; Bs[lq*4+2][lr] = b4.z; Bs[lq*4+3][lr] = b4.w;
        __syncthreads();
#pragma unroll
        for (int kk = 0; kk < 16; kk++) {
            float4 av = *(const float4*)&As[kk][ty * 4];
            float4 bv = *(const float4*)&Bs[kk][tx * 4];
            acc[0][0] += av.x*bv.x; acc[0][1] += av.x*bv.y; acc[0][2] += av.x*bv.z; acc[0][3] += av.x*bv.w;
            acc[1][0] += av.y*bv.x; acc[1][1] += av.y*bv.y; acc[1][2] += av.y*bv.z; acc[1][3] += av.y*bv.w;
            acc[2][0] += av.z*bv.x; acc[2][1] += av.z*bv.y; acc[2][2] += av.z*bv.z; acc[2][3] += av.z*bv.w;
            acc[3][0] += av.w*bv.x; acc[3][1] += av.w*bv.y; acc[3][2] += av.w*bv.z; acc[3][3] += av.w*bv.w;
        }
        __syncthreads();
    }
    float bb[4];
#pragma unroll
    for (int j = 0; j < 4; j++) {
        int n = n0 + tx * 4 + j;
        bb[j] = (bias0 ? bias0[n] : 0.f) + (bias1 ? bias1[n] : 0.f);
    }
#pragma unroll
    for (int i = 0; i < 4; i++) {
        float4 o4 = { acc[i][0]+bb[0], acc[i][1]+bb[1], acc[i][2]+bb[2], acc[i][3]+bb[3] };
        *(float4*)(C + (size_t)(m0 + ty * 4 + i) * ldc + n0 + tx * 4) = o4;
    }
}

// =================== persistent scan ===================
// smem layout (bytes):
//   wg   float2[16*513]  @ 0       (65664)
//   wdh  float[4*520]    @ 65664   (8320)
//   stage float[32*XSTR] @ 73984   (132352)   XSTR=1034 (x rows, 1024 data + pad)
//   red  float[8*520]    @ 206336  (16640)
//   mbias float[32]      @ 222976  (128)
#define XSTR 1034
#define CSTR 520
#define SM_WDH 65664
#define SM_ST  73984
#define SM_RED 206336
#define SM_MB  222976
#define SMEM_SCAN 223104

__global__ void __launch_bounds__(256) kt_scan(
    const int* __restrict__ mask,
    const float* __restrict__ Wih, const float* __restrict__ Whh,
    const float* __restrict__ Wdec, const float* __restrict__ bdec)
{
    extern __shared__ char smem[];
    float2* wg    = (float2*)smem;                 // [16][513]
    float*  wdh   = (float*)(smem + SM_WDH);       // [4][520]
    float*  stage = (float*)(smem + SM_ST);        // [32][XSTR]
    float*  red   = (float*)(smem + SM_RED);       // [8][520]
    float*  mbias = (float*)(smem + SM_MB);        // [32]

    int c = blockIdx.x, tid = threadIdx.x;
    int bB = c & 31, qB = c >> 5;

    // stationary gate weights: row g -> [Wih[g][256:768] | Whh[g][:]] as float2 pairs
    for (int idx = tid; idx < 16 * 512; idx += 256) {
        int gg = idx >> 9, kp = idx & 511;
        int g = c * 16 + gg; int k = kp * 2;
        float a, b2;
        if (k < 512) { a = Wih[g * 768 + 256 + k]; b2 = Wih[g * 768 + 257 + k]; }
        else         { a = Whh[g * 512 + k - 512]; b2 = Whh[g * 512 + k - 511]; }
        wg[gg * 513 + kp] = make_float2(a, b2);
    }
    for (int idx = tid; idx < 4 * 512; idx += 256) {
        int jl = idx >> 9, k = idx & 511;
        wdh[jl * CSTR + k] = Wdec[(size_t)(c * 4 + jl) * 1536 + 1024 + k];
    }
    if (tid < 32)
        mbias[tid] = (mask[bB * SSRC + qB * 32 + tid] > 0) ? 0.f : -1e9f;

    unsigned tgt = 0;
    __syncthreads();

    int ks = tid >> 5, gt = (tid >> 3) & 3, bt = tid & 7;   // phase A roles

    for (int t = 0; t < TT; t++) {
        int par = t & 1;
        // ======== phase A: gates_rec = W . x ========
        {
            const float2* gx2 = (const float2*)g_x;
            for (int idx = tid; idx < 32 * 512; idx += 256) {
                int b = idx >> 9, kp = idx & 511;
                *(float2*)(stage + b * XSTR + kp * 2) = gx2[b * 512 + kp];
            }
            __syncthreads();

            const ull* w0 = (const ull*)(wg + (gt*4+0)*513) + ks*64;
            const ull* w1 = (const ull*)(wg + (gt*4+1)*513) + ks*64;
            const ull* w2 = (const ull*)(wg + (gt*4+2)*513) + ks*64;
            const ull* w3 = (const ull*)(wg + (gt*4+3)*513) + ks*64;
            const ull* x0 = (const ull*)(stage + (bt*4+0)*XSTR) + ks*64;
            const ull* x1 = (const ull*)(stage + (bt*4+1)*XSTR) + ks*64;
            const ull* x2 = (const ull*)(stage + (bt*4+2)*XSTR) + ks*64;
            const ull* x3 = (const ull*)(stage + (bt*4+3)*XSTR) + ks*64;
            ull a00=0,a01=0,a02=0,a03=0, a10=0,a11=0,a12=0,a13=0;
            ull a20=0,a21=0,a22=0,a23=0, a30=0,a31=0,a32=0,a33=0;
#pragma unroll 4
            for (int kp = 0; kp < 64; kp++) {
                ull wa=w0[kp], wb=w1[kp], wc=w2[kp], wd=w3[kp];
                ull xa=x0[kp], xb=x1[kp], xc=x2[kp], xd=x3[kp];
                ffma2(a00,wa,xa); ffma2(a01,wa,xb); ffma2(a02,wa,xc); ffma2(a03,wa,xd);
                ffma2(a10,wb,xa); ffma2(a11,wb,xb); ffma2(a12,wb,xc); ffma2(a13,wb,xd);
                ffma2(a20,wc,xa); ffma2(a21,wc,xb); ffma2(a22,wc,xc); ffma2(a23,wc,xd);
                ffma2(a30,wd,xa); ffma2(a31,wd,xb); ffma2(a32,wd,xc); ffma2(a33,wd,xd);
            }
            __syncthreads();
#define RSUM(v) ({ float2 f_ = u2f(v); f_.x + f_.y; })
            {
                float4 r0 = { RSUM(a00), RSUM(a01), RSUM(a02), RSUM(a03) };
                float4 r1 = { RSUM(a10), RSUM(a11), RSUM(a12), RSUM(a13) };
                float4 r2 = { RSUM(a20), RSUM(a21), RSUM(a22), RSUM(a23) };
                float4 r3 = { RSUM(a30), RSUM(a31), RSUM(a32), RSUM(a33) };
                *(float4*)(red + ks*520 + (gt*4+0)*32 + bt*4) = r0;
                *(float4*)(red + ks*520 + (gt*4+1)*32 + bt*4) = r1;
                *(float4*)(red + ks*520 + (gt*4+2)*32 + bt*4) = r2;
                *(float4*)(red + ks*520 + (gt*4+3)*32 + bt*4) = r3;
            }
#undef RSUM
            __syncthreads();
            for (int cc = tid; cc < 512; cc += 256) {
                float s = 0.f;
#pragma unroll
                for (int q = 0; q < 8; q++) s += red[q*520 + cc];
                int g = cc >> 5, b = cc & 31;
                g_gates[b * G4 + c * 16 + g] = s;
            }
        }
        gbar(++tgt);

        // ======== phase B: cell + scores + split-softmax + partial ctx ========
        {
            float* hs = stage;            // 512
            float* sc = red;              // 32
            float* es = red + 64;         // 32

            const float* gy = g_gatesy + (size_t)(t * BB + bB) * G4;
            const float* gr = g_gates + bB * G4;
#pragma unroll
            for (int jj = 0; jj < 2; jj++) {
                int j = tid + jj * 256;
                float vi = gy[j]        + gr[j];
                float vf = gy[HH+j]     + gr[HH+j];
                float vg = gy[2*HH+j]   + gr[2*HH+j];
                float vo = gy[3*HH+j]   + gr[3*HH+j];
                float cc = g_c[par][bB * HH + j];
                float ig = 1.f / (1.f + __expf(-vi));
                float fg = 1.f / (1.f + __expf(-vf));
                float gg = tanhf(vg);
                float og = 1.f / (1.f + __expf(-vo));
                float cn = fg * cc + ig * gg;
                float hn = og * tanhf(cn);
                hs[j] = hn;
                if (qB == 0) {
                    g_c[par ^ 1][bB * HH + j] = cn;
                    g_x[bB * K2H + HH + j] = hn;
                }
            }
            __syncthreads();

            int w = tid >> 5, lane = tid & 31;
            float4 hreg[4];
#pragma unroll
            for (int p = 0; p < 4; p++)
                hreg[p] = *(const float4*)(hs + (lane + p * 32) * 4);
#pragma unroll
            for (int si = 0; si < 4; si++) {
                int sl = w * 4 + si;
                const float4* kp = (const float4*)(g_keys +
                    ((size_t)bB * SSRC + qB * 32 + sl) * HH);
                float acc = 0.f;
#pragma unroll
                for (int p = 0; p < 4; p++) {
                    float4 kv = kp[lane + p * 32];
                    acc += hreg[p].x*kv.x + hreg[p].y*kv.y + hreg[p].z*kv.z + hreg[p].w*kv.w;
                }
#pragma unroll
                for (int off = 16; off; off >>= 1)
                    acc += __shfl_down_sync(0xffffffffu, acc, off);
                if (lane == 0) sc[sl] = acc + mbias[sl];
            }
            __syncthreads();

            if (tid < 32) {
                float v = sc[tid];
                float m = v;
#pragma unroll
                for (int off = 16; off; off >>= 1)
                    m = fmaxf(m, __shfl_xor_sync(0xffffffffu, m, off));
                float e = __expf(v - m);
                es[tid] = e;
                float Z = e;
#pragma unroll
                for (int off = 16; off; off >>= 1)
                    Z += __shfl_xor_sync(0xffffffffu, Z, off);
                if (tid == 0) g_bstats[qB * 32 + bB] = make_float2(m, Z);
            }
            __syncthreads();

            {
                int j = tid;
                const float* ed = g_encdec + ((size_t)bB * SSRC + qB * 32) * HH;
                float p0 = 0.f, p1 = 0.f;
#pragma unroll 8
                for (int s = 0; s < 32; s++) {
                    float e = es[s];
                    p0 += e * ed[(size_t)s * HH + j];
                    p1 += e * ed[(size_t)s * HH + j + 256];
                }
                g_pctx[(qB * 32 + bB) * HH + j] = p0;
                g_pctx[(qB * 32 + bB) * HH + j + 256] = p1;
            }
        }
        gbar(++tgt);

        // ======== phase C: combine + Wdh.h + tanh ========
        {
            for (int idx = tid; idx < 32 * 128; idx += 256) {
                int b = idx >> 7, k4 = idx & 127;
                *(float4*)(stage + b * CSTR + k4 * 4) =
                    *(const float4*)(g_x + b * K2H + HH + k4 * 4);
            }
            __syncthreads();
            int kk = tid >> 7, cell = tid & 127, bC = cell >> 2, jl = cell & 3;
            {
                const float4* wp = (const float4*)(wdh + jl * CSTR + kk * 256);
                const float4* hp = (const float4*)(stage + bC * CSTR + kk * 256);
                float acc = 0.f;
#pragma unroll 8
                for (int k4 = 0; k4 < 64; k4++) {
                    float4 wv = wp[k4], hv = hp[k4];
                    acc += wv.x*hv.x + wv.y*hv.y + wv.z*hv.z + wv.w*hv.w;
                }
                red[kk * 128 + cell] = acc;
            }
            __syncthreads();
            if (tid < 128) {
                float wsum = red[tid] + red[128 + tid];
                int b = bC, j = c * 4 + jl;
                float2 st0 = g_bstats[b], st1 = g_bstats[32 + b];
                float2 st2 = g_bstats[64 + b], st3 = g_bstats[96 + b];
                float M = fmaxf(fmaxf(st0.x, st1.x), fmaxf(st2.x, st3.x));
                float w0 = __expf(st0.x - M), w1 = __expf(st1.x - M);
                float w2 = __expf(st2.x - M), w3 = __expf(st3.x - M);
                float den = st0.y*w0 + st1.y*w1 + st2.y*w2 + st3.y*w3;
                float num = w0 * g_pctx[(0*32+b)*HH + j] + w1 * g_pctx[(1*32+b)*HH + j]
                          + w2 * g_pctx[(2*32+b)*HH + j] + w3 * g_pctx[(3*32+b)*HH + j];
                float o = tanhf(num / den + wsum + bdec[j]);
                g_x[b * K2H + j] = o;
                g_oseq[((size_t)b * TT + t) * HH + j] = o;
            }
        }
        gbar(++tgt);
    }
}

// ---------------- vocab GEMM + fused sum-exp partials ----------------
#define MMA16816(d0,d1,d2,d3,A0,A1,A2,A3,B0,B1) \
    asm volatile("mma.sync.aligned.m16n8k16.row.col.f32.bf16.bf16.f32 " \
        "{%0,%1,%2,%3}, {%4,%5,%6,%7}, {%8,%9}, {%0,%1,%2,%3};" \
        : "+f"(d0), "+f"(d1), "+f"(d2), "+f"(d3) \
        : "r"(A0), "r"(A1), "r"(A2), "r"(A3), "r"(B0), "r"(B1))

__global__ void __launch_bounds__(256) kt_vocab_gemm(
    float* __restrict__ out, const float* __restrict__ bvocab)
{
    int nb = blockIdx.x, mb = blockIdx.y;
    int wid = threadIdx.x >> 5, lane = threadIdx.x & 31;
    int wm = wid >> 2, wn = wid & 3;
    int gid = lane >> 2, tg = lane & 3;

    __shared__ float rowsum[128][4];
    if (threadIdx.x < 128) {
#pragma unroll
        for (int w = 0; w < 4; w++) rowsum[threadIdx.x][w] = 0.f;
    }
    __syncthreads();

    float acc[4][4][4];
#pragma unroll
    for (int i = 0; i < 4; i++)
#pragma unroll
        for (int j = 0; j < 4; j++)
#pragma unroll
            for (int r = 0; r < 4; r++) acc[i][j][r] = 0.f;

    int mrow0 = mb * 8 + wm * 4;
    int nrow0 = nb * 16 + wn * 4;

#pragma unroll 2
    for (int kt = 0; kt < 32; kt++) {
        uint4 af[4];
        uint2 bf[4];
#pragma unroll
        for (int mt = 0; mt < 4; mt++)
            af[mt] = g_oswz[(((mrow0 + mt) * 32 + kt) << 5) + lane];
#pragma unroll
        for (int nt = 0; nt < 4; nt++)
            bf[nt] = g_wswz[(((size_t)(nrow0 + nt) * 32 + kt) << 5) + lane];
#pragma unroll
        for (int mt = 0; mt < 4; mt++)
#pragma unroll
            for (int nt = 0; nt < 4; nt++)
                MMA16816(acc[mt][nt][0], acc[mt][nt][1], acc[mt][nt][2], acc[mt][nt][3],
                         af[mt].x, af[mt].y, af[mt].z, af[mt].w, bf[nt].x, bf[nt].y);
    }

    int m_warp = mb * 128 + wm * 64;
    int n_warp = nb * 128 + wn * 32;
#pragma unroll
    for (int mt = 0; mt < 4; mt++) {
        float s0 = 0.f, s1 = 0.f;
#pragma unroll
        for (int nt = 0; nt < 4; nt++) {
            int r = m_warp + mt * 16 + gid;
            int ci = n_warp + nt * 8 + tg * 2;
            float bv0 = bvocab[ci], bv1 = bvocab[ci + 1];
            float v00 = acc[mt][nt][0] + bv0, v01 = acc[mt][nt][1] + bv1;
            float v10 = acc[mt][nt][2] + bv0, v11 = acc[mt][nt][3] + bv1;
            float2 w0 = { v00, v01 }, w1 = { v10, v11 };
            *reinterpret_cast<float2*>(out + (size_t)r * VV + ci) = w0;
            *reinterpret_cast<float2*>(out + (size_t)(r + 8) * VV + ci) = w1;
            s0 += __expf(v00) + __expf(v01);
            s1 += __expf(v10) + __expf(v11);
        }
        s0 += __shfl_xor_sync(0xffffffffu, s0, 1);
        s0 += __shfl_xor_sync(0xffffffffu, s0, 2);
        s1 += __shfl_xor_sync(0xffffffffu, s1, 1);
        s1 += __shfl_xor_sync(0xffffffffu, s1, 2);
        if (tg == 0) {
            rowsum[wm * 64 + mt * 16 + gid][wn] = s0;
            rowsum[wm * 64 + mt * 16 + gid + 8][wn] = s1;
        }
    }
    __syncthreads();
    if (threadIdx.x < 128) {
        float p = rowsum[threadIdx.x][0] + rowsum[threadIdx.x][1]
                + rowsum[threadIdx.x][2] + rowsum[threadIdx.x][3];
        g_partial[(size_t)(mb * 128 + threadIdx.x) * NTILE + nb] = p;
    }
}

__global__ void __launch_bounds__(256) kt_lsfinal(float* __restrict__ out) {
    int row = blockIdx.x, tid = threadIdx.x;
    __shared__ float red[256];
    __shared__ float lse_s;
    float s = 0.f;
    for (int i = tid; i < NTILE; i += 256) s += g_partial[(size_t)row * NTILE + i];
    red[tid] = s;
    __syncthreads();
#pragma unroll
    for (int off = 128; off; off >>= 1) {
        if (tid < off) red[tid] += red[tid + off];
        __syncthreads();
    }
    if (tid == 0) lse_s = logf(red[0]);
    __syncthreads();
    float lse = lse_s;
    float* p = out + (size_t)row * VV;
    for (int i = tid * 4; i < VV; i += 256 * 4) {
        float4 v = *reinterpret_cast<float4*>(p + i);
        v.x -= lse; v.y -= lse; v.z -= lse; v.w -= lse;
        *reinterpret_cast<float4*>(p + i) = v;
    }
}

// ---------------- launch ----------------
extern "C" void kernel_launch(void* const* d_in, const int* in_sizes, int n_in,
                              void* d_out, int out_size)
{
    const float* enc     = (const float*)d_in[0];
    const int*   mask    = (const int*)  d_in[1];
    const int*   ids     = (const int*)  d_in[2];
    const float* h0      = (const float*)d_in[3];
    const float* c0      = (const float*)d_in[4];
    const float* emb     = (const float*)d_in[5];
    const float* W_ih    = (const float*)d_in[6];
    const float* b_ih    = (const float*)d_in[7];
    const float* W_hh    = (const float*)d_in[8];
    const float* b_hh    = (const float*)d_in[9];
    const float* W_att   = (const float*)d_in[10];
    const float* W_dec   = (const float*)d_in[11];
    const float* b_dec   = (const float*)d_in[12];
    const float* W_vocab = (const float*)d_in[13];
    const float* b_vocab = (const float*)d_in[14];
    float* out = (float*)d_out;

    cudaFuncSetAttribute(kt_scan, cudaFuncAttributeMaxDynamicSharedMemorySize, SMEM_SCAN);

    kt_init<<<(BB*HH + 255)/256, 256>>>(h0, c0);
    kt_gather<<<(TT*BB*EE + 255)/256, 256>>>(emb, ids);

    {
        float* keysp; cudaGetSymbolAddress((void**)&keysp, g_keys);
        float* edp;   cudaGetSymbolAddress((void**)&edp, g_encdec);
        float* embp;  cudaGetSymbolAddress((void**)&embp, g_embseq);
        float* gyp;   cudaGetSymbolAddress((void**)&gyp, g_gatesy);
        // keys = enc @ W_att^T : M=4096 N=512 K=1024
        kt_gemm_nt<<<dim3(8, 64), 256>>>(enc, K2H, W_att, K2H, keysp, HH, K2H, nullptr, nullptr);
        // encdec = enc @ W_dec[:, :1024]^T : M=4096 N=512 K=1024 (ldb=1536)
        kt_gemm_nt<<<dim3(8, 64), 256>>>(enc, K2H, W_dec, 1536, edp, HH, K2H, nullptr, nullptr);
        // gates_y = emb_seq @ W_ih[:, :256]^T + b_ih + b_hh : M=4096 N=2048 K=256
        kt_gemm_nt<<<dim3(32, 64), 256>>>(embp, EE, W_ih, 768, gyp, G4, EE, b_ih, b_hh);
    }

    kt_scan<<<NBLK, 256, SMEM_SCAN>>>(mask, W_ih, W_hh, W_dec, b_dec);

    kt_prepack_w<<<(4000*32*32 + 255)/256, 256>>>(W_vocab);
    kt_prepack_o<<<(256*32*32 + 255)/256, 256>>>();
    kt_vocab_gemm<<<dim3(NTILE, (BB*TT)/128), 256>>>(out, b_vocab);
    kt_lsfinal<<<BB*TT, 256>>>(out);
}

// round 12
// speedup vs baseline: 2.8849x; 1.1608x over previous
#include <cuda_runtime.h>
#include <cuda_bf16.h>
#include <cstdint>
#include <math.h>

#define BB 32
#define TT 128
#define SSRC 128
#define HH 512
#define EE 256
#define VV 32000
#define K2H 1024
#define G4 2048
#define NBLK 128
#define NTILE 250
#define FSTR 32

typedef unsigned long long ull;

// ---------------- device scratch ----------------
static __device__ float g_keys[BB*SSRC*HH];
static __device__ float g_encdec[BB*SSRC*HH];        // [b][s][j]
static __device__ float g_gatesy[TT*BB*G4];
static __device__ float g_embseq[TT*BB*EE];
static __device__ float g_x[BB*K2H];                 // [o(512), h(512)]
static __device__ float g_pctx[4*BB*HH];             // [q][b][j]
static __device__ float2 g_bstats[4*BB];             // (m, Z)
static __device__ float g_oseq[BB*TT*HH];
static __device__ uint4 g_oswz[256*32*32];
static __device__ uint2 g_wswz[4000*32*32];
static __device__ float g_partial[(size_t)BB*TT*NTILE];
static __device__ unsigned g_flags[NBLK*FSTR];

static __device__ __forceinline__ uint32_t pk_bf2(float lo, float hi) {
    __nv_bfloat16 l = __float2bfloat16(lo), h = __float2bfloat16(hi);
    return (uint32_t)__bfloat16_as_ushort(l) | ((uint32_t)__bfloat16_as_ushort(h) << 16);
}
static __device__ __forceinline__ void ffma2(ull& acc, ull a, ull b) {
    asm volatile("fma.rn.f32x2 %0, %1, %2, %0;" : "+l"(acc) : "l"(a), "l"(b));
}
static __device__ __forceinline__ float2 u2f(ull v) {
    float2 f; asm("mov.b64 {%0, %1}, %2;" : "=f"(f.x), "=f"(f.y) : "l"(v)); return f;
}
#define PKU(out, lo, hi) asm("mov.b64 %0, {%1, %2};" : "=l"(out) : "f"(lo), "f"(hi))

// flag-array grid barrier: one 128B line per CTA flag, relaxed polls + backoff
static __device__ __forceinline__ void gbar(unsigned tgt) {
    __syncthreads();
    if (threadIdx.x == 0)
        asm volatile("st.release.gpu.global.u32 [%0], %1;"
                     :: "l"(&g_flags[blockIdx.x * FSTR]), "r"(tgt) : "memory");
    if (threadIdx.x < NBLK) {
        const unsigned* fp = &g_flags[threadIdx.x * FSTR];
        unsigned v;
        asm volatile("ld.relaxed.gpu.global.u32 %0, [%1];" : "=r"(v) : "l"(fp) : "memory");
        while (v < tgt) {
            __nanosleep(64);
            asm volatile("ld.relaxed.gpu.global.u32 %0, [%1];" : "=r"(v) : "l"(fp) : "memory");
        }
    }
    asm volatile("fence.acq_rel.gpu;" ::: "memory");
    __syncthreads();
}

// ---------------- prep kernels ----------------
__global__ void kt_init(const float* __restrict__ h0) {
    int i = blockIdx.x * 256 + threadIdx.x;
    if (i < NBLK * FSTR) g_flags[i] = 0;
    if (i < BB * HH) {
        int b = i / HH, j = i % HH;
        g_x[b * K2H + j] = 0.f;
        g_x[b * K2H + HH + j] = h0[i];
    }
}

__global__ void kt_gather(const float* __restrict__ emb, const int* __restrict__ ids) {
    int i = blockIdx.x * 256 + threadIdx.x;
    if (i >= TT * BB * EE) return;
    int e = i % EE; int tb = i / EE; int b = tb % BB; int t = tb / BB;
    int tok = ids[b * (TT + 1) + t];
    g_embseq[(t * BB + b) * EE + e] = emb[tok * EE + e];
}

__global__ void kt_prepack_w(const float* __restrict__ Wv) {
    int i = blockIdx.x * 256 + threadIdx.x;
    if (i >= 4000 * 32 * 32) return;
    int lane = i & 31; int tile = i >> 5;
    int kt = tile & 31; int nrow = tile >> 5;
    int gid = lane >> 2, tg = lane & 3;
    const float* p = Wv + (size_t)(nrow * 8 + gid) * HH + kt * 16 + tg * 2;
    uint2 v; v.x = pk_bf2(p[0], p[1]); v.y = pk_bf2(p[8], p[9]);
    g_wswz[i] = v;
}

__global__ void kt_prepack_o() {
    int i = blockIdx.x * 256 + threadIdx.x;
    if (i >= 256 * 32 * 32) return;
    int lane = i & 31; int tile = i >> 5;
    int kt = tile & 31; int mrow = tile >> 5;
    int gid = lane >> 2, tg = lane & 3;
    const float* p = g_oseq + (size_t)(mrow * 16 + gid) * HH + kt * 16 + tg * 2;
    uint4 v;
    v.x = pk_bf2(p[0], p[1]);
    v.y = pk_bf2(p[8 * HH], p[8 * HH + 1]);
    v.z = pk_bf2(p[8], p[9]);
    v.w = pk_bf2(p[8 * HH + 8], p[8 * HH + 9]);
    g_oswz[i] = v;
}

// ---------------- fp32 GEMM: 128x64 tile, 8x4/thread, f32x2 FMA ----------------
// C[m][n] = sum_k A[m][k]*B[n][k] (+bias). M%128==0, N%64==0, K%16==0.
__global__ void __launch_bounds__(256) kt_gemm_nt(
    const float* __restrict__ A, int lda, const float* __restrict__ Bm, int ldb,
    float* __restrict__ C, int ldc, int K,
    const float* __restrict__ bias0, const float* __restrict__ bias1)
{
    __shared__ float As[16][132];
    __shared__ float Bs[16][68];
    int tid = threadIdx.x;
    int tx = tid & 15, ty = tid >> 4;
    int m0 = blockIdx.y * 128, n0 = blockIdx.x * 64;
    int ar = tid >> 2, alq = tid & 3;

    ull accp[8][2];
#pragma unroll
    for (int i = 0; i < 8; i++) { accp[i][0] = 0ull; accp[i][1] = 0ull; }

    for (int k0 = 0; k0 < K; k0 += 16) {
        float4 a4a = *(const float4*)(A + (size_t)(m0 + ar) * lda + k0 + alq * 4);
        float4 a4b = *(const float4*)(A + (size_t)(m0 + ar + 64) * lda + k0 + alq * 4);
        float4 b4  = *(const float4*)(Bm + (size_t)(n0 + ar) * ldb + k0 + alq * 4);
        As[alq*4+0][ar] = a4a.x; As[alq*4+1][ar] = a4a.y;
        As[alq*4+2][ar] = a4a.z; As[alq*4+3][ar] = a4a.w;
        As[alq*4+0][ar+64] = a4b.x; As[alq*4+1][ar+64] = a4b.y;
        As[alq*4+2][ar+64] = a4b.z; As[alq*4+3][ar+64] = a4b.w;
        Bs[alq*4+0][ar] = b4.x; Bs[alq*4+1][ar] = b4.y;
        Bs[alq*4+2][ar] = b4.z; Bs[alq*4+3][ar] = b4.w;
        __syncthreads();
#pragma unroll
        for (int kk = 0; kk < 16; kk++) {
            float4 av0 = *(const float4*)&As[kk][ty * 8];
            float4 av1 = *(const float4*)&As[kk][ty * 8 + 4];
            float4 bv  = *(const float4*)&Bs[kk][tx * 4];
            ull b01, b23, s;
            PKU(b01, bv.x, bv.y); PKU(b23, bv.z, bv.w);
            PKU(s, av0.x, av0.x); ffma2(accp[0][0], s, b01); ffma2(accp[0][1], s, b23);
            PKU(s, av0.y, av0.y); ffma2(accp[1][0], s, b01); ffma2(accp[1][1], s, b23);
            PKU(s, av0.z, av0.z); ffma2(accp[2][0], s, b01); ffma2(accp[2][1], s, b23);
            PKU(s, av0.w, av0.w); ffma2(accp[3][0], s, b01); ffma2(accp[3][1], s, b23);
            PKU(s, av1.x, av1.x); ffma2(accp[4][0], s, b01); ffma2(accp[4][1], s, b23);
            PKU(s, av1.y, av1.y); ffma2(accp[5][0], s, b01); ffma2(accp[5][1], s, b23);
            PKU(s, av1.z, av1.z); ffma2(accp[6][0], s, b01); ffma2(accp[6][1], s, b23);
            PKU(s, av1.w, av1.w); ffma2(accp[7][0], s, b01); ffma2(accp[7][1], s, b23);
        }
        __syncthreads();
    }
    float bb[4];
#pragma unroll
    for (int j = 0; j < 4; j++) {
        int n = n0 + tx * 4 + j;
        bb[j] = (bias0 ? bias0[n] : 0.f) + (bias1 ? bias1[n] : 0.f);
    }
#pragma unroll
    for (int i = 0; i < 8; i++) {
        float2 lo = u2f(accp[i][0]), hi = u2f(accp[i][1]);
        float4 o4 = { lo.x + bb[0], lo.y + bb[1], hi.x + bb[2], hi.y + bb[3] };
        *(float4*)(C + (size_t)(m0 + ty * 8 + i) * ldc + n0 + tx * 4) = o4;
    }
}

// =================== persistent scan (512 threads) ===================
// CTA c owns j in [4c, 4c+4): 16 gate rows (4 types x 4 j), cell state in smem.
// smem (bytes): wg f2[16*513]@0 (65664) | wdh f[4*520]@65664 (8320) |
//   stage f[32*1034]@73984 (132352) | cs f[128]@206336 | mbias f[32]@206848
// aliases inside stage (float offsets): red16@0 [16*520], gsum@8320 [16*33];
//   phaseB: hs@0[512], sc@512[32], es@576[32]; phaseC: hrows [32*520], red2@16640[512]
#define XSTR 1034
#define CSTR 520
#define SM_WDH 65664
#define SM_ST  73984
#define SM_CS  206336
#define SM_MB  206848
#define SMEM_SCAN 207104

__global__ void __launch_bounds__(512) kt_scan(
    const int* __restrict__ mask,
    const float* __restrict__ Wih, const float* __restrict__ Whh,
    const float* __restrict__ Wdec, const float* __restrict__ bdec,
    const float* __restrict__ c0)
{
    extern __shared__ char smem[];
    float2* wg    = (float2*)smem;                 // [16][513]
    float*  wdh   = (float*)(smem + SM_WDH);       // [4][520]
    float*  stage = (float*)(smem + SM_ST);        // [32][XSTR] + aliases
    float*  cs    = (float*)(smem + SM_CS);        // [128] persistent cell state
    float*  mbias = (float*)(smem + SM_MB);        // [32]

    int c = blockIdx.x, tid = threadIdx.x;
    int bB = c & 31, qB = c >> 5;

    // stationary gate weights: local row r = type*4 + jj  ->  global g = type*512 + c*4 + jj
    for (int idx = tid; idx < 16 * 512; idx += 512) {
        int r = idx >> 9, kp = idx & 511;
        int type = r >> 2, jj = r & 3;
        int g = type * 512 + c * 4 + jj;
        int k = kp * 2;
        float a, b2;
        if (k < 512) { a = Wih[g * 768 + 256 + k]; b2 = Wih[g * 768 + 257 + k]; }
        else         { a = Whh[g * 512 + k - 512]; b2 = Whh[g * 512 + k - 511]; }
        wg[r * 513 + kp] = make_float2(a, b2);
    }
    for (int idx = tid; idx < 4 * 512; idx += 512) {
        int jl = idx >> 9, k = idx & 511;
        wdh[jl * CSTR + k] = Wdec[(size_t)(c * 4 + jl) * 1536 + 1024 + k];
    }
    if (tid < 32)
        mbias[tid] = (mask[bB * SSRC + qB * 32 + tid] > 0) ? 0.f : -1e9f;
    if (tid < 128)
        cs[tid] = c0[(tid >> 2) * HH + c * 4 + (tid & 3)];

    unsigned tgt = 0;
    __syncthreads();

    int ks = tid >> 5, gt = (tid >> 3) & 3, bt = tid & 7;   // phase A roles

    for (int t = 0; t < TT; t++) {
        // ======== phase A: gates (16 rows x 32 b) + cell update ========
        {
            const float2* gx2 = (const float2*)g_x;
            for (int idx = tid; idx < 32 * 512; idx += 512) {
                int b = idx >> 9, kp = idx & 511;
                *(float2*)(stage + b * XSTR + kp * 2) = gx2[b * 512 + kp];
            }
            float gy0 = 0, gy1 = 0, gy2 = 0, gy3 = 0;
            if (tid < 128) {
                int b = tid >> 2, jj = tid & 3;
                const float* gy = g_gatesy + (size_t)(t * BB + b) * G4 + c * 4 + jj;
                gy0 = gy[0]; gy1 = gy[512]; gy2 = gy[1024]; gy3 = gy[1536];
            }
            __syncthreads();

            const ull* w0 = (const ull*)(wg + (gt*4+0)*513) + ks*32;
            const ull* w1 = (const ull*)(wg + (gt*4+1)*513) + ks*32;
            const ull* w2 = (const ull*)(wg + (gt*4+2)*513) + ks*32;
            const ull* w3 = (const ull*)(wg + (gt*4+3)*513) + ks*32;
            const ull* x0 = (const ull*)(stage + (bt*4+0)*XSTR) + ks*32;
            const ull* x1 = (const ull*)(stage + (bt*4+1)*XSTR) + ks*32;
            const ull* x2 = (const ull*)(stage + (bt*4+2)*XSTR) + ks*32;
            const ull* x3 = (const ull*)(stage + (bt*4+3)*XSTR) + ks*32;
            ull a00=0,a01=0,a02=0,a03=0, a10=0,a11=0,a12=0,a13=0;
            ull a20=0,a21=0,a22=0,a23=0, a30=0,a31=0,a32=0,a33=0;
#pragma unroll 4
            for (int kp = 0; kp < 32; kp++) {
                ull wa=w0[kp], wb=w1[kp], wc=w2[kp], wd=w3[kp];
                ull xa=x0[kp], xb=x1[kp], xc=x2[kp], xd=x3[kp];
                ffma2(a00,wa,xa); ffma2(a01,wa,xb); ffma2(a02,wa,xc); ffma2(a03,wa,xd);
                ffma2(a10,wb,xa); ffma2(a11,wb,xb); ffma2(a12,wb,xc); ffma2(a13,wb,xd);
                ffma2(a20,wc,xa); ffma2(a21,wc,xb); ffma2(a22,wc,xc); ffma2(a23,wc,xd);
                ffma2(a30,wd,xa); ffma2(a31,wd,xb); ffma2(a32,wd,xc); ffma2(a33,wd,xd);
            }
            __syncthreads();   // stage reads done; alias red16/gsum into stage
            float* red16 = stage;
            float* gsum  = stage + 8320;
#define RSUM(v) ({ float2 f_ = u2f(v); f_.x + f_.y; })
            {
                float4 r0 = { RSUM(a00), RSUM(a01), RSUM(a02), RSUM(a03) };
                float4 r1 = { RSUM(a10), RSUM(a11), RSUM(a12), RSUM(a13) };
                float4 r2 = { RSUM(a20), RSUM(a21), RSUM(a22), RSUM(a23) };
                float4 r3 = { RSUM(a30), RSUM(a31), RSUM(a32), RSUM(a33) };
                *(float4*)(red16 + ks*520 + (gt*4+0)*32 + bt*4) = r0;
                *(float4*)(red16 + ks*520 + (gt*4+1)*32 + bt*4) = r1;
                *(float4*)(red16 + ks*520 + (gt*4+2)*32 + bt*4) = r2;
                *(float4*)(red16 + ks*520 + (gt*4+3)*32 + bt*4) = r3;
            }
#undef RSUM
            __syncthreads();
            {
                int r = tid >> 5, b = tid & 31;
                float s = 0.f;
#pragma unroll
                for (int q = 0; q < 16; q++) s += red16[q*520 + r*32 + b];
                gsum[r * 33 + b] = s;
            }
            __syncthreads();
            if (tid < 128) {
                int b = tid >> 2, jj = tid & 3;
                float vi = gsum[jj * 33 + b]        + gy0;
                float vf = gsum[(4 + jj) * 33 + b]  + gy1;
                float vg = gsum[(8 + jj) * 33 + b]  + gy2;
                float vo = gsum[(12 + jj) * 33 + b] + gy3;
                float cc = cs[tid];
                float ig = 1.f / (1.f + __expf(-vi));
                float fg = 1.f / (1.f + __expf(-vf));
                float gg = tanhf(vg);
                float og = 1.f / (1.f + __expf(-vo));
                float cn = fg * cc + ig * gg;
                float hn = og * tanhf(cn);
                cs[tid] = cn;
                g_x[b * K2H + HH + c * 4 + jj] = hn;
            }
        }
        gbar(++tgt);

        // ======== phase B: scores + split-softmax + partial ctx (CTA = qB x bB) ========
        {
            float* hs = stage;
            float* sc = stage + 512;
            float* es = stage + 576;
            hs[tid] = g_x[bB * K2H + HH + tid];
            __syncthreads();

            int w = tid >> 5, lane = tid & 31;
            float4 hreg[4];
#pragma unroll
            for (int p = 0; p < 4; p++)
                hreg[p] = *(const float4*)(hs + (lane + p * 32) * 4);
#pragma unroll
            for (int si = 0; si < 2; si++) {
                int sl = w * 2 + si;
                const float4* kp = (const float4*)(g_keys +
                    ((size_t)bB * SSRC + qB * 32 + sl) * HH);
                float acc = 0.f;
#pragma unroll
                for (int p = 0; p < 4; p++) {
                    float4 kv = kp[lane + p * 32];
                    acc += hreg[p].x*kv.x + hreg[p].y*kv.y + hreg[p].z*kv.z + hreg[p].w*kv.w;
                }
#pragma unroll
                for (int off = 16; off; off >>= 1)
                    acc += __shfl_down_sync(0xffffffffu, acc, off);
                if (lane == 0) sc[sl] = acc + mbias[sl];
            }
            __syncthreads();

            if (tid < 32) {
                float v = sc[tid];
                float m = v;
#pragma unroll
                for (int off = 16; off; off >>= 1)
                    m = fmaxf(m, __shfl_xor_sync(0xffffffffu, m, off));
                float e = __expf(v - m);
                es[tid] = e;
                float Z = e;
#pragma unroll
                for (int off = 16; off; off >>= 1)
                    Z += __shfl_xor_sync(0xffffffffu, Z, off);
                if (tid == 0) g_bstats[qB * 32 + bB] = make_float2(m, Z);
            }
            __syncthreads();

            {
                int j = tid;
                const float* ed = g_encdec + ((size_t)bB * SSRC + qB * 32) * HH;
                float p = 0.f;
#pragma unroll 8
                for (int s = 0; s < 32; s++) p += es[s] * ed[(size_t)s * HH + j];
                g_pctx[(qB * 32 + bB) * HH + j] = p;
            }
        }
        gbar(++tgt);

        // ======== phase C: combine + Wdh.h + tanh -> o ========
        {
            for (int idx = tid; idx < 32 * 128; idx += 512) {
                int b = idx >> 7, k4 = idx & 127;
                *(float4*)(stage + b * CSTR + k4 * 4) =
                    *(const float4*)(g_x + b * K2H + HH + k4 * 4);
            }
            __syncthreads();
            float* red2 = stage + 16640;
            {
                int kk = tid >> 7, cell = tid & 127, bC = cell >> 2, jl = cell & 3;
                const float4* wp = (const float4*)(wdh + jl * CSTR + kk * 128);
                const float4* hp = (const float4*)(stage + bC * CSTR + kk * 128);
                float acc = 0.f;
#pragma unroll 8
                for (int k4 = 0; k4 < 32; k4++) {
                    float4 wv = wp[k4], hv = hp[k4];
                    acc += wv.x*hv.x + wv.y*hv.y + wv.z*hv.z + wv.w*hv.w;
                }
                red2[kk * 128 + cell] = acc;
            }
            __syncthreads();
            if (tid < 128) {
                float wsum = red2[tid] + red2[128 + tid] + red2[256 + tid] + red2[384 + tid];
                int b = tid >> 2, jl = tid & 3, j = c * 4 + jl;
                float2 st0 = g_bstats[b], st1 = g_bstats[32 + b];
                float2 st2 = g_bstats[64 + b], st3 = g_bstats[96 + b];
                float M = fmaxf(fmaxf(st0.x, st1.x), fmaxf(st2.x, st3.x));
                float w0 = __expf(st0.x - M), w1 = __expf(st1.x - M);
                float w2 = __expf(st2.x - M), w3 = __expf(st3.x - M);
                float den = st0.y*w0 + st1.y*w1 + st2.y*w2 + st3.y*w3;
                float num = w0 * g_pctx[(0*32+b)*HH + j] + w1 * g_pctx[(1*32+b)*HH + j]
                          + w2 * g_pctx[(2*32+b)*HH + j] + w3 * g_pctx[(3*32+b)*HH + j];
                float o = tanhf(num / den + wsum + bdec[j]);
                g_x[b * K2H + j] = o;
                g_oseq[((size_t)b * TT + t) * HH + j] = o;
            }
        }
        gbar(++tgt);
    }
}

// ---------------- vocab GEMM + fused sum-exp partials ----------------
#define MMA16816(d0,d1,d2,d3,A0,A1,A2,A3,B0,B1) \
    asm volatile("mma.sync.aligned.m16n8k16.row.col.f32.bf16.bf16.f32 " \
        "{%0,%1,%2,%3}, {%4,%5,%6,%7}, {%8,%9}, {%0,%1,%2,%3};" \
        : "+f"(d0), "+f"(d1), "+f"(d2), "+f"(d3) \
        : "r"(A0), "r"(A1), "r"(A2), "r"(A3), "r"(B0), "r"(B1))

__global__ void __launch_bounds__(256) kt_vocab_gemm(
    float* __restrict__ out, const float* __restrict__ bvocab)
{
    int nb = blockIdx.x, mb = blockIdx.y;
    int wid = threadIdx.x >> 5, lane = threadIdx.x & 31;
    int wm = wid >> 2, wn = wid & 3;
    int gid = lane >> 2, tg = lane & 3;

    __shared__ float rowsum[128][4];
    if (threadIdx.x < 128) {
#pragma unroll
        for (int w = 0; w < 4; w++) rowsum[threadIdx.x][w] = 0.f;
    }
    __syncthreads();

    float acc[4][4][4];
#pragma unroll
    for (int i = 0; i < 4; i++)
#pragma unroll
        for (int j = 0; j < 4; j++)
#pragma unroll
            for (int r = 0; r < 4; r++) acc[i][j][r] = 0.f;

    int mrow0 = mb * 8 + wm * 4;
    int nrow0 = nb * 16 + wn * 4;

#pragma unroll 2
    for (int kt = 0; kt < 32; kt++) {
        uint4 af[4];
        uint2 bf[4];
#pragma unroll
        for (int mt = 0; mt < 4; mt++)
            af[mt] = g_oswz[(((mrow0 + mt) * 32 + kt) << 5) + lane];
#pragma unroll
        for (int nt = 0; nt < 4; nt++)
            bf[nt] = g_wswz[(((size_t)(nrow0 + nt) * 32 + kt) << 5) + lane];
#pragma unroll
        for (int mt = 0; mt < 4; mt++)
#pragma unroll
            for (int nt = 0; nt < 4; nt++)
                MMA16816(acc[mt][nt][0], acc[mt][nt][1], acc[mt][nt][2], acc[mt][nt][3],
                         af[mt].x, af[mt].y, af[mt].z, af[mt].w, bf[nt].x, bf[nt].y);
    }

    int m_warp = mb * 128 + wm * 64;
    int n_warp = nb * 128 + wn * 32;
#pragma unroll
    for (int mt = 0; mt < 4; mt++) {
        float s0 = 0.f, s1 = 0.f;
#pragma unroll
        for (int nt = 0; nt < 4; nt++) {
            int r = m_warp + mt * 16 + gid;
            int ci = n_warp + nt * 8 + tg * 2;
            float bv0 = bvocab[ci], bv1 = bvocab[ci + 1];
            float v00 = acc[mt][nt][0] + bv0, v01 = acc[mt][nt][1] + bv1;
            float v10 = acc[mt][nt][2] + bv0, v11 = acc[mt][nt][3] + bv1;
            float2 w0 = { v00, v01 }, w1 = { v10, v11 };
            *reinterpret_cast<float2*>(out + (size_t)r * VV + ci) = w0;
            *reinterpret_cast<float2*>(out + (size_t)(r + 8) * VV + ci) = w1;
            s0 += __expf(v00) + __expf(v01);
            s1 += __expf(v10) + __expf(v11);
        }
        s0 += __shfl_xor_sync(0xffffffffu, s0, 1);
        s0 += __shfl_xor_sync(0xffffffffu, s0, 2);
        s1 += __shfl_xor_sync(0xffffffffu, s1, 1);
        s1 += __shfl_xor_sync(0xffffffffu, s1, 2);
        if (tg == 0) {
            rowsum[wm * 64 + mt * 16 + gid][wn] = s0;
            rowsum[wm * 64 + mt * 16 + gid + 8][wn] = s1;
        }
    }
    __syncthreads();
    if (threadIdx.x < 128) {
        float p = rowsum[threadIdx.x][0] + rowsum[threadIdx.x][1]
                + rowsum[threadIdx.x][2] + rowsum[threadIdx.x][3];
        g_partial[(size_t)(mb * 128 + threadIdx.x) * NTILE + nb] = p;
    }
}

__global__ void __launch_bounds__(256) kt_lsfinal(float* __restrict__ out) {
    int row = blockIdx.x, tid = threadIdx.x;
    __shared__ float red[256];
    __shared__ float lse_s;
    float s = 0.f;
    for (int i = tid; i < NTILE; i += 256) s += g_partial[(size_t)row * NTILE + i];
    red[tid] = s;
    __syncthreads();
#pragma unroll
    for (int off = 128; off; off >>= 1) {
        if (tid < off) red[tid] += red[tid + off];
        __syncthreads();
    }
    if (tid == 0) lse_s = logf(red[0]);
    __syncthreads();
    float lse = lse_s;
    float* p = out + (size_t)row * VV;
    for (int i = tid * 4; i < VV; i += 256 * 4) {
        float4 v = *reinterpret_cast<float4*>(p + i);
        v.x -= lse; v.y -= lse; v.z -= lse; v.w -= lse;
        *reinterpret_cast<float4*>(p + i) = v;
    }
}

// ---------------- launch ----------------
extern "C" void kernel_launch(void* const* d_in, const int* in_sizes, int n_in,
                              void* d_out, int out_size)
{
    const float* enc     = (const float*)d_in[0];
    const int*   mask    = (const int*)  d_in[1];
    const int*   ids     = (const int*)  d_in[2];
    const float* h0      = (const float*)d_in[3];
    const float* c0      = (const float*)d_in[4];
    const float* emb     = (const float*)d_in[5];
    const float* W_ih    = (const float*)d_in[6];
    const float* b_ih    = (const float*)d_in[7];
    const float* W_hh    = (const float*)d_in[8];
    const float* b_hh    = (const float*)d_in[9];
    const float* W_att   = (const float*)d_in[10];
    const float* W_dec   = (const float*)d_in[11];
    const float* b_dec   = (const float*)d_in[12];
    const float* W_vocab = (const float*)d_in[13];
    const float* b_vocab = (const float*)d_in[14];
    float* out = (float*)d_out;

    cudaFuncSetAttribute(kt_scan, cudaFuncAttributeMaxDynamicSharedMemorySize, SMEM_SCAN);

    kt_init<<<(BB*HH + 255)/256, 256>>>(h0);
    kt_gather<<<(TT*BB*EE + 255)/256, 256>>>(emb, ids);

    {
        float* keysp; cudaGetSymbolAddress((void**)&keysp, g_keys);
        float* edp;   cudaGetSymbolAddress((void**)&edp, g_encdec);
        float* embp;  cudaGetSymbolAddress((void**)&embp, g_embseq);
        float* gyp;   cudaGetSymbolAddress((void**)&gyp, g_gatesy);
        // keys = enc @ W_att^T : M=4096 N=512 K=1024
        kt_gemm_nt<<<dim3(8, 32), 256>>>(enc, K2H, W_att, K2H, keysp, HH, K2H, nullptr, nullptr);
        // encdec = enc @ W_dec[:, :1024]^T : M=4096 N=512 K=1024 (ldb=1536)
        kt_gemm_nt<<<dim3(8, 32), 256>>>(enc, K2H, W_dec, 1536, edp, HH, K2H, nullptr, nullptr);
        // gates_y = emb_seq @ W_ih[:, :256]^T + b_ih + b_hh : M=4096 N=2048 K=256
        kt_gemm_nt<<<dim3(32, 32), 256>>>(embp, EE, W_ih, 768, gyp, G4, EE, b_ih, b_hh);
    }

    kt_scan<<<NBLK, 512, SMEM_SCAN>>>(mask, W_ih, W_hh, W_dec, b_dec, c0);

    kt_prepack_w<<<(4000*32*32 + 255)/256, 256>>>(W_vocab);
    kt_prepack_o<<<(256*32*32 + 255)/256, 256>>>();
    kt_vocab_gemm<<<dim3(NTILE, (BB*TT)/128), 256>>>(out, b_vocab);
    kt_lsfinal<<<BB*TT, 256>>>(out);
}

// round 14
// speedup vs baseline: 3.1647x; 1.0970x over previous
#include <cuda_runtime.h>
#include <cuda_bf16.h>
#include <cstdint>
#include <math.h>

#define BB 32
#define TT 128
#define SSRC 128
#define HH 512
#define EE 256
#define VV 32000
#define K2H 1024
#define G4 2048
#define NBLK 128
#define NTILE 250
#define FSTR 32

typedef unsigned long long ull;

// ---------------- device scratch ----------------
static __device__ float g_keys[BB*SSRC*HH];
static __device__ float g_encdec[BB*SSRC*HH];        // [b][s][j]
static __device__ float g_gatesy[TT*BB*G4];
static __device__ float g_embseq[TT*BB*EE];
static __device__ float g_x[BB*K2H];                 // [o(512), h(512)]
static __device__ float g_pctx[4*BB*HH];             // [q][b][j]
static __device__ float2 g_bstats[4*BB];             // (m, Z)
static __device__ float g_oseq[BB*TT*HH];
static __device__ uint4 g_oswz[256*32*32];
static __device__ uint2 g_wswz[4000*32*32];
static __device__ float g_partial[(size_t)BB*TT*NTILE];
static __device__ unsigned g_flags[NBLK*FSTR];

static __device__ __forceinline__ uint32_t pk_bf2(float lo, float hi) {
    __nv_bfloat16 l = __float2bfloat16(lo), h = __float2bfloat16(hi);
    return (uint32_t)__bfloat16_as_ushort(l) | ((uint32_t)__bfloat16_as_ushort(h) << 16);
}
static __device__ __forceinline__ void ffma2(ull& acc, ull a, ull b) {
    asm volatile("fma.rn.f32x2 %0, %1, %2, %0;" : "+l"(acc) : "l"(a), "l"(b));
}
static __device__ __forceinline__ float2 u2f(ull v) {
    float2 f; asm("mov.b64 {%0, %1}, %2;" : "=f"(f.x), "=f"(f.y) : "l"(v)); return f;
}
#define PKU(out, lo, hi) asm("mov.b64 %0, {%1, %2};" : "=l"(out) : "f"(lo), "f"(hi))

// flag-array grid barrier: one 128B line per flag, relaxed spin + single acquire
static __device__ __forceinline__ void gbar(unsigned tgt) {
    __syncthreads();
    if (threadIdx.x == 0)
        asm volatile("st.release.gpu.global.u32 [%0], %1;"
                     :: "l"(&g_flags[blockIdx.x * FSTR]), "r"(tgt) : "memory");
    if (threadIdx.x < NBLK) {
        const unsigned* fp = &g_flags[threadIdx.x * FSTR];
        unsigned v;
        asm volatile("ld.relaxed.gpu.global.u32 %0, [%1];" : "=r"(v) : "l"(fp) : "memory");
        while (v < tgt) {
            __nanosleep(32);
            asm volatile("ld.relaxed.gpu.global.u32 %0, [%1];" : "=r"(v) : "l"(fp) : "memory");
        }
        asm volatile("ld.acquire.gpu.global.u32 %0, [%1];" : "=r"(v) : "l"(fp) : "memory");
    }
    __syncthreads();
}

// ---------------- prep kernels ----------------
__global__ void kt_init(const float* __restrict__ h0) {
    int i = blockIdx.x * 256 + threadIdx.x;
    if (i < NBLK * FSTR) g_flags[i] = 0;
    if (i < BB * HH) {
        int b = i / HH, j = i % HH;
        g_x[b * K2H + j] = 0.f;
        g_x[b * K2H + HH + j] = h0[i];
    }
}

__global__ void kt_gather(const float* __restrict__ emb, const int* __restrict__ ids) {
    int i = blockIdx.x * 256 + threadIdx.x;
    if (i >= TT * BB * EE) return;
    int e = i % EE; int tb = i / EE; int b = tb % BB; int t = tb / BB;
    int tok = ids[b * (TT + 1) + t];
    g_embseq[(t * BB + b) * EE + e] = emb[tok * EE + e];
}

__global__ void kt_prepack_w(const float* __restrict__ Wv) {
    int i = blockIdx.x * 256 + threadIdx.x;
    if (i >= 4000 * 32 * 32) return;
    int lane = i & 31; int tile = i >> 5;
    int kt = tile & 31; int nrow = tile >> 5;
    int gid = lane >> 2, tg = lane & 3;
    const float* p = Wv + (size_t)(nrow * 8 + gid) * HH + kt * 16 + tg * 2;
    uint2 v; v.x = pk_bf2(p[0], p[1]); v.y = pk_bf2(p[8], p[9]);
    g_wswz[i] = v;
}

__global__ void kt_prepack_o() {
    int i = blockIdx.x * 256 + threadIdx.x;
    if (i >= 256 * 32 * 32) return;
    int lane = i & 31; int tile = i >> 5;
    int kt = tile & 31; int mrow = tile >> 5;
    int gid = lane >> 2, tg = lane & 3;
    const float* p = g_oseq + (size_t)(mrow * 16 + gid) * HH + kt * 16 + tg * 2;
    uint4 v;
    v.x = pk_bf2(p[0], p[1]);
    v.y = pk_bf2(p[8 * HH], p[8 * HH + 1]);
    v.z = pk_bf2(p[8], p[9]);
    v.w = pk_bf2(p[8 * HH + 8], p[8 * HH + 9]);
    g_oswz[i] = v;
}

// ---------------- fp32 GEMM: 128x64 tile, 8x4/thread, f32x2 FMA ----------------
__global__ void __launch_bounds__(256) kt_gemm_nt(
    const float* __restrict__ A, int lda, const float* __restrict__ Bm, int ldb,
    float* __restrict__ C, int ldc, int K,
    const float* __restrict__ bias0, const float* __restrict__ bias1)
{
    __shared__ float As[16][132];
    __shared__ float Bs[16][68];
    int tid = threadIdx.x;
    int tx = tid & 15, ty = tid >> 4;
    int m0 = blockIdx.y * 128, n0 = blockIdx.x * 64;
    int ar = tid >> 2, alq = tid & 3;

    ull accp[8][2];
#pragma unroll
    for (int i = 0; i < 8; i++) { accp[i][0] = 0ull; accp[i][1] = 0ull; }

    for (int k0 = 0; k0 < K; k0 += 16) {
        float4 a4a = *(const float4*)(A + (size_t)(m0 + ar) * lda + k0 + alq * 4);
        float4 a4b = *(const float4*)(A + (size_t)(m0 + ar + 64) * lda + k0 + alq * 4);
        float4 b4  = *(const float4*)(Bm + (size_t)(n0 + ar) * ldb + k0 + alq * 4);
        As[alq*4+0][ar] = a4a.x; As[alq*4+1][ar] = a4a.y;
        As[alq*4+2][ar] = a4a.z; As[alq*4+3][ar] = a4a.w;
        As[alq*4+0][ar+64] = a4b.x; As[alq*4+1][ar+64] = a4b.y;
        As[alq*4+2][ar+64] = a4b.z; As[alq*4+3][ar+64] = a4b.w;
        Bs[alq*4+0][ar] = b4.x; Bs[alq*4+1][ar] = b4.y;
        Bs[alq*4+2][ar] = b4.z; Bs[alq*4+3][ar] = b4.w;
        __syncthreads();
#pragma unroll
        for (int kk = 0; kk < 16; kk++) {
            float4 av0 = *(const float4*)&As[kk][ty * 8];
            float4 av1 = *(const float4*)&As[kk][ty * 8 + 4];
            float4 bv  = *(const float4*)&Bs[kk][tx * 4];
            ull b01, b23, s;
            PKU(b01, bv.x, bv.y); PKU(b23, bv.z, bv.w);
            PKU(s, av0.x, av0.x); ffma2(accp[0][0], s, b01); ffma2(accp[0][1], s, b23);
            PKU(s, av0.y, av0.y); ffma2(accp[1][0], s, b01); ffma2(accp[1][1], s, b23);
            PKU(s, av0.z, av0.z); ffma2(accp[2][0], s, b01); ffma2(accp[2][1], s, b23);
            PKU(s, av0.w, av0.w); ffma2(accp[3][0], s, b01); ffma2(accp[3][1], s, b23);
            PKU(s, av1.x, av1.x); ffma2(accp[4][0], s, b01); ffma2(accp[4][1], s, b23);
            PKU(s, av1.y, av1.y); ffma2(accp[5][0], s, b01); ffma2(accp[5][1], s, b23);
            PKU(s, av1.z, av1.z); ffma2(accp[6][0], s, b01); ffma2(accp[6][1], s, b23);
            PKU(s, av1.w, av1.w); ffma2(accp[7][0], s, b01); ffma2(accp[7][1], s, b23);
        }
        __syncthreads();
    }
    float bb[4];
#pragma unroll
    for (int j = 0; j < 4; j++) {
        int n = n0 + tx * 4 + j;
        bb[j] = (bias0 ? bias0[n] : 0.f) + (bias1 ? bias1[n] : 0.f);
    }
#pragma unroll
    for (int i = 0; i < 8; i++) {
        float2 lo = u2f(accp[i][0]), hi = u2f(accp[i][1]);
        float4 o4 = { lo.x + bb[0], lo.y + bb[1], hi.x + bb[2], hi.y + bb[3] };
        *(float4*)(C + (size_t)(m0 + ty * 8 + i) * ldc + n0 + tx * 4) = o4;
    }
}

// =================== persistent scan (512 threads, slim smem) ===================
// CTA c owns j in [4c, 4c+4). Cell state in smem. Phase A stages x in 2 halves
// (512 floats = 256 ull per row per half; 16 k-splits x 16 ull each).
// smem (bytes): wg f2[16*513]@0 (65664) | wdh f[4*520]@65664 (8320) |
//   stage f[17024]@73984 (68096) | cs f[128]@142080 | mbias f[32]@142592
#define HSTR 514
#define CSTR 516
#define SM_WDH 65664
#define SM_ST  73984
#define SM_CS  142080
#define SM_MB  142592
#define SMEM_SCAN 142720

__global__ void __launch_bounds__(512) kt_scan(
    const int* __restrict__ mask,
    const float* __restrict__ Wih, const float* __restrict__ Whh,
    const float* __restrict__ Wdec, const float* __restrict__ bdec,
    const float* __restrict__ c0)
{
    extern __shared__ char smem[];
    float2* wg    = (float2*)smem;                 // [16][513]
    float*  wdh   = (float*)(smem + SM_WDH);       // [4][520]
    float*  stage = (float*)(smem + SM_ST);        // aliases
    float*  cs    = (float*)(smem + SM_CS);        // [128] cell state
    float*  mbias = (float*)(smem + SM_MB);        // [32]

    int c = blockIdx.x, tid = threadIdx.x;
    int bB = c & 31, qB = c >> 5;

    // stationary gate weights: local row r = type*4 + jj -> global g = type*512 + c*4 + jj
    for (int idx = tid; idx < 16 * 512; idx += 512) {
        int r = idx >> 9, kp = idx & 511;
        int type = r >> 2, jj = r & 3;
        int g = type * 512 + c * 4 + jj;
        int k = kp * 2;
        float a, b2;
        if (k < 512) { a = Wih[g * 768 + 256 + k]; b2 = Wih[g * 768 + 257 + k]; }
        else         { a = Whh[g * 512 + k - 512]; b2 = Whh[g * 512 + k - 511]; }
        wg[r * 513 + kp] = make_float2(a, b2);
    }
    for (int idx = tid; idx < 4 * 512; idx += 512) {
        int jl = idx >> 9, k = idx & 511;
        wdh[jl * 520 + k] = Wdec[(size_t)(c * 4 + jl) * 1536 + 1024 + k];
    }
    if (tid < 32)
        mbias[tid] = (mask[bB * SSRC + qB * 32 + tid] > 0) ? 0.f : -1e9f;
    if (tid < 128)
        cs[tid] = c0[(tid >> 2) * HH + c * 4 + (tid & 3)];

    unsigned tgt = 0;
    __syncthreads();

    int ks = tid >> 5, gt = (tid >> 3) & 3, bt = tid & 7;   // phase A roles

    for (int t = 0; t < TT; t++) {
        // ======== phase A: gates (16 rows x 32 b) + cell update, x staged in halves ====
        {
            float gy0 = 0, gy1 = 0, gy2 = 0, gy3 = 0;
            if (tid < 128) {
                int b = tid >> 2, jj = tid & 3;
                const float* gy = g_gatesy + (size_t)(t * BB + b) * G4 + c * 4 + jj;
                gy0 = gy[0]; gy1 = gy[512]; gy2 = gy[1024]; gy3 = gy[1536];
            }
            ull a00=0,a01=0,a02=0,a03=0, a10=0,a11=0,a12=0,a13=0;
            ull a20=0,a21=0,a22=0,a23=0, a30=0,a31=0,a32=0,a33=0;
            const float2* gx2 = (const float2*)g_x;
#pragma unroll
            for (int half = 0; half < 2; half++) {
                for (int idx = tid; idx < 32 * 256; idx += 512) {
                    int b = idx >> 8, kp = idx & 255;
                    *(float2*)(stage + b * HSTR + kp * 2) = gx2[b * 512 + half * 256 + kp];
                }
                __syncthreads();
                const ull* w0 = (const ull*)(wg + (gt*4+0)*513) + half*256 + ks*16;
                const ull* w1 = (const ull*)(wg + (gt*4+1)*513) + half*256 + ks*16;
                const ull* w2 = (const ull*)(wg + (gt*4+2)*513) + half*256 + ks*16;
                const ull* w3 = (const ull*)(wg + (gt*4+3)*513) + half*256 + ks*16;
                const ull* x0 = (const ull*)(stage + (bt*4+0)*HSTR) + ks*16;
                const ull* x1 = (const ull*)(stage + (bt*4+1)*HSTR) + ks*16;
                const ull* x2 = (const ull*)(stage + (bt*4+2)*HSTR) + ks*16;
                const ull* x3 = (const ull*)(stage + (bt*4+3)*HSTR) + ks*16;
#pragma unroll
                for (int kp = 0; kp < 16; kp++) {
                    ull wa=w0[kp], wb=w1[kp], wc=w2[kp], wd=w3[kp];
                    ull xa=x0[kp], xb=x1[kp], xc=x2[kp], xd=x3[kp];
                    ffma2(a00,wa,xa); ffma2(a01,wa,xb); ffma2(a02,wa,xc); ffma2(a03,wa,xd);
                    ffma2(a10,wb,xa); ffma2(a11,wb,xb); ffma2(a12,wb,xc); ffma2(a13,wb,xd);
                    ffma2(a20,wc,xa); ffma2(a21,wc,xb); ffma2(a22,wc,xc); ffma2(a23,wc,xd);
                    ffma2(a30,wd,xa); ffma2(a31,wd,xb); ffma2(a32,wd,xc); ffma2(a33,wd,xd);
                }
                __syncthreads();
            }
            float* red16 = stage;
            float* gsum  = stage + 8320;
#define RSUM(v) ({ float2 f_ = u2f(v); f_.x + f_.y; })
            {
                float4 r0 = { RSUM(a00), RSUM(a01), RSUM(a02), RSUM(a03) };
                float4 r1 = { RSUM(a10), RSUM(a11), RSUM(a12), RSUM(a13) };
                float4 r2 = { RSUM(a20), RSUM(a21), RSUM(a22), RSUM(a23) };
                float4 r3 = { RSUM(a30), RSUM(a31), RSUM(a32), RSUM(a33) };
                *(float4*)(red16 + ks*520 + (gt*4+0)*32 + bt*4) = r0;
                *(float4*)(red16 + ks*520 + (gt*4+1)*32 + bt*4) = r1;
                *(float4*)(red16 + ks*520 + (gt*4+2)*32 + bt*4) = r2;
                *(float4*)(red16 + ks*520 + (gt*4+3)*32 + bt*4) = r3;
            }
#undef RSUM
            __syncthreads();
            {
                int r = tid >> 5, b = tid & 31;
                float s = 0.f;
#pragma unroll
                for (int q = 0; q < 16; q++) s += red16[q*520 + r*32 + b];
                gsum[r * 33 + b] = s;
            }
            __syncthreads();
            if (tid < 128) {
                int b = tid >> 2, jj = tid & 3;
                float vi = gsum[jj * 33 + b]        + gy0;
                float vf = gsum[(4 + jj) * 33 + b]  + gy1;
                float vg = gsum[(8 + jj) * 33 + b]  + gy2;
                float vo = gsum[(12 + jj) * 33 + b] + gy3;
                float cc = cs[tid];
                float ig = 1.f / (1.f + __expf(-vi));
                float fg = 1.f / (1.f + __expf(-vf));
                float gg = tanhf(vg);
                float og = 1.f / (1.f + __expf(-vo));
                float cn = fg * cc + ig * gg;
                float hn = og * tanhf(cn);
                cs[tid] = cn;
                g_x[b * K2H + HH + c * 4 + jj] = hn;
            }
        }
        gbar(++tgt);

        // ======== phase B: scores + split-softmax + partial ctx (CTA = qB x bB) ========
        {
            float* hs = stage;
            float* sc = stage + 512;
            float* es = stage + 576;
            hs[tid] = g_x[bB * K2H + HH + tid];
            __syncthreads();

            int w = tid >> 5, lane = tid & 31;
            float4 hreg[4];
#pragma unroll
            for (int p = 0; p < 4; p++)
                hreg[p] = *(const float4*)(hs + (lane + p * 32) * 4);
#pragma unroll
            for (int si = 0; si < 2; si++) {
                int sl = w * 2 + si;
                const float4* kp = (const float4*)(g_keys +
                    ((size_t)bB * SSRC + qB * 32 + sl) * HH);
                float acc = 0.f;
#pragma unroll
                for (int p = 0; p < 4; p++) {
                    float4 kv = kp[lane + p * 32];
                    acc += hreg[p].x*kv.x + hreg[p].y*kv.y + hreg[p].z*kv.z + hreg[p].w*kv.w;
                }
#pragma unroll
                for (int off = 16; off; off >>= 1)
                    acc += __shfl_down_sync(0xffffffffu, acc, off);
                if (lane == 0) sc[sl] = acc + mbias[sl];
            }
            __syncthreads();

            if (tid < 32) {
                float v = sc[tid];
                float m = v;
#pragma unroll
                for (int off = 16; off; off >>= 1)
                    m = fmaxf(m, __shfl_xor_sync(0xffffffffu, m, off));
                float e = __expf(v - m);
                es[tid] = e;
                float Z = e;
#pragma unroll
                for (int off = 16; off; off >>= 1)
                    Z += __shfl_xor_sync(0xffffffffu, Z, off);
                if (tid == 0) g_bstats[qB * 32 + bB] = make_float2(m, Z);
            }
            __syncthreads();

            {
                int j = tid;
                const float* ed = g_encdec + ((size_t)bB * SSRC + qB * 32) * HH;
                float p = 0.f;
#pragma unroll 8
                for (int s = 0; s < 32; s++) p += es[s] * ed[(size_t)s * HH + j];
                g_pctx[(qB * 32 + bB) * HH + j] = p;
            }
        }
        gbar(++tgt);

        // ======== phase C: combine + Wdh.h + tanh -> o ========
        {
            for (int idx = tid; idx < 32 * 128; idx += 512) {
                int b = idx >> 7, k4 = idx & 127;
                *(float4*)(stage + b * CSTR + k4 * 4) =
                    *(const float4*)(g_x + b * K2H + HH + k4 * 4);
            }
            __syncthreads();
            float* red2 = stage + 16512;
            {
                int kk = tid >> 7, cell = tid & 127, bC = cell >> 2, jl = cell & 3;
                const float4* wp = (const float4*)(wdh + jl * 520 + kk * 128);
                const float4* hp = (const float4*)(stage + bC * CSTR + kk * 128);
                float acc = 0.f;
#pragma unroll 8
                for (int k4 = 0; k4 < 32; k4++) {
                    float4 wv = wp[k4], hv = hp[k4];
                    acc += wv.x*hv.x + wv.y*hv.y + wv.z*hv.z + wv.w*hv.w;
                }
                red2[kk * 128 + cell] = acc;
            }
            __syncthreads();
            if (tid < 128) {
                float wsum = red2[tid] + red2[128 + tid] + red2[256 + tid] + red2[384 + tid];
                int b = tid >> 2, jl = tid & 3, j = c * 4 + jl;
                float2 st0 = g_bstats[b], st1 = g_bstats[32 + b];
                float2 st2 = g_bstats[64 + b], st3 = g_bstats[96 + b];
                float M = fmaxf(fmaxf(st0.x, st1.x), fmaxf(st2.x, st3.x));
                float w0 = __expf(st0.x - M), w1 = __expf(st1.x - M);
                float w2 = __expf(st2.x - M), w3 = __expf(st3.x - M);
                float den = st0.y*w0 + st1.y*w1 + st2.y*w2 + st3.y*w3;
                float num = w0 * g_pctx[(0*32+b)*HH + j] + w1 * g_pctx[(1*32+b)*HH + j]
                          + w2 * g_pctx[(2*32+b)*HH + j] + w3 * g_pctx[(3*32+b)*HH + j];
                float o = tanhf(num / den + wsum + bdec[j]);
                g_x[b * K2H + j] = o;
                g_oseq[((size_t)b * TT + t) * HH + j] = o;
            }
        }
        gbar(++tgt);
    }
}

// ---------------- vocab GEMM + fused sum-exp partials ----------------
#define MMA16816(d0,d1,d2,d3,A0,A1,A2,A3,B0,B1) \
    asm volatile("mma.sync.aligned.m16n8k16.row.col.f32.bf16.bf16.f32 " \
        "{%0,%1,%2,%3}, {%4,%5,%6,%7}, {%8,%9}, {%0,%1,%2,%3};" \
        : "+f"(d0), "+f"(d1), "+f"(d2), "+f"(d3) \
        : "r"(A0), "r"(A1), "r"(A2), "r"(A3), "r"(B0), "r"(B1))

__global__ void __launch_bounds__(256) kt_vocab_gemm(
    float* __restrict__ out, const float* __restrict__ bvocab)
{
    int nb = blockIdx.x, mb = blockIdx.y;
    int wid = threadIdx.x >> 5, lane = threadIdx.x & 31;
    int wm = wid >> 2, wn = wid & 3;
    int gid = lane >> 2, tg = lane & 3;

    __shared__ float rowsum[128][4];
    if (threadIdx.x < 128) {
#pragma unroll
        for (int w = 0; w < 4; w++) rowsum[threadIdx.x][w] = 0.f;
    }
    __syncthreads();

    float acc[4][4][4];
#pragma unroll
    for (int i = 0; i < 4; i++)
#pragma unroll
        for (int j = 0; j < 4; j++)
#pragma unroll
            for (int r = 0; r < 4; r++) acc[i][j][r] = 0.f;

    int mrow0 = mb * 8 + wm * 4;
    int nrow0 = nb * 16 + wn * 4;

#pragma unroll 2
    for (int kt = 0; kt < 32; kt++) {
        uint4 af[4];
        uint2 bf[4];
#pragma unroll
        for (int mt = 0; mt < 4; mt++)
            af[mt] = g_oswz[(((mrow0 + mt) * 32 + kt) << 5) + lane];
#pragma unroll
        for (int nt = 0; nt < 4; nt++)
            bf[nt] = g_wswz[(((size_t)(nrow0 + nt) * 32 + kt) << 5) + lane];
#pragma unroll
        for (int mt = 0; mt < 4; mt++)
#pragma unroll
            for (int nt = 0; nt < 4; nt++)
                MMA16816(acc[mt][nt][0], acc[mt][nt][1], acc[mt][nt][2], acc[mt][nt][3],
                         af[mt].x, af[mt].y, af[mt].z, af[mt].w, bf[nt].x, bf[nt].y);
    }

    int m_warp = mb * 128 + wm * 64;
    int n_warp = nb * 128 + wn * 32;
#pragma unroll
    for (int mt = 0; mt < 4; mt++) {
        float s0 = 0.f, s1 = 0.f;
#pragma unroll
        for (int nt = 0; nt < 4; nt++) {
            int r = m_warp + mt * 16 + gid;
            int ci = n_warp + nt * 8 + tg * 2;
            float bv0 = bvocab[ci], bv1 = bvocab[ci + 1];
            float v00 = acc[mt][nt][0] + bv0, v01 = acc[mt][nt][1] + bv1;
            float v10 = acc[mt][nt][2] + bv0, v11 = acc[mt][nt][3] + bv1;
            float2 w0 = { v00, v01 }, w1 = { v10, v11 };
            *reinterpret_cast<float2*>(out + (size_t)r * VV + ci) = w0;
            *reinterpret_cast<float2*>(out + (size_t)(r + 8) * VV + ci) = w1;
            s0 += __expf(v00) + __expf(v01);
            s1 += __expf(v10) + __expf(v11);
        }
        s0 += __shfl_xor_sync(0xffffffffu, s0, 1);
        s0 += __shfl_xor_sync(0xffffffffu, s0, 2);
        s1 += __shfl_xor_sync(0xffffffffu, s1, 1);
        s1 += __shfl_xor_sync(0xffffffffu, s1, 2);
        if (tg == 0) {
            rowsum[wm * 64 + mt * 16 + gid][wn] = s0;
            rowsum[wm * 64 + mt * 16 + gid + 8][wn] = s1;
        }
    }
    __syncthreads();
    if (threadIdx.x < 128) {
        float p = rowsum[threadIdx.x][0] + rowsum[threadIdx.x][1]
                + rowsum[threadIdx.x][2] + rowsum[threadIdx.x][3];
        g_partial[(size_t)(mb * 128 + threadIdx.x) * NTILE + nb] = p;
    }
}

__global__ void __launch_bounds__(256) kt_lsfinal(float* __restrict__ out) {
    int row = blockIdx.x, tid = threadIdx.x;
    __shared__ float red[256];
    __shared__ float lse_s;
    float s = 0.f;
    for (int i = tid; i < NTILE; i += 256) s += g_partial[(size_t)row * NTILE + i];
    red[tid] = s;
    __syncthreads();
#pragma unroll
    for (int off = 128; off; off >>= 1) {
        if (tid < off) red[tid] += red[tid + off];
        __syncthreads();
    }
    if (tid == 0) lse_s = logf(red[0]);
    __syncthreads();
    float lse = lse_s;
    float* p = out + (size_t)row * VV;
    for (int i = tid * 4; i < VV; i += 256 * 4) {
        float4 v = *reinterpret_cast<float4*>(p + i);
        v.x -= lse; v.y -= lse; v.z -= lse; v.w -= lse;
        *reinterpret_cast<float4*>(p + i) = v;
    }
}

// ---------------- launch ----------------
extern "C" void kernel_launch(void* const* d_in, const int* in_sizes, int n_in,
                              void* d_out, int out_size)
{
    const float* enc     = (const float*)d_in[0];
    const int*   mask    = (const int*)  d_in[1];
    const int*   ids     = (const int*)  d_in[2];
    const float* h0      = (const float*)d_in[3];
    const float* c0      = (const float*)d_in[4];
    const float* emb     = (const float*)d_in[5];
    const float* W_ih    = (const float*)d_in[6];
    const float* b_ih    = (const float*)d_in[7];
    const float* W_hh    = (const float*)d_in[8];
    const float* b_hh    = (const float*)d_in[9];
    const float* W_att   = (const float*)d_in[10];
    const float* W_dec   = (const float*)d_in[11];
    const float* b_dec   = (const float*)d_in[12];
    const float* W_vocab = (const float*)d_in[13];
    const float* b_vocab = (const float*)d_in[14];
    float* out = (float*)d_out;

    cudaFuncSetAttribute(kt_scan, cudaFuncAttributeMaxDynamicSharedMemorySize, SMEM_SCAN);

    kt_init<<<(BB*HH + 255)/256, 256>>>(h0);
    kt_gather<<<(TT*BB*EE + 255)/256, 256>>>(emb, ids);

    {
        float* keysp; cudaGetSymbolAddress((void**)&keysp, g_keys);
        float* edp;   cudaGetSymbolAddress((void**)&edp, g_encdec);
        float* embp;  cudaGetSymbolAddress((void**)&embp, g_embseq);
        float* gyp;   cudaGetSymbolAddress((void**)&gyp, g_gatesy);
        // keys = enc @ W_att^T : M=4096 N=512 K=1024
        kt_gemm_nt<<<dim3(8, 32), 256>>>(enc, K2H, W_att, K2H, keysp, HH, K2H, nullptr, nullptr);
        // encdec = enc @ W_dec[:, :1024]^T : M=4096 N=512 K=1024 (ldb=1536)
        kt_gemm_nt<<<dim3(8, 32), 256>>>(enc, K2H, W_dec, 1536, edp, HH, K2H, nullptr, nullptr);
        // gates_y = emb_seq @ W_ih[:, :256]^T + b_ih + b_hh : M=4096 N=2048 K=256
        kt_gemm_nt<<<dim3(32, 32), 256>>>(embp, EE, W_ih, 768, gyp, G4, EE, b_ih, b_hh);
    }

    kt_scan<<<NBLK, 512, SMEM_SCAN>>>(mask, W_ih, W_hh, W_dec, b_dec, c0);

    kt_prepack_w<<<(4000*32*32 + 255)/256, 256>>>(W_vocab);
    kt_prepack_o<<<(256*32*32 + 255)/256, 256>>>();
    kt_vocab_gemm<<<dim3(NTILE, (BB*TT)/128), 256>>>(out, b_vocab);
    kt_lsfinal<<<BB*TT, 256>>>(out);
}